// round 1
// baseline (speedup 1.0000x reference)
#include <cuda_runtime.h>
#include <math.h>

#define NROW 12288
#define NAGC 3
#define BSZ  4096

// ---------------- scratch (device globals; no allocations) ----------------
__device__ float g_h2[(size_t)NROW * 8000];   // conv output features (393 MB)
__device__ float g_act1[NROW * 256];          // fc1 output
__device__ float g_inps[NROW * 60];           // concat[obs, acts, feats]
__device__ float g_stats[128];                // mu[0:60], invstd[64:124]
__device__ float g_emb[NROW * 256];           // [sa | other]
__device__ float g_keys[NROW * 128];
__device__ float g_vals[NROW * 128];
__device__ float g_q[NROW * 128];
__device__ float g_m1[NROW * 256];
__device__ float g_m2[NROW * 256];

// ---------------- fused conv1 + conv2 (per-row, smem) ----------------
// scan (256) -> conv1 (32x252, relu) -> conv2 (32x250, relu) -> g_h2[row][oc*250+p]
__global__ void __launch_bounds__(256) conv_kernel(
    const float* __restrict__ scan,
    const float* __restrict__ w1, const float* __restrict__ b1,
    const float* __restrict__ w2, const float* __restrict__ b2)
{
    __shared__ float ss[256];
    __shared__ float h1s[252 * 32];   // [pos][ic]
    __shared__ float w1s[5 * 32];     // [tap][oc]
    __shared__ float w2s[96 * 32];    // [(ic*3+tap)][oc]
    __shared__ float b1s[32], b2s[32];

    int t = threadIdx.x;
    int row = blockIdx.x;

    ss[t] = scan[(size_t)row * 256 + t];
    if (t < 160) { int oc = t / 5, tap = t % 5; w1s[tap * 32 + oc] = w1[t]; }
    if (t < 32)  { b1s[t] = b1[t]; b2s[t] = b2[t]; }
    for (int idx = t; idx < 3072; idx += 256) {
        int oc = idx / 96, rem = idx % 96;
        w2s[rem * 32 + oc] = w2[idx];
    }
    __syncthreads();

    int oc = t & 31, pg = t >> 5;
    int base = pg * 32;

    // conv1 + relu
    {
        float wa = w1s[0 * 32 + oc], wb = w1s[1 * 32 + oc], wc = w1s[2 * 32 + oc];
        float wd = w1s[3 * 32 + oc], we = w1s[4 * 32 + oc];
        float bb = b1s[oc];
        #pragma unroll
        for (int i = 0; i < 32; i++) {
            int p = base + i;
            if (p < 252) {
                float a = bb + wa * ss[p] + wb * ss[p + 1] + wc * ss[p + 2]
                             + wd * ss[p + 3] + we * ss[p + 4];
                h1s[p * 32 + oc] = fmaxf(a, 0.f);
            }
        }
    }
    __syncthreads();

    // conv2 + relu (register window per input channel)
    float acc[32];
    #pragma unroll
    for (int i = 0; i < 32; i++) acc[i] = b2s[oc];

    for (int ic = 0; ic < 32; ic++) {
        float win[34];
        #pragma unroll
        for (int i = 0; i < 34; i++) {
            int p = base + i;
            win[i] = (p < 252) ? h1s[p * 32 + ic] : 0.f;
        }
        #pragma unroll
        for (int tap = 0; tap < 3; tap++) {
            float w = w2s[(ic * 3 + tap) * 32 + oc];
            #pragma unroll
            for (int i = 0; i < 32; i++) acc[i] += w * win[i + tap];
        }
    }

    float* orow = g_h2 + (size_t)row * 8000 + oc * 250;
    #pragma unroll
    for (int i = 0; i < 32; i++) {
        int p = base + i;
        if (p < 250) orow[p] = fmaxf(acc[i], 0.f);
    }
}

// ---------------- generic NT SGEMM: C[M,256] = A[M,K] @ B[256,K]^T (+bias, relu) --
// BM=64, BN=128, BK=16, 256 threads, 4x8 micro-tile. M=12288, N=256 fixed.
// ASEL: 0=g_h2, 1=g_emb, 2=g_m1.  CSEL: 0=g_act1, 1=g_m1, 2=g_m2.
template <int ASEL, int CSEL>
__global__ void __launch_bounds__(256) sgemm_nt(
    const float* __restrict__ B, const float* __restrict__ bias, int K, int relu)
{
    const float* A = (ASEL == 0) ? g_h2 : (ASEL == 1) ? g_emb : g_m1;
    float* C       = (CSEL == 0) ? g_act1 : (CSEL == 1) ? g_m1 : g_m2;

    __shared__ float As[16][64];
    __shared__ float Bs[16][128];

    int t = threadIdx.x;
    int bn = blockIdx.x, bm = blockIdx.y;
    int arow = t >> 2;              // 0..63
    int acol = (t & 3) * 4;         // 0,4,8,12

    const float* Ag  = A + (size_t)(bm * 64 + arow) * K + acol;
    const float* Bg0 = B + (size_t)(bn * 128 + arow) * K + acol;
    const float* Bg1 = Bg0 + (size_t)64 * K;

    int tx = t & 15, ty = t >> 4;

    float acc[4][8];
    #pragma unroll
    for (int i = 0; i < 4; i++)
        #pragma unroll
        for (int j = 0; j < 8; j++) acc[i][j] = 0.f;

    for (int k0 = 0; k0 < K; k0 += 16) {
        float4 av = *(const float4*)(Ag + k0);
        float4 b0 = *(const float4*)(Bg0 + k0);
        float4 b1 = *(const float4*)(Bg1 + k0);
        As[acol + 0][arow] = av.x; As[acol + 1][arow] = av.y;
        As[acol + 2][arow] = av.z; As[acol + 3][arow] = av.w;
        Bs[acol + 0][arow] = b0.x; Bs[acol + 1][arow] = b0.y;
        Bs[acol + 2][arow] = b0.z; Bs[acol + 3][arow] = b0.w;
        Bs[acol + 0][arow + 64] = b1.x; Bs[acol + 1][arow + 64] = b1.y;
        Bs[acol + 2][arow + 64] = b1.z; Bs[acol + 3][arow + 64] = b1.w;
        __syncthreads();

        #pragma unroll
        for (int k = 0; k < 16; k++) {
            float a[4], bb[8];
            *(float4*)a        = *(const float4*)&As[k][ty * 4];
            *(float4*)bb       = *(const float4*)&Bs[k][tx * 8];
            *(float4*)(bb + 4) = *(const float4*)&Bs[k][tx * 8 + 4];
            #pragma unroll
            for (int i = 0; i < 4; i++)
                #pragma unroll
                for (int j = 0; j < 8; j++) acc[i][j] += a[i] * bb[j];
        }
        __syncthreads();
    }

    int col0 = bn * 128 + tx * 8;
    #pragma unroll
    for (int i = 0; i < 4; i++) {
        int row = bm * 64 + ty * 4 + i;
        #pragma unroll
        for (int j = 0; j < 8; j++) {
            float v = acc[i][j] + bias[col0 + j];
            if (relu) v = fmaxf(v, 0.f);
            C[(size_t)row * 256 + col0 + j] = v;
        }
    }
}

// ---------------- fc2 (256->10) + concat[obs,acts,feats] -> g_inps ----------------
__global__ void __launch_bounds__(256) fc2_concat(
    const float* __restrict__ w2, const float* __restrict__ b2,
    const float* __restrict__ obs, const float* __restrict__ acts)
{
    __shared__ float fs[8][10];
    int warp = threadIdx.x >> 5, lane = threadIdx.x & 31;
    int r = blockIdx.x * 8 + warp;

    const float* xr = g_act1 + (size_t)r * 256;
    float x[8];
    #pragma unroll
    for (int i = 0; i < 8; i++) x[i] = xr[lane + 32 * i];

    #pragma unroll
    for (int j = 0; j < 10; j++) {
        float s = 0.f;
        #pragma unroll
        for (int i = 0; i < 8; i++) s += x[i] * w2[j * 256 + lane + 32 * i];
        #pragma unroll
        for (int off = 16; off; off >>= 1) s += __shfl_xor_sync(0xffffffffu, s, off);
        if (lane == 0) fs[warp][j] = s + b2[j];
    }
    __syncwarp();

    float* ir = g_inps + (size_t)r * 60;
    for (int c = lane; c < 60; c += 32) {
        float v;
        if (c < 48)      v = obs[(size_t)r * 48 + c];
        else if (c < 50) v = acts[(size_t)r * 2 + (c - 48)];
        else             v = fs[warp][c - 50];
        ir[c] = v;
    }
}

// ---------------- batch stats over 12288 rows, 60 cols ----------------
__global__ void __launch_bounds__(256) stats_kernel()
{
    int c = blockIdx.x, t = threadIdx.x;
    float s = 0.f, sq = 0.f;
    for (int r = t; r < NROW; r += 256) {
        float v = g_inps[(size_t)r * 60 + c];
        s += v; sq += v * v;
    }
    __shared__ float sh1[256], sh2[256];
    sh1[t] = s; sh2[t] = sq;
    __syncthreads();
    for (int st = 128; st; st >>= 1) {
        if (t < st) { sh1[t] += sh1[t + st]; sh2[t] += sh2[t + st]; }
        __syncthreads();
    }
    if (t == 0) {
        float mu = sh1[0] * (1.f / NROW);
        float var = sh2[0] * (1.f / NROW) - mu * mu;
        g_stats[c] = mu;
        g_stats[64 + c] = rsqrtf(var + 1e-5f);
    }
}

// -------- normalize + encoder(leaky) + keys/vals/q (32 rows per block) --------
__global__ void __launch_bounds__(256) enc_kvq(
    const float* __restrict__ enc_w, const float* __restrict__ enc_b,
    const float* __restrict__ Wk, const float* __restrict__ Wv,
    const float* __restrict__ bv, const float* __restrict__ Wq)
{
    __shared__ float xn[32][60];
    __shared__ float sas[32][128];
    __shared__ float wch[32][129];
    __shared__ float mu_s[60], inv_s[60];

    int t = threadIdx.x;
    int row0 = blockIdx.x * 32;
    int g = row0 >> 12;   // /4096

    if (t < 60) { mu_s[t] = g_stats[t]; inv_s[t] = g_stats[64 + t]; }
    __syncthreads();

    for (int idx = t; idx < 32 * 60; idx += 256) {
        int r = idx / 60, c = idx % 60;
        xn[r][c] = (g_inps[(size_t)(row0 + r) * 60 + c] - mu_s[c]) * inv_s[c];
    }
    __syncthreads();

    int jj = t & 31, rg = t >> 5;   // warp = fixed rg, jj 0..31

    // Phase A: sa = leaky(normed @ enc_w^T + enc_b)
    for (int jc = 0; jc < 4; jc++) {
        for (int idx = t; idx < 32 * 60; idx += 256) {
            int rr = idx / 60, c = idx % 60;
            wch[rr][c] = enc_w[(jc * 32 + rr) * 60 + c];
        }
        __syncthreads();

        float a0 = 0.f, a1 = 0.f, a2 = 0.f, a3 = 0.f;
        #pragma unroll
        for (int c = 0; c < 60; c++) {
            float w = wch[jj][c];
            a0 += xn[rg * 4 + 0][c] * w;
            a1 += xn[rg * 4 + 1][c] * w;
            a2 += xn[rg * 4 + 2][c] * w;
            a3 += xn[rg * 4 + 3][c] * w;
        }
        float bb = enc_b[jc * 32 + jj];
        float v0 = a0 + bb, v1 = a1 + bb, v2 = a2 + bb, v3 = a3 + bb;
        v0 = (v0 >= 0.f) ? v0 : 0.01f * v0;
        v1 = (v1 >= 0.f) ? v1 : 0.01f * v1;
        v2 = (v2 >= 0.f) ? v2 : 0.01f * v2;
        v3 = (v3 >= 0.f) ? v3 : 0.01f * v3;
        int col = jc * 32 + jj;
        sas[rg * 4 + 0][col] = v0; sas[rg * 4 + 1][col] = v1;
        sas[rg * 4 + 2][col] = v2; sas[rg * 4 + 3][col] = v3;
        g_emb[(size_t)(row0 + rg * 4 + 0) * 256 + col] = v0;
        g_emb[(size_t)(row0 + rg * 4 + 1) * 256 + col] = v1;
        g_emb[(size_t)(row0 + rg * 4 + 2) * 256 + col] = v2;
        g_emb[(size_t)(row0 + rg * 4 + 3) * 256 + col] = v3;
        __syncthreads();
    }

    // Phase B: keys / vals / q = sa @ W^T (128x128 each)
    for (int m = 0; m < 3; m++) {
        const float* W = (m == 0) ? Wk : (m == 1) ? Wv : (Wq + (size_t)g * 128 * 128);
        float* Out     = (m == 0) ? g_keys : (m == 1) ? g_vals : g_q;
        for (int jc = 0; jc < 4; jc++) {
            for (int idx = t; idx < 32 * 128; idx += 256) {
                int rr = idx >> 7, c = idx & 127;
                wch[rr][c] = W[(jc * 32 + rr) * 128 + c];
            }
            __syncthreads();

            float a0 = 0.f, a1 = 0.f, a2 = 0.f, a3 = 0.f;
            #pragma unroll
            for (int c = 0; c < 128; c++) {
                float w = wch[jj][c];
                a0 += sas[rg * 4 + 0][c] * w;
                a1 += sas[rg * 4 + 1][c] * w;
                a2 += sas[rg * 4 + 2][c] * w;
                a3 += sas[rg * 4 + 3][c] * w;
            }
            int col = jc * 32 + jj;
            if (m == 1) {
                float bb = bv[col];
                a0 += bb; a1 += bb; a2 += bb; a3 += bb;
                a0 = (a0 >= 0.f) ? a0 : 0.01f * a0;
                a1 = (a1 >= 0.f) ? a1 : 0.01f * a1;
                a2 = (a2 >= 0.f) ? a2 : 0.01f * a2;
                a3 = (a3 >= 0.f) ? a3 : 0.01f * a3;
            }
            Out[(size_t)(row0 + rg * 4 + 0) * 128 + col] = a0;
            Out[(size_t)(row0 + rg * 4 + 1) * 128 + col] = a1;
            Out[(size_t)(row0 + rg * 4 + 2) * 128 + col] = a2;
            Out[(size_t)(row0 + rg * 4 + 3) * 128 + col] = a3;
            __syncthreads();
        }
    }
}

// ---------------- tiny 3-agent cross-attention -> other half of emb ----------------
__global__ void __launch_bounds__(128) attn_kernel()
{
    __shared__ float qs[3][128], ks[3][128], vs[3][128];
    int b = blockIdx.x;
    int t = threadIdx.x;

    #pragma unroll
    for (int g = 0; g < 3; g++) {
        size_t roff = (size_t)(g * BSZ + b) * 128 + t;
        qs[g][t] = g_q[roff];
        ks[g][t] = g_keys[roff];
        vs[g][t] = g_vals[roff];
    }
    __syncthreads();

    const float scale = 0.25f;   // 1/sqrt(16)
    #pragma unroll
    for (int g = 0; g < 3; g++) {
        int o1 = (g == 0) ? 1 : 0;
        int o2 = (g == 2) ? 1 : 2;
        float q = qs[g][t];
        float p1 = q * ks[o1][t];
        float p2 = q * ks[o2][t];
        #pragma unroll
        for (int off = 8; off; off >>= 1) {
            p1 += __shfl_xor_sync(0xffffffffu, p1, off);
            p2 += __shfl_xor_sync(0xffffffffu, p2, off);
        }
        float l1 = p1 * scale, l2 = p2 * scale;
        float mx = fmaxf(l1, l2);
        float e1 = expf(l1 - mx), e2 = expf(l2 - mx);
        float inv = 1.f / (e1 + e2);
        float other = (e1 * vs[o1][t] + e2 * vs[o2][t]) * inv;
        g_emb[(size_t)(g * BSZ + b) * 256 + 128 + t] = other;
    }
}

// ---------------- final 256 -> 1 dot per row ----------------
__global__ void __launch_bounds__(256) final_dot(
    const float* __restrict__ w3, const float* __restrict__ b3, float* __restrict__ out)
{
    int warp = threadIdx.x >> 5, lane = threadIdx.x & 31;
    int r = blockIdx.x * 8 + warp;
    const float* xr = g_m2 + (size_t)r * 256;
    float s = 0.f;
    #pragma unroll
    for (int i = 0; i < 8; i++) s += xr[lane + 32 * i] * w3[lane + 32 * i];
    #pragma unroll
    for (int off = 16; off; off >>= 1) s += __shfl_xor_sync(0xffffffffu, s, off);
    if (lane == 0) out[r] = s + b3[0];
}

// ---------------- launch ----------------
extern "C" void kernel_launch(void* const* d_in, const int* in_sizes, int n_in,
                              void* d_out, int out_size)
{
    const float* obs     = (const float*)d_in[0];
    const float* acts    = (const float*)d_in[1];
    const float* scan    = (const float*)d_in[2];
    const float* conv_w1 = (const float*)d_in[3];
    const float* conv_b1 = (const float*)d_in[4];
    const float* conv_w2 = (const float*)d_in[5];
    const float* conv_b2 = (const float*)d_in[6];
    const float* fc_w1   = (const float*)d_in[7];
    const float* fc_b1   = (const float*)d_in[8];
    const float* fc_w2   = (const float*)d_in[9];
    const float* fc_b2   = (const float*)d_in[10];
    const float* enc_w   = (const float*)d_in[11];
    const float* enc_b   = (const float*)d_in[12];
    const float* Wk      = (const float*)d_in[13];
    const float* Wv      = (const float*)d_in[14];
    const float* bv      = (const float*)d_in[15];
    const float* Wq      = (const float*)d_in[16];
    const float* q1_w1   = (const float*)d_in[17];
    const float* q1_b1   = (const float*)d_in[18];
    const float* q1_w2   = (const float*)d_in[19];
    const float* q1_b2   = (const float*)d_in[20];
    const float* q1_w3   = (const float*)d_in[21];
    const float* q1_b3   = (const float*)d_in[22];
    const float* q2_w1   = (const float*)d_in[23];
    const float* q2_b1   = (const float*)d_in[24];
    const float* q2_w2   = (const float*)d_in[25];
    const float* q2_b2   = (const float*)d_in[26];
    const float* q2_w3   = (const float*)d_in[27];
    const float* q2_b3   = (const float*)d_in[28];
    float* out = (float*)d_out;

    dim3 ggrid(2, 192);   // N=256 / BN=128, M=12288 / BM=64

    conv_kernel<<<NROW, 256>>>(scan, conv_w1, conv_b1, conv_w2, conv_b2);
    sgemm_nt<0, 0><<<ggrid, 256>>>(fc_w1, fc_b1, 8000, 1);           // fc1 + relu
    fc2_concat<<<NROW / 8, 256>>>(fc_w2, fc_b2, obs, acts);
    stats_kernel<<<60, 256>>>();
    enc_kvq<<<NROW / 32, 256>>>(enc_w, enc_b, Wk, Wv, bv, Wq);
    attn_kernel<<<BSZ, 128>>>();

    // q1 MLP
    sgemm_nt<1, 1><<<ggrid, 256>>>(q1_w1, q1_b1, 256, 1);
    sgemm_nt<2, 2><<<ggrid, 256>>>(q1_w2, q1_b2, 256, 1);
    final_dot<<<NROW / 8, 256>>>(q1_w3, q1_b3, out);

    // q2 MLP
    sgemm_nt<1, 1><<<ggrid, 256>>>(q2_w1, q2_b1, 256, 1);
    sgemm_nt<2, 2><<<ggrid, 256>>>(q2_w2, q2_b2, 256, 1);
    final_dot<<<NROW / 8, 256>>>(q2_w3, q2_b3, out + NROW);
}

// round 3
// speedup vs baseline: 1.8616x; 1.8616x over previous
#include <cuda_runtime.h>
#include <cuda_bf16.h>
#include <math.h>
#include <cstdint>

#define NROW 12288
#define BSZ  4096

// ---------------- scratch (device globals; no allocations) ----------------
__device__ __nv_bfloat16 g_ah[(size_t)NROW * 8000];   // conv output hi
__device__ __nv_bfloat16 g_al[(size_t)NROW * 8000];   // conv output lo
__device__ __nv_bfloat16 g_fwh[256 * 8000];           // fc_w1 hi
__device__ __nv_bfloat16 g_fwl[256 * 8000];           // fc_w1 lo
__device__ __nv_bfloat16 g_qwh[4 * 256 * 256];        // 4 MLP weights hi
__device__ __nv_bfloat16 g_qwl[4 * 256 * 256];        // 4 MLP weights lo
__device__ float g_act1[NROW * 256];                  // fc1 output (fp32)
__device__ float g_inps[NROW * 60];
__device__ float g_stats[128];
__device__ __nv_bfloat16 g_embh[NROW * 256];          // emb split
__device__ __nv_bfloat16 g_embl[NROW * 256];
__device__ __nv_bfloat16 g_mh[NROW * 256];            // mlp hidden split
__device__ __nv_bfloat16 g_ml[NROW * 256];
__device__ float g_m2[NROW * 256];
__device__ float g_keys[NROW * 128];
__device__ float g_vals[NROW * 128];
__device__ float g_q[NROW * 128];

// ====================== helpers ======================
__device__ __forceinline__ uint32_t smem_u32(const void* p) {
    uint32_t a;
    asm("{ .reg .u64 t; cvta.to.shared.u64 t, %1; cvt.u32.u64 %0, t; }"
        : "=r"(a) : "l"(p));
    return a;
}
__device__ __forceinline__ void bsplit(float v, __nv_bfloat16& h, __nv_bfloat16& l) {
    h = __float2bfloat16(v);
    l = __float2bfloat16(v - __bfloat162float(h));
}
#define CPA16(s, g) \
    asm volatile("cp.async.cg.shared.global [%0], [%1], 16;" :: "r"(s), "l"(g))
#define CPC() asm volatile("cp.async.commit_group;" ::: "memory")
#define LDSM4(r0, r1, r2, r3, a) \
    asm volatile("ldmatrix.sync.aligned.m8n8.x4.shared.b16 {%0,%1,%2,%3}, [%4];" \
                 : "=r"(r0), "=r"(r1), "=r"(r2), "=r"(r3) : "r"(a))
#define MMA16816(d, a, b) \
    asm volatile("mma.sync.aligned.m16n8k16.row.col.f32.bf16.bf16.f32 " \
                 "{%0,%1,%2,%3},{%4,%5,%6,%7},{%8,%9},{%0,%1,%2,%3};" \
                 : "+f"((d)[0]), "+f"((d)[1]), "+f"((d)[2]), "+f"((d)[3]) \
                 : "r"((a)[0]), "r"((a)[1]), "r"((a)[2]), "r"((a)[3]), \
                   "r"((b)[0]), "r"((b)[1]))

// ============ bf16x3 HMMA GEMM: C[12288,256] = A[12288,K] @ B[256,K]^T ============
// BM=128, BN=64, BK=64, 256 threads (8 warps as 2M x 4N, warp tile 64x16).
// MODE: 0 fc1 (A=conv split, W=fc_w1, out fp32 g_act1)
//       1 q1 layer1 (A=emb, W slot0, out split g_mh/g_ml)
//       2 q1 layer2 (A=g_mh/l, W slot1, out fp32 g_m2)
//       3 q2 layer1 (A=emb, W slot2, out split)
//       4 q2 layer2 (A=g_mh/l, W slot3, out fp32 g_m2)
// All modes apply relu.
#define GSMEM 98304
template <int MODE>
__global__ void __launch_bounds__(256, 2) gemm_bf3(
    const float* __restrict__ bias, int K)
{
    const __nv_bfloat16 *Ah, *Al, *Bh, *Bl;
    if (MODE == 0)      { Ah = g_ah;   Al = g_al;   Bh = g_fwh;          Bl = g_fwl; }
    else if (MODE == 1) { Ah = g_embh; Al = g_embl; Bh = g_qwh;          Bl = g_qwl; }
    else if (MODE == 2) { Ah = g_mh;   Al = g_ml;   Bh = g_qwh + 65536;  Bl = g_qwl + 65536; }
    else if (MODE == 3) { Ah = g_embh; Al = g_embl; Bh = g_qwh + 131072; Bl = g_qwl + 131072; }
    else                { Ah = g_mh;   Al = g_ml;   Bh = g_qwh + 196608; Bl = g_qwl + 196608; }
    constexpr bool OUTF32 = (MODE == 0 || MODE == 2 || MODE == 4);

    extern __shared__ char smem[];
    const uint32_t sb = smem_u32(smem);

    const int t = threadIdx.x, lane = t & 31, wid = t >> 5;
    const int row0 = blockIdx.y * 128, col0 = blockIdx.x * 64;

    // global load mapping
    const int ar = t >> 1, ac0 = (t & 1) * 4;   // A: row 0..127, 4 chunks of 16B
    const int br = t >> 2, bc0 = (t & 3) * 2;   // B: row 0..63,  2 chunks of 16B
    const __nv_bfloat16* gAh = Ah + (size_t)(row0 + ar) * K;
    const __nv_bfloat16* gAl = Al + (size_t)(row0 + ar) * K;
    const __nv_bfloat16* gBh = Bh + (size_t)(col0 + br) * K;
    const __nv_bfloat16* gBl = Bl + (size_t)(col0 + br) * K;

    // compute-side lane constants
    const int m0 = (wid & 1) * 64;
    const int n0 = (wid >> 1) * 16;
    const int lr = lane & 15;
    const int kh = lane >> 4;                               // A k-half (0/1)
    const int brow = n0 + (lane & 7) + ((lane >> 4) << 3);  // B smem row
    const int bko = (lane >> 3) & 1;                        // B k-half

    const int T = K / 64;
    float acc[4][2][4];
    #pragma unroll
    for (int a = 0; a < 4; a++)
        #pragma unroll
        for (int b = 0; b < 2; b++)
            #pragma unroll
            for (int c = 0; c < 4; c++) acc[a][b][c] = 0.f;

    auto load_stage = [&](int tt, int s) {
        uint32_t base = sb + s * 49152;
        const __nv_bfloat16* pAh = gAh + (size_t)tt * 64;
        const __nv_bfloat16* pAl = gAl + (size_t)tt * 64;
        const __nv_bfloat16* pBh = gBh + (size_t)tt * 64;
        const __nv_bfloat16* pBl = gBl + (size_t)tt * 64;
        #pragma unroll
        for (int q = 0; q < 4; q++) {
            int c = ac0 + q;
            uint32_t off = ar * 128 + ((c ^ (ar & 7)) << 4);
            CPA16(base + off,         pAh + c * 8);
            CPA16(base + 16384 + off, pAl + c * 8);
        }
        #pragma unroll
        for (int q = 0; q < 2; q++) {
            int c = bc0 + q;
            uint32_t off = br * 128 + ((c ^ (br & 7)) << 4);
            CPA16(base + 32768 + off, pBh + c * 8);
            CPA16(base + 40960 + off, pBl + c * 8);
        }
    };

    load_stage(0, 0);
    CPC();

    for (int tt = 0; tt < T; tt++) {
        if (tt + 1 < T) {
            load_stage(tt + 1, (tt + 1) & 1);
            CPC();
            asm volatile("cp.async.wait_group 1;" ::: "memory");
        } else {
            asm volatile("cp.async.wait_group 0;" ::: "memory");
        }
        __syncthreads();

        uint32_t base = sb + (tt & 1) * 49152;
        #pragma unroll
        for (int ks = 0; ks < 4; ks++) {
            uint32_t ahf[4][4], alf[4][4], bhf[4], blf[4];
            int ch = ks * 2 + kh;
            #pragma unroll
            for (int mi = 0; mi < 4; mi++) {
                int r = m0 + mi * 16 + lr;
                uint32_t a = base + r * 128 + ((ch ^ (r & 7)) << 4);
                LDSM4(ahf[mi][0], ahf[mi][1], ahf[mi][2], ahf[mi][3], a);
                LDSM4(alf[mi][0], alf[mi][1], alf[mi][2], alf[mi][3], a + 16384);
            }
            int bch = ks * 2 + bko;
            uint32_t ba = base + 32768 + brow * 128 + ((bch ^ (brow & 7)) << 4);
            LDSM4(bhf[0], bhf[1], bhf[2], bhf[3], ba);
            LDSM4(blf[0], blf[1], blf[2], blf[3], ba + 8192);

            #pragma unroll
            for (int mi = 0; mi < 4; mi++) {
                #pragma unroll
                for (int nf = 0; nf < 2; nf++) {
                    MMA16816(acc[mi][nf], ahf[mi], bhf + 2 * nf);
                    MMA16816(acc[mi][nf], ahf[mi], blf + 2 * nf);
                    MMA16816(acc[mi][nf], alf[mi], bhf + 2 * nf);
                }
            }
        }
        __syncthreads();
    }

    // epilogue
    float* Cf = (MODE == 0) ? g_act1 : g_m2;
    #pragma unroll
    for (int mi = 0; mi < 4; mi++) {
        #pragma unroll
        for (int nf = 0; nf < 2; nf++) {
            int col = col0 + n0 + nf * 8 + (lane & 3) * 2;
            float b0 = bias[col], b1 = bias[col + 1];
            #pragma unroll
            for (int h = 0; h < 2; h++) {
                int row = row0 + m0 + mi * 16 + (lane >> 2) + h * 8;
                float v0 = fmaxf(acc[mi][nf][h * 2 + 0] + b0, 0.f);
                float v1 = fmaxf(acc[mi][nf][h * 2 + 1] + b1, 0.f);
                size_t idx = (size_t)row * 256 + col;
                if (OUTF32) {
                    *(float2*)(Cf + idx) = make_float2(v0, v1);
                } else {
                    __nv_bfloat16 h0, l0, h1, l1;
                    bsplit(v0, h0, l0);
                    bsplit(v1, h1, l1);
                    *(__nv_bfloat162*)(g_mh + idx) = __halves2bfloat162(h0, h1);
                    *(__nv_bfloat162*)(g_ml + idx) = __halves2bfloat162(l0, l1);
                }
            }
        }
    }
}

// ---------------- weight split: fp32 -> bf16 hi/lo ----------------
template <int SLOT>
__global__ void wsplit(const float* __restrict__ w, int n)
{
    int i = blockIdx.x * 256 + threadIdx.x;
    if (i >= n) return;
    __nv_bfloat16 *H, *L;
    if (SLOT == 0) { H = g_fwh; L = g_fwl; }
    else           { H = g_qwh + (SLOT - 1) * 65536; L = g_qwl + (SLOT - 1) * 65536; }
    __nv_bfloat16 hh, ll;
    bsplit(w[i], hh, ll);
    H[i] = hh;
    L[i] = ll;
}

// ---------------- fused conv1 + conv2 -> bf16 split ----------------
__global__ void __launch_bounds__(256) conv_kernel(
    const float* __restrict__ scan,
    const float* __restrict__ w1, const float* __restrict__ b1,
    const float* __restrict__ w2, const float* __restrict__ b2)
{
    __shared__ float ss[256];
    __shared__ float h1s[252 * 32];
    __shared__ float w1s[5 * 32];
    __shared__ float w2s[96 * 32];
    __shared__ float b1s[32], b2s[32];

    int t = threadIdx.x;
    int row = blockIdx.x;

    ss[t] = scan[(size_t)row * 256 + t];
    if (t < 160) { int oc = t / 5, tap = t % 5; w1s[tap * 32 + oc] = w1[t]; }
    if (t < 32)  { b1s[t] = b1[t]; b2s[t] = b2[t]; }
    for (int idx = t; idx < 3072; idx += 256) {
        int oc = idx / 96, rem = idx % 96;
        w2s[rem * 32 + oc] = w2[idx];
    }
    __syncthreads();

    int oc = t & 31, pg = t >> 5;
    int base = pg * 32;

    {
        float wa = w1s[0 * 32 + oc], wb = w1s[1 * 32 + oc], wc = w1s[2 * 32 + oc];
        float wd = w1s[3 * 32 + oc], we = w1s[4 * 32 + oc];
        float bb = b1s[oc];
        #pragma unroll
        for (int i = 0; i < 32; i++) {
            int p = base + i;
            if (p < 252) {
                float a = bb + wa * ss[p] + wb * ss[p + 1] + wc * ss[p + 2]
                             + wd * ss[p + 3] + we * ss[p + 4];
                h1s[p * 32 + oc] = fmaxf(a, 0.f);
            }
        }
    }
    __syncthreads();

    float acc[32];
    #pragma unroll
    for (int i = 0; i < 32; i++) acc[i] = b2s[oc];

    for (int ic = 0; ic < 32; ic++) {
        float win[34];
        #pragma unroll
        for (int i = 0; i < 34; i++) {
            int p = base + i;
            win[i] = (p < 252) ? h1s[p * 32 + ic] : 0.f;
        }
        #pragma unroll
        for (int tap = 0; tap < 3; tap++) {
            float w = w2s[(ic * 3 + tap) * 32 + oc];
            #pragma unroll
            for (int i = 0; i < 32; i++) acc[i] += w * win[i + tap];
        }
    }

    size_t obase = (size_t)row * 8000 + oc * 250;
    #pragma unroll
    for (int i = 0; i < 32; i += 2) {
        int p = base + i;
        if (p < 250) {   // 250 even, p even -> pair always in-bounds together
            float v0 = fmaxf(acc[i], 0.f);
            float v1 = fmaxf(acc[i + 1], 0.f);
            __nv_bfloat16 h0, l0, h1, l1;
            bsplit(v0, h0, l0);
            bsplit(v1, h1, l1);
            *(__nv_bfloat162*)(g_ah + obase + p) = __halves2bfloat162(h0, h1);
            *(__nv_bfloat162*)(g_al + obase + p) = __halves2bfloat162(l0, l1);
        }
    }
}

// ---------------- fc2 (256->10) + concat[obs,acts,feats] -> g_inps ----------------
__global__ void __launch_bounds__(256) fc2_concat(
    const float* __restrict__ w2, const float* __restrict__ b2,
    const float* __restrict__ obs, const float* __restrict__ acts)
{
    __shared__ float fs[8][10];
    int warp = threadIdx.x >> 5, lane = threadIdx.x & 31;
    int r = blockIdx.x * 8 + warp;

    const float* xr = g_act1 + (size_t)r * 256;
    float x[8];
    #pragma unroll
    for (int i = 0; i < 8; i++) x[i] = xr[lane + 32 * i];

    #pragma unroll
    for (int j = 0; j < 10; j++) {
        float s = 0.f;
        #pragma unroll
        for (int i = 0; i < 8; i++) s += x[i] * w2[j * 256 + lane + 32 * i];
        #pragma unroll
        for (int off = 16; off; off >>= 1) s += __shfl_xor_sync(0xffffffffu, s, off);
        if (lane == 0) fs[warp][j] = s + b2[j];
    }
    __syncwarp();

    float* ir = g_inps + (size_t)r * 60;
    for (int c = lane; c < 60; c += 32) {
        float v;
        if (c < 48)      v = obs[(size_t)r * 48 + c];
        else if (c < 50) v = acts[(size_t)r * 2 + (c - 48)];
        else             v = fs[warp][c - 50];
        ir[c] = v;
    }
}

// ---------------- batch stats ----------------
__global__ void __launch_bounds__(256) stats_kernel()
{
    int c = blockIdx.x, t = threadIdx.x;
    float s = 0.f, sq = 0.f;
    for (int r = t; r < NROW; r += 256) {
        float v = g_inps[(size_t)r * 60 + c];
        s += v; sq += v * v;
    }
    __shared__ float sh1[256], sh2[256];
    sh1[t] = s; sh2[t] = sq;
    __syncthreads();
    for (int st = 128; st; st >>= 1) {
        if (t < st) { sh1[t] += sh1[t + st]; sh2[t] += sh2[t + st]; }
        __syncthreads();
    }
    if (t == 0) {
        float mu = sh1[0] * (1.f / NROW);
        float var = sh2[0] * (1.f / NROW) - mu * mu;
        g_stats[c] = mu;
        g_stats[64 + c] = rsqrtf(var + 1e-5f);
    }
}

// -------- normalize + encoder(leaky) + keys/vals/q ----------
__global__ void __launch_bounds__(256) enc_kvq(
    const float* __restrict__ enc_w, const float* __restrict__ enc_b,
    const float* __restrict__ Wk, const float* __restrict__ Wv,
    const float* __restrict__ bv, const float* __restrict__ Wq)
{
    __shared__ float xn[32][60];
    __shared__ float sas[32][128];
    __shared__ float wch[32][129];
    __shared__ float mu_s[60], inv_s[60];

    int t = threadIdx.x;
    int row0 = blockIdx.x * 32;
    int g = row0 >> 12;

    if (t < 60) { mu_s[t] = g_stats[t]; inv_s[t] = g_stats[64 + t]; }
    __syncthreads();

    for (int idx = t; idx < 32 * 60; idx += 256) {
        int r = idx / 60, c = idx % 60;
        xn[r][c] = (g_inps[(size_t)(row0 + r) * 60 + c] - mu_s[c]) * inv_s[c];
    }
    __syncthreads();

    int jj = t & 31, rg = t >> 5;

    for (int jc = 0; jc < 4; jc++) {
        for (int idx = t; idx < 32 * 60; idx += 256) {
            int rr = idx / 60, c = idx % 60;
            wch[rr][c] = enc_w[(jc * 32 + rr) * 60 + c];
        }
        __syncthreads();

        float a0 = 0.f, a1 = 0.f, a2 = 0.f, a3 = 0.f;
        #pragma unroll
        for (int c = 0; c < 60; c++) {
            float w = wch[jj][c];
            a0 += xn[rg * 4 + 0][c] * w;
            a1 += xn[rg * 4 + 1][c] * w;
            a2 += xn[rg * 4 + 2][c] * w;
            a3 += xn[rg * 4 + 3][c] * w;
        }
        float bb = enc_b[jc * 32 + jj];
        float v[4] = {a0 + bb, a1 + bb, a2 + bb, a3 + bb};
        int col = jc * 32 + jj;
        #pragma unroll
        for (int q = 0; q < 4; q++) {
            float vv = (v[q] >= 0.f) ? v[q] : 0.01f * v[q];
            sas[rg * 4 + q][col] = vv;
            __nv_bfloat16 hh, ll;
            bsplit(vv, hh, ll);
            size_t idx = (size_t)(row0 + rg * 4 + q) * 256 + col;
            g_embh[idx] = hh;
            g_embl[idx] = ll;
        }
        __syncthreads();
    }

    for (int m = 0; m < 3; m++) {
        const float* W = (m == 0) ? Wk : (m == 1) ? Wv : (Wq + (size_t)g * 128 * 128);
        float* Out     = (m == 0) ? g_keys : (m == 1) ? g_vals : g_q;
        for (int jc = 0; jc < 4; jc++) {
            for (int idx = t; idx < 32 * 128; idx += 256) {
                int rr = idx >> 7, c = idx & 127;
                wch[rr][c] = W[(jc * 32 + rr) * 128 + c];
            }
            __syncthreads();

            float a0 = 0.f, a1 = 0.f, a2 = 0.f, a3 = 0.f;
            #pragma unroll
            for (int c = 0; c < 128; c++) {
                float w = wch[jj][c];
                a0 += sas[rg * 4 + 0][c] * w;
                a1 += sas[rg * 4 + 1][c] * w;
                a2 += sas[rg * 4 + 2][c] * w;
                a3 += sas[rg * 4 + 3][c] * w;
            }
            int col = jc * 32 + jj;
            if (m == 1) {
                float bb = bv[col];
                a0 += bb; a1 += bb; a2 += bb; a3 += bb;
                a0 = (a0 >= 0.f) ? a0 : 0.01f * a0;
                a1 = (a1 >= 0.f) ? a1 : 0.01f * a1;
                a2 = (a2 >= 0.f) ? a2 : 0.01f * a2;
                a3 = (a3 >= 0.f) ? a3 : 0.01f * a3;
            }
            Out[(size_t)(row0 + rg * 4 + 0) * 128 + col] = a0;
            Out[(size_t)(row0 + rg * 4 + 1) * 128 + col] = a1;
            Out[(size_t)(row0 + rg * 4 + 2) * 128 + col] = a2;
            Out[(size_t)(row0 + rg * 4 + 3) * 128 + col] = a3;
            __syncthreads();
        }
    }
}

// ---------------- tiny 3-agent cross-attention ----------------
__global__ void __launch_bounds__(128) attn_kernel()
{
    __shared__ float qs[3][128], ks[3][128], vs[3][128];
    int b = blockIdx.x;
    int t = threadIdx.x;

    #pragma unroll
    for (int g = 0; g < 3; g++) {
        size_t roff = (size_t)(g * BSZ + b) * 128 + t;
        qs[g][t] = g_q[roff];
        ks[g][t] = g_keys[roff];
        vs[g][t] = g_vals[roff];
    }
    __syncthreads();

    const float scale = 0.25f;
    #pragma unroll
    for (int g = 0; g < 3; g++) {
        int o1 = (g == 0) ? 1 : 0;
        int o2 = (g == 2) ? 1 : 2;
        float q = qs[g][t];
        float p1 = q * ks[o1][t];
        float p2 = q * ks[o2][t];
        #pragma unroll
        for (int off = 8; off; off >>= 1) {
            p1 += __shfl_xor_sync(0xffffffffu, p1, off);
            p2 += __shfl_xor_sync(0xffffffffu, p2, off);
        }
        float l1 = p1 * scale, l2 = p2 * scale;
        float mx = fmaxf(l1, l2);
        float e1 = expf(l1 - mx), e2 = expf(l2 - mx);
        float inv = 1.f / (e1 + e2);
        float other = (e1 * vs[o1][t] + e2 * vs[o2][t]) * inv;
        __nv_bfloat16 hh, ll;
        bsplit(other, hh, ll);
        size_t idx = (size_t)(g * BSZ + b) * 256 + 128 + t;
        g_embh[idx] = hh;
        g_embl[idx] = ll;
    }
}

// ---------------- final 256 -> 1 dot per row ----------------
__global__ void __launch_bounds__(256) final_dot(
    const float* __restrict__ w3, const float* __restrict__ b3, float* __restrict__ out)
{
    int warp = threadIdx.x >> 5, lane = threadIdx.x & 31;
    int r = blockIdx.x * 8 + warp;
    const float* xr = g_m2 + (size_t)r * 256;
    float s = 0.f;
    #pragma unroll
    for (int i = 0; i < 8; i++) s += xr[lane + 32 * i] * w3[lane + 32 * i];
    #pragma unroll
    for (int off = 16; off; off >>= 1) s += __shfl_xor_sync(0xffffffffu, s, off);
    if (lane == 0) out[r] = s + b3[0];
}

// ---------------- launch ----------------
extern "C" void kernel_launch(void* const* d_in, const int* in_sizes, int n_in,
                              void* d_out, int out_size)
{
    const float* obs     = (const float*)d_in[0];
    const float* acts    = (const float*)d_in[1];
    const float* scan    = (const float*)d_in[2];
    const float* conv_w1 = (const float*)d_in[3];
    const float* conv_b1 = (const float*)d_in[4];
    const float* conv_w2 = (const float*)d_in[5];
    const float* conv_b2 = (const float*)d_in[6];
    const float* fc_w1   = (const float*)d_in[7];
    const float* fc_b1   = (const float*)d_in[8];
    const float* fc_w2   = (const float*)d_in[9];
    const float* fc_b2   = (const float*)d_in[10];
    const float* enc_w   = (const float*)d_in[11];
    const float* enc_b   = (const float*)d_in[12];
    const float* Wk      = (const float*)d_in[13];
    const float* Wv      = (const float*)d_in[14];
    const float* bv      = (const float*)d_in[15];
    const float* Wq      = (const float*)d_in[16];
    const float* q1_w1   = (const float*)d_in[17];
    const float* q1_b1   = (const float*)d_in[18];
    const float* q1_w2   = (const float*)d_in[19];
    const float* q1_b2   = (const float*)d_in[20];
    const float* q1_w3   = (const float*)d_in[21];
    const float* q1_b3   = (const float*)d_in[22];
    const float* q2_w1   = (const float*)d_in[23];
    const float* q2_b1   = (const float*)d_in[24];
    const float* q2_w2   = (const float*)d_in[25];
    const float* q2_b2   = (const float*)d_in[26];
    const float* q2_w3   = (const float*)d_in[27];
    const float* q2_b3   = (const float*)d_in[28];
    float* out = (float*)d_out;

    cudaFuncSetAttribute(gemm_bf3<0>, cudaFuncAttributeMaxDynamicSharedMemorySize, GSMEM);
    cudaFuncSetAttribute(gemm_bf3<1>, cudaFuncAttributeMaxDynamicSharedMemorySize, GSMEM);
    cudaFuncSetAttribute(gemm_bf3<2>, cudaFuncAttributeMaxDynamicSharedMemorySize, GSMEM);
    cudaFuncSetAttribute(gemm_bf3<3>, cudaFuncAttributeMaxDynamicSharedMemorySize, GSMEM);
    cudaFuncSetAttribute(gemm_bf3<4>, cudaFuncAttributeMaxDynamicSharedMemorySize, GSMEM);

    dim3 ggrid(4, 96);   // N=256/64, M=12288/128

    // weight splits (independent of conv)
    wsplit<0><<<(256 * 8000 + 255) / 256, 256>>>(fc_w1, 256 * 8000);
    wsplit<1><<<256, 256>>>(q1_w1, 65536);
    wsplit<2><<<256, 256>>>(q1_w2, 65536);
    wsplit<3><<<256, 256>>>(q2_w1, 65536);
    wsplit<4><<<256, 256>>>(q2_w2, 65536);

    conv_kernel<<<NROW, 256>>>(scan, conv_w1, conv_b1, conv_w2, conv_b2);
    gemm_bf3<0><<<ggrid, 256, GSMEM>>>(fc_b1, 8000);          // fc1 + relu
    fc2_concat<<<NROW / 8, 256>>>(fc_w2, fc_b2, obs, acts);
    stats_kernel<<<60, 256>>>();
    enc_kvq<<<NROW / 32, 256>>>(enc_w, enc_b, Wk, Wv, bv, Wq);
    attn_kernel<<<BSZ, 128>>>();

    // q1 MLP
    gemm_bf3<1><<<ggrid, 256, GSMEM>>>(q1_b1, 256);
    gemm_bf3<2><<<ggrid, 256, GSMEM>>>(q1_b2, 256);
    final_dot<<<NROW / 8, 256>>>(q1_w3, q1_b3, out);

    // q2 MLP
    gemm_bf3<3><<<ggrid, 256, GSMEM>>>(q2_b1, 256);
    gemm_bf3<4><<<ggrid, 256, GSMEM>>>(q2_b2, 256);
    final_dot<<<NROW / 8, 256>>>(q2_w3, q2_b3, out + NROW);
}

// round 4
// speedup vs baseline: 3.1897x; 1.7134x over previous
#include <cuda_runtime.h>
#include <cuda_bf16.h>
#include <math.h>
#include <cstdint>

#define NROW 12288
#define BSZ  4096

// ---------------- scratch (device globals; no allocations) ----------------
__device__ __nv_bfloat16 g_ah[(size_t)NROW * 8000];   // conv output hi
__device__ __nv_bfloat16 g_al[(size_t)NROW * 8000];   // conv output lo
__device__ __nv_bfloat16 g_fwh[256 * 8000];           // fc_w1 hi
__device__ __nv_bfloat16 g_fwl[256 * 8000];           // fc_w1 lo
__device__ __nv_bfloat16 g_qwh[4 * 256 * 256];        // 4 MLP weights hi
__device__ __nv_bfloat16 g_qwl[4 * 256 * 256];        // 4 MLP weights lo
__device__ float g_act1[NROW * 256];                  // fc1 output (fp32)
__device__ float g_inps[NROW * 60];
__device__ float g_stats[128];
__device__ __nv_bfloat16 g_embh[NROW * 256];          // emb split
__device__ __nv_bfloat16 g_embl[NROW * 256];
__device__ __nv_bfloat16 g_mh[NROW * 256];            // mlp hidden split
__device__ __nv_bfloat16 g_ml[NROW * 256];
__device__ float g_m2[NROW * 256];
__device__ float g_keys[NROW * 128];
__device__ float g_vals[NROW * 128];
__device__ float g_q[NROW * 128];

// ====================== helpers ======================
__device__ __forceinline__ uint32_t smem_u32(const void* p) {
    uint32_t a;
    asm("{ .reg .u64 t; cvta.to.shared.u64 t, %1; cvt.u32.u64 %0, t; }"
        : "=r"(a) : "l"(p));
    return a;
}
__device__ __forceinline__ void bsplit(float v, __nv_bfloat16& h, __nv_bfloat16& l) {
    h = __float2bfloat16(v);
    l = __float2bfloat16(v - __bfloat162float(h));
}
#define CPA16(s, g) \
    asm volatile("cp.async.cg.shared.global [%0], [%1], 16;" :: "r"(s), "l"(g))
#define CPC() asm volatile("cp.async.commit_group;" ::: "memory")
#define LDSM4(r0, r1, r2, r3, a) \
    asm volatile("ldmatrix.sync.aligned.m8n8.x4.shared.b16 {%0,%1,%2,%3}, [%4];" \
                 : "=r"(r0), "=r"(r1), "=r"(r2), "=r"(r3) : "r"(a))
#define MMA16816(d, a, b) \
    asm volatile("mma.sync.aligned.m16n8k16.row.col.f32.bf16.bf16.f32 " \
                 "{%0,%1,%2,%3},{%4,%5,%6,%7},{%8,%9},{%0,%1,%2,%3};" \
                 : "+f"((d)[0]), "+f"((d)[1]), "+f"((d)[2]), "+f"((d)[3]) \
                 : "r"((a)[0]), "r"((a)[1]), "r"((a)[2]), "r"((a)[3]), \
                   "r"((b)[0]), "r"((b)[1]))

// ============ bf16x3 HMMA GEMM: C[12288,256] = A[12288,K] @ B[256,K]^T ============
#define GSMEM 98304
template <int MODE>
__global__ void __launch_bounds__(256, 2) gemm_bf3(
    const float* __restrict__ bias, int K)
{
    const __nv_bfloat16 *Ah, *Al, *Bh, *Bl;
    if (MODE == 0)      { Ah = g_ah;   Al = g_al;   Bh = g_fwh;          Bl = g_fwl; }
    else if (MODE == 1) { Ah = g_embh; Al = g_embl; Bh = g_qwh;          Bl = g_qwl; }
    else if (MODE == 2) { Ah = g_mh;   Al = g_ml;   Bh = g_qwh + 65536;  Bl = g_qwl + 65536; }
    else if (MODE == 3) { Ah = g_embh; Al = g_embl; Bh = g_qwh + 131072; Bl = g_qwl + 131072; }
    else                { Ah = g_mh;   Al = g_ml;   Bh = g_qwh + 196608; Bl = g_qwl + 196608; }
    constexpr bool OUTF32 = (MODE == 0 || MODE == 2 || MODE == 4);

    extern __shared__ char smem[];
    const uint32_t sb = smem_u32(smem);

    const int t = threadIdx.x, lane = t & 31, wid = t >> 5;
    const int row0 = blockIdx.y * 128, col0 = blockIdx.x * 64;

    const int ar = t >> 1, ac0 = (t & 1) * 4;
    const int br = t >> 2, bc0 = (t & 3) * 2;
    const __nv_bfloat16* gAh = Ah + (size_t)(row0 + ar) * K;
    const __nv_bfloat16* gAl = Al + (size_t)(row0 + ar) * K;
    const __nv_bfloat16* gBh = Bh + (size_t)(col0 + br) * K;
    const __nv_bfloat16* gBl = Bl + (size_t)(col0 + br) * K;

    const int m0 = (wid & 1) * 64;
    const int n0 = (wid >> 1) * 16;
    const int lr = lane & 15;
    const int kh = lane >> 4;
    const int brow = n0 + (lane & 7) + ((lane >> 4) << 3);
    const int bko = (lane >> 3) & 1;

    const int T = K / 64;
    float acc[4][2][4];
    #pragma unroll
    for (int a = 0; a < 4; a++)
        #pragma unroll
        for (int b = 0; b < 2; b++)
            #pragma unroll
            for (int c = 0; c < 4; c++) acc[a][b][c] = 0.f;

    auto load_stage = [&](int tt, int s) {
        uint32_t base = sb + s * 49152;
        const __nv_bfloat16* pAh = gAh + (size_t)tt * 64;
        const __nv_bfloat16* pAl = gAl + (size_t)tt * 64;
        const __nv_bfloat16* pBh = gBh + (size_t)tt * 64;
        const __nv_bfloat16* pBl = gBl + (size_t)tt * 64;
        #pragma unroll
        for (int q = 0; q < 4; q++) {
            int c = ac0 + q;
            uint32_t off = ar * 128 + ((c ^ (ar & 7)) << 4);
            CPA16(base + off,         pAh + c * 8);
            CPA16(base + 16384 + off, pAl + c * 8);
        }
        #pragma unroll
        for (int q = 0; q < 2; q++) {
            int c = bc0 + q;
            uint32_t off = br * 128 + ((c ^ (br & 7)) << 4);
            CPA16(base + 32768 + off, pBh + c * 8);
            CPA16(base + 40960 + off, pBl + c * 8);
        }
    };

    load_stage(0, 0);
    CPC();

    for (int tt = 0; tt < T; tt++) {
        if (tt + 1 < T) {
            load_stage(tt + 1, (tt + 1) & 1);
            CPC();
            asm volatile("cp.async.wait_group 1;" ::: "memory");
        } else {
            asm volatile("cp.async.wait_group 0;" ::: "memory");
        }
        __syncthreads();

        uint32_t base = sb + (tt & 1) * 49152;
        #pragma unroll
        for (int ks = 0; ks < 4; ks++) {
            uint32_t ahf[4][4], alf[4][4], bhf[4], blf[4];
            int ch = ks * 2 + kh;
            #pragma unroll
            for (int mi = 0; mi < 4; mi++) {
                int r = m0 + mi * 16 + lr;
                uint32_t a = base + r * 128 + ((ch ^ (r & 7)) << 4);
                LDSM4(ahf[mi][0], ahf[mi][1], ahf[mi][2], ahf[mi][3], a);
                LDSM4(alf[mi][0], alf[mi][1], alf[mi][2], alf[mi][3], a + 16384);
            }
            int bch = ks * 2 + bko;
            uint32_t ba = base + 32768 + brow * 128 + ((bch ^ (brow & 7)) << 4);
            LDSM4(bhf[0], bhf[1], bhf[2], bhf[3], ba);
            LDSM4(blf[0], blf[1], blf[2], blf[3], ba + 8192);

            #pragma unroll
            for (int mi = 0; mi < 4; mi++) {
                #pragma unroll
                for (int nf = 0; nf < 2; nf++) {
                    MMA16816(acc[mi][nf], ahf[mi], bhf + 2 * nf);
                    MMA16816(acc[mi][nf], ahf[mi], blf + 2 * nf);
                    MMA16816(acc[mi][nf], alf[mi], bhf + 2 * nf);
                }
            }
        }
        __syncthreads();
    }

    float* Cf = (MODE == 0) ? g_act1 : g_m2;
    #pragma unroll
    for (int mi = 0; mi < 4; mi++) {
        #pragma unroll
        for (int nf = 0; nf < 2; nf++) {
            int col = col0 + n0 + nf * 8 + (lane & 3) * 2;
            float b0 = bias[col], b1 = bias[col + 1];
            #pragma unroll
            for (int h = 0; h < 2; h++) {
                int row = row0 + m0 + mi * 16 + (lane >> 2) + h * 8;
                float v0 = fmaxf(acc[mi][nf][h * 2 + 0] + b0, 0.f);
                float v1 = fmaxf(acc[mi][nf][h * 2 + 1] + b1, 0.f);
                size_t idx = (size_t)row * 256 + col;
                if (OUTF32) {
                    *(float2*)(Cf + idx) = make_float2(v0, v1);
                } else {
                    __nv_bfloat16 h0, l0, h1, l1;
                    bsplit(v0, h0, l0);
                    bsplit(v1, h1, l1);
                    *(__nv_bfloat162*)(g_mh + idx) = __halves2bfloat162(h0, h1);
                    *(__nv_bfloat162*)(g_ml + idx) = __halves2bfloat162(l0, l1);
                }
            }
        }
    }
}

// ---------------- weight split kernels ----------------
__global__ void wsplit0(const float* __restrict__ w, int n)
{
    int i = blockIdx.x * 256 + threadIdx.x;
    if (i >= n) return;
    __nv_bfloat16 hh, ll;
    bsplit(w[i], hh, ll);
    g_fwh[i] = hh;
    g_fwl[i] = ll;
}
__global__ void wsplit4(const float* __restrict__ w0, const float* __restrict__ w1,
                        const float* __restrict__ w2, const float* __restrict__ w3)
{
    int i = blockIdx.x * 256 + threadIdx.x;   // grid 1024 -> 262144 threads
    int which = i >> 16, j = i & 65535;
    const float* src = (which == 0) ? w0 : (which == 1) ? w1 : (which == 2) ? w2 : w3;
    __nv_bfloat16 hh, ll;
    bsplit(src[j], hh, ll);
    g_qwh[i] = hh;
    g_qwl[i] = ll;
}

// ============ fused conv1(SIMT) + conv2(bf16x3 MMA) ============
// One batch row per block. h1 stored [pos][ic] bf16 hi/lo with 80B row stride,
// so im2col A[p][k=tap*32+ic] = h1_flat shifted rows; every 16-k slice is one
// contiguous 32B chunk -> direct ldmatrix. MMA: M=32(oc), N=256(pos), K=96.
#define CV_SMEM 56960
// smem offsets (bytes)
#define CV_SCAN 0
#define CV_W1   1024
#define CV_B1   1664
#define CV_B2   1792
#define CV_H1H  2048
#define CV_H1L  22848
#define CV_W2H  43648
#define CV_W2L  50304

__global__ void __launch_bounds__(256, 2) conv_kernel(
    const float* __restrict__ scan,
    const float* __restrict__ w1, const float* __restrict__ b1,
    const float* __restrict__ w2, const float* __restrict__ b2)
{
    extern __shared__ char smem[];
    const uint32_t sb = smem_u32(smem);
    float* s_scan = (float*)(smem + CV_SCAN);
    float* s_w1   = (float*)(smem + CV_W1);
    float* s_b1   = (float*)(smem + CV_B1);
    float* s_b2   = (float*)(smem + CV_B2);
    __nv_bfloat16* s_h1h = (__nv_bfloat16*)(smem + CV_H1H);
    __nv_bfloat16* s_h1l = (__nv_bfloat16*)(smem + CV_H1L);
    __nv_bfloat16* s_w2h = (__nv_bfloat16*)(smem + CV_W2H);
    __nv_bfloat16* s_w2l = (__nv_bfloat16*)(smem + CV_W2L);

    const int t = threadIdx.x, lane = t & 31, wid = t >> 5;
    const int row = blockIdx.x;

    s_scan[t] = scan[(size_t)row * 256 + t];
    if (t < 160) s_w1[t] = w1[t];
    if (t < 32) { s_b1[t] = b1[t]; s_b2[t] = b2[t]; }
    // w2 split: [oc][k = tap*32+ic], row stride 104 bf16 (208B)
    for (int idx = t; idx < 3072; idx += 256) {
        int oc = idx / 96, rem = idx % 96;
        int ic = rem / 3, tap = rem % 3;
        __nv_bfloat16 hh, ll;
        bsplit(w2[idx], hh, ll);
        int o = oc * 104 + tap * 32 + ic;
        s_w2h[o] = hh;
        s_w2l[o] = ll;
    }
    __syncthreads();

    // conv1 (fp32) -> split h1 [pos][ic], stride 40 bf16 (80B)
    for (int idx = t; idx < 8064; idx += 256) {
        int p = idx >> 5, ic = idx & 31;
        float a = s_b1[ic];
        #pragma unroll
        for (int tap = 0; tap < 5; tap++)
            a += s_w1[ic * 5 + tap] * s_scan[p + tap];
        a = fmaxf(a, 0.f);
        __nv_bfloat16 hh, ll;
        bsplit(a, hh, ll);
        s_h1h[p * 40 + ic] = hh;
        s_h1l[p * 40 + ic] = ll;
    }
    // zero-pad positions 252..259
    {
        int p = 252 + (t >> 5), ic = t & 31;
        s_h1h[p * 40 + ic] = __float2bfloat16(0.f);
        s_h1l[p * 40 + ic] = __float2bfloat16(0.f);
    }
    __syncthreads();

    // ---- MMA phase: each warp computes oc 0..31 x positions [wid*32, +32) ----
    const int n0 = wid * 32;
    const int lr = lane & 15;
    const int kh = lane >> 4;
    const int browl = (lane & 7) + ((lane >> 4) << 3);
    const int bko = (lane >> 3) & 1;

    float acc[2][4][4];
    #pragma unroll
    for (int a = 0; a < 2; a++)
        #pragma unroll
        for (int b = 0; b < 4; b++)
            #pragma unroll
            for (int c = 0; c < 4; c++) acc[a][b][c] = 0.f;

    #pragma unroll
    for (int ks = 0; ks < 6; ks++) {
        int tap = ks >> 1;
        int ic16 = (ks & 1) * 32;    // byte offset within h1 row

        uint32_t awh[2][4], awl[2][4];
        #pragma unroll
        for (int mi = 0; mi < 2; mi++) {
            uint32_t a = sb + CV_W2H + (mi * 16 + lr) * 208 + ks * 32 + kh * 16;
            LDSM4(awh[mi][0], awh[mi][1], awh[mi][2], awh[mi][3], a);
            LDSM4(awl[mi][0], awl[mi][1], awl[mi][2], awl[mi][3], a + 6656);
        }
        uint32_t bh[2][4], bl[2][4];
        #pragma unroll
        for (int nt = 0; nt < 2; nt++) {
            int nrow = n0 + nt * 16 + browl + tap;
            uint32_t b = sb + CV_H1H + nrow * 80 + ic16 + bko * 16;
            LDSM4(bh[nt][0], bh[nt][1], bh[nt][2], bh[nt][3], b);
            LDSM4(bl[nt][0], bl[nt][1], bl[nt][2], bl[nt][3], b + 20800);
        }
        #pragma unroll
        for (int mi = 0; mi < 2; mi++) {
            #pragma unroll
            for (int nj = 0; nj < 4; nj++) {
                int nt = nj >> 1, hf = (nj & 1) * 2;
                MMA16816(acc[mi][nj], awh[mi], &bh[nt][hf]);
                MMA16816(acc[mi][nj], awh[mi], &bl[nt][hf]);
                MMA16816(acc[mi][nj], awl[mi], &bh[nt][hf]);
            }
        }
    }

    // epilogue: d rows = oc, cols = positions
    __nv_bfloat16* oh = g_ah + (size_t)row * 8000;
    __nv_bfloat16* ol = g_al + (size_t)row * 8000;
    #pragma unroll
    for (int mi = 0; mi < 2; mi++) {
        #pragma unroll
        for (int nj = 0; nj < 4; nj++) {
            int p0 = n0 + nj * 8 + (lane & 3) * 2;
            if (p0 < 250) {
                #pragma unroll
                for (int h = 0; h < 2; h++) {
                    int oc = mi * 16 + (lane >> 2) + h * 8;
                    float bb = s_b2[oc];
                    float v0 = fmaxf(acc[mi][nj][h * 2 + 0] + bb, 0.f);
                    float v1 = fmaxf(acc[mi][nj][h * 2 + 1] + bb, 0.f);
                    __nv_bfloat16 h0, l0, h1, l1;
                    bsplit(v0, h0, l0);
                    bsplit(v1, h1, l1);
                    int o = oc * 250 + p0;
                    *(__nv_bfloat162*)(oh + o) = __halves2bfloat162(h0, h1);
                    *(__nv_bfloat162*)(ol + o) = __halves2bfloat162(l0, l1);
                }
            }
        }
    }
}

// ---------------- fc2 (256->10) + concat[obs,acts,feats] -> g_inps ----------------
__global__ void __launch_bounds__(256) fc2_concat(
    const float* __restrict__ w2, const float* __restrict__ b2,
    const float* __restrict__ obs, const float* __restrict__ acts)
{
    __shared__ float fs[8][10];
    int warp = threadIdx.x >> 5, lane = threadIdx.x & 31;
    int r = blockIdx.x * 8 + warp;

    const float* xr = g_act1 + (size_t)r * 256;
    float x[8];
    #pragma unroll
    for (int i = 0; i < 8; i++) x[i] = xr[lane + 32 * i];

    #pragma unroll
    for (int j = 0; j < 10; j++) {
        float s = 0.f;
        #pragma unroll
        for (int i = 0; i < 8; i++) s += x[i] * w2[j * 256 + lane + 32 * i];
        #pragma unroll
        for (int off = 16; off; off >>= 1) s += __shfl_xor_sync(0xffffffffu, s, off);
        if (lane == 0) fs[warp][j] = s + b2[j];
    }
    __syncwarp();

    float* ir = g_inps + (size_t)r * 60;
    for (int c = lane; c < 60; c += 32) {
        float v;
        if (c < 48)      v = obs[(size_t)r * 48 + c];
        else if (c < 50) v = acts[(size_t)r * 2 + (c - 48)];
        else             v = fs[warp][c - 50];
        ir[c] = v;
    }
}

// ---------------- batch stats ----------------
__global__ void __launch_bounds__(256) stats_kernel()
{
    int c = blockIdx.x, t = threadIdx.x;
    float s = 0.f, sq = 0.f;
    for (int r = t; r < NROW; r += 256) {
        float v = g_inps[(size_t)r * 60 + c];
        s += v; sq += v * v;
    }
    __shared__ float sh1[256], sh2[256];
    sh1[t] = s; sh2[t] = sq;
    __syncthreads();
    for (int st = 128; st; st >>= 1) {
        if (t < st) { sh1[t] += sh1[t + st]; sh2[t] += sh2[t + st]; }
        __syncthreads();
    }
    if (t == 0) {
        float mu = sh1[0] * (1.f / NROW);
        float var = sh2[0] * (1.f / NROW) - mu * mu;
        g_stats[c] = mu;
        g_stats[64 + c] = rsqrtf(var + 1e-5f);
    }
}

// -------- normalize + encoder(leaky) + keys/vals/q ----------
__global__ void __launch_bounds__(256) enc_kvq(
    const float* __restrict__ enc_w, const float* __restrict__ enc_b,
    const float* __restrict__ Wk, const float* __restrict__ Wv,
    const float* __restrict__ bv, const float* __restrict__ Wq)
{
    __shared__ float xn[32][60];
    __shared__ float sas[32][128];
    __shared__ float wch[32][129];
    __shared__ float mu_s[60], inv_s[60];

    int t = threadIdx.x;
    int row0 = blockIdx.x * 32;
    int g = row0 >> 12;

    if (t < 60) { mu_s[t] = g_stats[t]; inv_s[t] = g_stats[64 + t]; }
    __syncthreads();

    for (int idx = t; idx < 32 * 60; idx += 256) {
        int r = idx / 60, c = idx % 60;
        xn[r][c] = (g_inps[(size_t)(row0 + r) * 60 + c] - mu_s[c]) * inv_s[c];
    }
    __syncthreads();

    int jj = t & 31, rg = t >> 5;

    for (int jc = 0; jc < 4; jc++) {
        for (int idx = t; idx < 32 * 60; idx += 256) {
            int rr = idx / 60, c = idx % 60;
            wch[rr][c] = enc_w[(jc * 32 + rr) * 60 + c];
        }
        __syncthreads();

        float a0 = 0.f, a1 = 0.f, a2 = 0.f, a3 = 0.f;
        #pragma unroll
        for (int c = 0; c < 60; c++) {
            float w = wch[jj][c];
            a0 += xn[rg * 4 + 0][c] * w;
            a1 += xn[rg * 4 + 1][c] * w;
            a2 += xn[rg * 4 + 2][c] * w;
            a3 += xn[rg * 4 + 3][c] * w;
        }
        float bb = enc_b[jc * 32 + jj];
        float v[4] = {a0 + bb, a1 + bb, a2 + bb, a3 + bb};
        int col = jc * 32 + jj;
        #pragma unroll
        for (int q = 0; q < 4; q++) {
            float vv = (v[q] >= 0.f) ? v[q] : 0.01f * v[q];
            sas[rg * 4 + q][col] = vv;
            __nv_bfloat16 hh, ll;
            bsplit(vv, hh, ll);
            size_t idx = (size_t)(row0 + rg * 4 + q) * 256 + col;
            g_embh[idx] = hh;
            g_embl[idx] = ll;
        }
        __syncthreads();
    }

    for (int m = 0; m < 3; m++) {
        const float* W = (m == 0) ? Wk : (m == 1) ? Wv : (Wq + (size_t)g * 128 * 128);
        float* Out     = (m == 0) ? g_keys : (m == 1) ? g_vals : g_q;
        for (int jc = 0; jc < 4; jc++) {
            for (int idx = t; idx < 32 * 128; idx += 256) {
                int rr = idx >> 7, c = idx & 127;
                wch[rr][c] = W[(jc * 32 + rr) * 128 + c];
            }
            __syncthreads();

            float a0 = 0.f, a1 = 0.f, a2 = 0.f, a3 = 0.f;
            #pragma unroll
            for (int c = 0; c < 128; c++) {
                float w = wch[jj][c];
                a0 += sas[rg * 4 + 0][c] * w;
                a1 += sas[rg * 4 + 1][c] * w;
                a2 += sas[rg * 4 + 2][c] * w;
                a3 += sas[rg * 4 + 3][c] * w;
            }
            int col = jc * 32 + jj;
            if (m == 1) {
                float bb = bv[col];
                a0 += bb; a1 += bb; a2 += bb; a3 += bb;
                a0 = (a0 >= 0.f) ? a0 : 0.01f * a0;
                a1 = (a1 >= 0.f) ? a1 : 0.01f * a1;
                a2 = (a2 >= 0.f) ? a2 : 0.01f * a2;
                a3 = (a3 >= 0.f) ? a3 : 0.01f * a3;
            }
            Out[(size_t)(row0 + rg * 4 + 0) * 128 + col] = a0;
            Out[(size_t)(row0 + rg * 4 + 1) * 128 + col] = a1;
            Out[(size_t)(row0 + rg * 4 + 2) * 128 + col] = a2;
            Out[(size_t)(row0 + rg * 4 + 3) * 128 + col] = a3;
            __syncthreads();
        }
    }
}

// ---------------- tiny 3-agent cross-attention ----------------
__global__ void __launch_bounds__(128) attn_kernel()
{
    __shared__ float qs[3][128], ks[3][128], vs[3][128];
    int b = blockIdx.x;
    int t = threadIdx.x;

    #pragma unroll
    for (int g = 0; g < 3; g++) {
        size_t roff = (size_t)(g * BSZ + b) * 128 + t;
        qs[g][t] = g_q[roff];
        ks[g][t] = g_keys[roff];
        vs[g][t] = g_vals[roff];
    }
    __syncthreads();

    const float scale = 0.25f;
    #pragma unroll
    for (int g = 0; g < 3; g++) {
        int o1 = (g == 0) ? 1 : 0;
        int o2 = (g == 2) ? 1 : 2;
        float q = qs[g][t];
        float p1 = q * ks[o1][t];
        float p2 = q * ks[o2][t];
        #pragma unroll
        for (int off = 8; off; off >>= 1) {
            p1 += __shfl_xor_sync(0xffffffffu, p1, off);
            p2 += __shfl_xor_sync(0xffffffffu, p2, off);
        }
        float l1 = p1 * scale, l2 = p2 * scale;
        float mx = fmaxf(l1, l2);
        float e1 = expf(l1 - mx), e2 = expf(l2 - mx);
        float inv = 1.f / (e1 + e2);
        float other = (e1 * vs[o1][t] + e2 * vs[o2][t]) * inv;
        __nv_bfloat16 hh, ll;
        bsplit(other, hh, ll);
        size_t idx = (size_t)(g * BSZ + b) * 256 + 128 + t;
        g_embh[idx] = hh;
        g_embl[idx] = ll;
    }
}

// ---------------- final 256 -> 1 dot per row ----------------
__global__ void __launch_bounds__(256) final_dot(
    const float* __restrict__ w3, const float* __restrict__ b3, float* __restrict__ out)
{
    int warp = threadIdx.x >> 5, lane = threadIdx.x & 31;
    int r = blockIdx.x * 8 + warp;
    const float* xr = g_m2 + (size_t)r * 256;
    float s = 0.f;
    #pragma unroll
    for (int i = 0; i < 8; i++) s += xr[lane + 32 * i] * w3[lane + 32 * i];
    #pragma unroll
    for (int off = 16; off; off >>= 1) s += __shfl_xor_sync(0xffffffffu, s, off);
    if (lane == 0) out[r] = s + b3[0];
}

// ---------------- launch ----------------
extern "C" void kernel_launch(void* const* d_in, const int* in_sizes, int n_in,
                              void* d_out, int out_size)
{
    const float* obs     = (const float*)d_in[0];
    const float* acts    = (const float*)d_in[1];
    const float* scan    = (const float*)d_in[2];
    const float* conv_w1 = (const float*)d_in[3];
    const float* conv_b1 = (const float*)d_in[4];
    const float* conv_w2 = (const float*)d_in[5];
    const float* conv_b2 = (const float*)d_in[6];
    const float* fc_w1   = (const float*)d_in[7];
    const float* fc_b1   = (const float*)d_in[8];
    const float* fc_w2   = (const float*)d_in[9];
    const float* fc_b2   = (const float*)d_in[10];
    const float* enc_w   = (const float*)d_in[11];
    const float* enc_b   = (const float*)d_in[12];
    const float* Wk      = (const float*)d_in[13];
    const float* Wv      = (const float*)d_in[14];
    const float* bv      = (const float*)d_in[15];
    const float* Wq      = (const float*)d_in[16];
    const float* q1_w1   = (const float*)d_in[17];
    const float* q1_b1   = (const float*)d_in[18];
    const float* q1_w2   = (const float*)d_in[19];
    const float* q1_b2   = (const float*)d_in[20];
    const float* q1_w3   = (const float*)d_in[21];
    const float* q1_b3   = (const float*)d_in[22];
    const float* q2_w1   = (const float*)d_in[23];
    const float* q2_b1   = (const float*)d_in[24];
    const float* q2_w2   = (const float*)d_in[25];
    const float* q2_b2   = (const float*)d_in[26];
    const float* q2_w3   = (const float*)d_in[27];
    const float* q2_b3   = (const float*)d_in[28];
    float* out = (float*)d_out;

    cudaFuncSetAttribute(gemm_bf3<0>, cudaFuncAttributeMaxDynamicSharedMemorySize, GSMEM);
    cudaFuncSetAttribute(gemm_bf3<1>, cudaFuncAttributeMaxDynamicSharedMemorySize, GSMEM);
    cudaFuncSetAttribute(gemm_bf3<2>, cudaFuncAttributeMaxDynamicSharedMemorySize, GSMEM);
    cudaFuncSetAttribute(gemm_bf3<3>, cudaFuncAttributeMaxDynamicSharedMemorySize, GSMEM);
    cudaFuncSetAttribute(gemm_bf3<4>, cudaFuncAttributeMaxDynamicSharedMemorySize, GSMEM);
    cudaFuncSetAttribute(conv_kernel, cudaFuncAttributeMaxDynamicSharedMemorySize, CV_SMEM);

    dim3 ggrid(4, 96);   // N=256/64, M=12288/128

    // weight splits (independent of conv)
    wsplit0<<<(256 * 8000 + 255) / 256, 256>>>(fc_w1, 256 * 8000);
    wsplit4<<<1024, 256>>>(q1_w1, q1_w2, q2_w1, q2_w2);

    conv_kernel<<<NROW, 256, CV_SMEM>>>(scan, conv_w1, conv_b1, conv_w2, conv_b2);
    gemm_bf3<0><<<ggrid, 256, GSMEM>>>(fc_b1, 8000);          // fc1 + relu
    fc2_concat<<<NROW / 8, 256>>>(fc_w2, fc_b2, obs, acts);
    stats_kernel<<<60, 256>>>();
    enc_kvq<<<NROW / 32, 256>>>(enc_w, enc_b, Wk, Wv, bv, Wq);
    attn_kernel<<<BSZ, 128>>>();

    // q1 MLP
    gemm_bf3<1><<<ggrid, 256, GSMEM>>>(q1_b1, 256);
    gemm_bf3<2><<<ggrid, 256, GSMEM>>>(q1_b2, 256);
    final_dot<<<NROW / 8, 256>>>(q1_w3, q1_b3, out);

    // q2 MLP
    gemm_bf3<3><<<ggrid, 256, GSMEM>>>(q2_b1, 256);
    gemm_bf3<4><<<ggrid, 256, GSMEM>>>(q2_b2, 256);
    final_dot<<<NROW / 8, 256>>>(q2_w3, q2_b3, out + NROW);
}

// round 5
// speedup vs baseline: 3.9513x; 1.2387x over previous
#include <cuda_runtime.h>
#include <cuda_bf16.h>
#include <math.h>
#include <cstdint>

#define NROW 12288
#define BSZ  4096

// ---------------- scratch (device globals; no allocations) ----------------
__device__ float g_h2[(size_t)NROW * 8000];           // conv output (fp32)
__device__ __nv_bfloat16 g_fwh[256 * 8000];           // fc_w1 hi
__device__ __nv_bfloat16 g_fwl[256 * 8000];           // fc_w1 lo
__device__ __nv_bfloat16 g_qwh[4 * 256 * 256];        // slots: q1_w1,q2_w1,q1_w2,q2_w2 hi
__device__ __nv_bfloat16 g_qwl[4 * 256 * 256];        // lo
__device__ float g_part[3 * (size_t)NROW * 256];      // fc1 K-split partials
__device__ float g_inps[NROW * 60];
__device__ float g_stats[128];
__device__ __nv_bfloat16 g_embh[NROW * 256];          // emb split
__device__ __nv_bfloat16 g_embl[NROW * 256];
__device__ __nv_bfloat16 g_mh[(size_t)NROW * 512];    // mlp hidden split (q1|q2)
__device__ __nv_bfloat16 g_ml[(size_t)NROW * 512];
__device__ float g_m2[(size_t)NROW * 512];            // mlp layer2 out (q1|q2)
__device__ float g_keys[NROW * 128];
__device__ float g_vals[NROW * 128];
__device__ float g_q[NROW * 128];

// ====================== helpers ======================
__device__ __forceinline__ uint32_t smem_u32(const void* p) {
    uint32_t a;
    asm("{ .reg .u64 t; cvta.to.shared.u64 t, %1; cvt.u32.u64 %0, t; }"
        : "=r"(a) : "l"(p));
    return a;
}
__device__ __forceinline__ void bsplit(float v, __nv_bfloat16& h, __nv_bfloat16& l) {
    h = __float2bfloat16(v);
    l = __float2bfloat16(v - __bfloat162float(h));
}
#define CPA16(s, g) \
    asm volatile("cp.async.cg.shared.global [%0], [%1], 16;" :: "r"(s), "l"(g))
#define CPC() asm volatile("cp.async.commit_group;" ::: "memory")
#define LDSM4(r0, r1, r2, r3, a) \
    asm volatile("ldmatrix.sync.aligned.m8n8.x4.shared.b16 {%0,%1,%2,%3}, [%4];" \
                 : "=r"(r0), "=r"(r1), "=r"(r2), "=r"(r3) : "r"(a))
#define MMA16816(d, a, b) \
    asm volatile("mma.sync.aligned.m16n8k16.row.col.f32.bf16.bf16.f32 " \
                 "{%0,%1,%2,%3},{%4,%5,%6,%7},{%8,%9},{%0,%1,%2,%3};" \
                 : "+f"((d)[0]), "+f"((d)[1]), "+f"((d)[2]), "+f"((d)[3]) \
                 : "r"((a)[0]), "r"((a)[1]), "r"((a)[2]), "r"((a)[3]), \
                   "r"((b)[0]), "r"((b)[1]))

// ================= fc1: bf16x3 GEMM, BM128/BN128/BK32, 3-stage, K-split ==========
// A = g_h2 fp32 (split in-kernel); B = g_fwh/g_fwl; out fp32 partial (no bias/relu).
// grid (2, 96, 3); 8 warps as 2M x 4N (warp tile 64x32).
#define FSMEM (3 * 32768)
__global__ void __launch_bounds__(256, 2) fc1_gemm()
{
    extern __shared__ char smem[];
    const uint32_t sb = smem_u32(smem);

    const int t = threadIdx.x, lane = t & 31, wid = t >> 5;
    const int bn = blockIdx.x, bm = blockIdx.y, z = blockIdx.z;
    const int kt0 = (z == 0) ? 0 : (z == 1) ? 84 : 167;
    const int T   = (z == 0) ? 84 : 83;
    const int row0 = bm * 128, col0 = bn * 128;

    // fill mapping: fr = row 0..127, each thread covers 16 k-elements
    const int fr = t >> 1;
    const int c0 = (t & 1) * 2;    // 16B-chunk base (4 chunks per 64B row)
    const float* gA = g_h2 + (size_t)(row0 + fr) * 8000 + kt0 * 32 + (t & 1) * 16;
    const __nv_bfloat16* gBh = g_fwh + (size_t)(col0 + fr) * 8000 + kt0 * 32;
    const __nv_bfloat16* gBl = g_fwl + (size_t)(col0 + fr) * 8000 + kt0 * 32;
    const int fsw = (fr >> 1) & 3;

    // compute mapping
    const int mw = wid & 1, nw = wid >> 1;

    float acc[4][4][4];
    #pragma unroll
    for (int a = 0; a < 4; a++)
        #pragma unroll
        for (int b = 0; b < 4; b++)
            #pragma unroll
            for (int c = 0; c < 4; c++) acc[a][b][c] = 0.f;

    auto fill = [&](int tt, int s) {
        char* st = smem + s * 32768;
        // A: LDG fp32 -> split -> STS
        const float4* pa = (const float4*)(gA + (size_t)tt * 32);
        float v[16];
        *(float4*)(v)      = pa[0];
        *(float4*)(v + 4)  = pa[1];
        *(float4*)(v + 8)  = pa[2];
        *(float4*)(v + 12) = pa[3];
        uint32_t hp[8], lp[8];
        #pragma unroll
        for (int i = 0; i < 8; i++) {
            __nv_bfloat16 h0, l0, h1, l1;
            bsplit(v[2 * i], h0, l0);
            bsplit(v[2 * i + 1], h1, l1);
            __nv_bfloat162 hh = __halves2bfloat162(h0, h1);
            __nv_bfloat162 ll = __halves2bfloat162(l0, l1);
            hp[i] = *(uint32_t*)&hh;
            lp[i] = *(uint32_t*)&ll;
        }
        #pragma unroll
        for (int j = 0; j < 2; j++) {
            int cs = (c0 + j) ^ fsw;
            *(uint4*)(st + fr * 64 + cs * 16) =
                make_uint4(hp[j * 4], hp[j * 4 + 1], hp[j * 4 + 2], hp[j * 4 + 3]);
            *(uint4*)(st + 8192 + fr * 64 + cs * 16) =
                make_uint4(lp[j * 4], lp[j * 4 + 1], lp[j * 4 + 2], lp[j * 4 + 3]);
        }
        // B via cp.async
        const __nv_bfloat16* pbh = gBh + (size_t)tt * 32;
        const __nv_bfloat16* pbl = gBl + (size_t)tt * 32;
        #pragma unroll
        for (int j = 0; j < 2; j++) {
            int c = c0 + j;
            int cs = c ^ fsw;
            CPA16(sb + s * 32768 + 16384 + fr * 64 + cs * 16, pbh + c * 8);
            CPA16(sb + s * 32768 + 24576 + fr * 64 + cs * 16, pbl + c * 8);
        }
    };

    fill(0, 0); CPC();
    fill(1, 1); CPC();

    for (int tt = 0; tt < T; tt++) {
        asm volatile("cp.async.wait_group 1;" ::: "memory");
        __syncthreads();

        const uint32_t stu = sb + (tt % 3) * 32768;
        #pragma unroll
        for (int ks = 0; ks < 2; ks++) {
            uint32_t bhf[2][4], blf[2][4];
            #pragma unroll
            for (int nt = 0; nt < 2; nt++) {
                int nr = nw * 32 + nt * 16 + (lane & 7) + ((lane >> 4) << 3);
                int cs = (ks * 2 + ((lane >> 3) & 1)) ^ ((nr >> 1) & 3);
                uint32_t ba = stu + 16384 + nr * 64 + cs * 16;
                LDSM4(bhf[nt][0], bhf[nt][1], bhf[nt][2], bhf[nt][3], ba);
                LDSM4(blf[nt][0], blf[nt][1], blf[nt][2], blf[nt][3], ba + 8192);
            }
            #pragma unroll
            for (int mi = 0; mi < 4; mi++) {
                int r = mw * 64 + mi * 16 + (lane & 15);
                int cs = (ks * 2 + (lane >> 4)) ^ ((r >> 1) & 3);
                uint32_t aa = stu + r * 64 + cs * 16;
                uint32_t ah[4], al[4];
                LDSM4(ah[0], ah[1], ah[2], ah[3], aa);
                LDSM4(al[0], al[1], al[2], al[3], aa + 8192);
                #pragma unroll
                for (int nj = 0; nj < 4; nj++) {
                    int nt = nj >> 1, hf = (nj & 1) * 2;
                    MMA16816(acc[mi][nj], ah, &bhf[nt][hf]);
                    MMA16816(acc[mi][nj], ah, &blf[nt][hf]);
                    MMA16816(acc[mi][nj], al, &bhf[nt][hf]);
                }
            }
        }

        if (tt + 2 < T) fill(tt + 2, (tt + 2) % 3);
        CPC();
    }

    // epilogue: fp32 partials (no bias/relu)
    float* P = g_part + (size_t)z * NROW * 256;
    #pragma unroll
    for (int mi = 0; mi < 4; mi++) {
        #pragma unroll
        for (int nj = 0; nj < 4; nj++) {
            int col = col0 + nw * 32 + nj * 8 + (lane & 3) * 2;
            #pragma unroll
            for (int h = 0; h < 2; h++) {
                int row = row0 + mw * 64 + mi * 16 + (lane >> 2) + h * 8;
                *(float2*)(P + (size_t)row * 256 + col) =
                    make_float2(acc[mi][nj][h * 2], acc[mi][nj][h * 2 + 1]);
            }
        }
    }
}

// ============ MLP GEMM (K=256): BM128/BN64/BK64, 2-stage, bf16x3 ============
// LAYER 1: A=emb(256-wide), B rows 0..511 (q1_w1|q2_w1), out split -> g_mh/g_ml[512]
// LAYER 2: z sel: A=g_mh+z*256 (512 stride), B slot 2+z, out fp32 -> g_m2 col z*256+
#define GSMEM 98304
template <int LAYER>
__global__ void __launch_bounds__(256, 2) mlp_gemm(
    const float* __restrict__ biasA, const float* __restrict__ biasB)
{
    const int K = 256;
    const int z = (LAYER == 2) ? blockIdx.z : 0;
    const __nv_bfloat16* Ah = (LAYER == 1) ? g_embh : g_mh + z * 256;
    const __nv_bfloat16* Al = (LAYER == 1) ? g_embl : g_ml + z * 256;
    const int AS = (LAYER == 1) ? 256 : 512;
    const __nv_bfloat16* Bh = (LAYER == 1) ? g_qwh : g_qwh + (2 + z) * 65536;
    const __nv_bfloat16* Bl = (LAYER == 1) ? g_qwl : g_qwl + (2 + z) * 65536;

    extern __shared__ char smem[];
    const uint32_t sb = smem_u32(smem);

    const int t = threadIdx.x, lane = t & 31, wid = t >> 5;
    const int row0 = blockIdx.y * 128, col0 = blockIdx.x * 64;

    const int ar = t >> 1, ac0 = (t & 1) * 4;
    const int br = t >> 2, bc0 = (t & 3) * 2;
    const __nv_bfloat16* gAh = Ah + (size_t)(row0 + ar) * AS;
    const __nv_bfloat16* gAl = Al + (size_t)(row0 + ar) * AS;
    const __nv_bfloat16* gBh = Bh + (size_t)(col0 + br) * K;
    const __nv_bfloat16* gBl = Bl + (size_t)(col0 + br) * K;

    const int m0 = (wid & 1) * 64;
    const int n0 = (wid >> 1) * 16;
    const int lr = lane & 15;
    const int kh = lane >> 4;
    const int brow = n0 + (lane & 7) + ((lane >> 4) << 3);
    const int bko = (lane >> 3) & 1;

    const int T = K / 64;   // 4
    float acc[4][2][4];
    #pragma unroll
    for (int a = 0; a < 4; a++)
        #pragma unroll
        for (int b = 0; b < 2; b++)
            #pragma unroll
            for (int c = 0; c < 4; c++) acc[a][b][c] = 0.f;

    auto load_stage = [&](int tt, int s) {
        uint32_t base = sb + s * 49152;
        const __nv_bfloat16* pAh = gAh + tt * 64;
        const __nv_bfloat16* pAl = gAl + tt * 64;
        const __nv_bfloat16* pBh = gBh + tt * 64;
        const __nv_bfloat16* pBl = gBl + tt * 64;
        #pragma unroll
        for (int q = 0; q < 4; q++) {
            int c = ac0 + q;
            uint32_t off = ar * 128 + ((c ^ (ar & 7)) << 4);
            CPA16(base + off,         pAh + c * 8);
            CPA16(base + 16384 + off, pAl + c * 8);
        }
        #pragma unroll
        for (int q = 0; q < 2; q++) {
            int c = bc0 + q;
            uint32_t off = br * 128 + ((c ^ (br & 7)) << 4);
            CPA16(base + 32768 + off, pBh + c * 8);
            CPA16(base + 40960 + off, pBl + c * 8);
        }
    };

    load_stage(0, 0);
    CPC();

    for (int tt = 0; tt < T; tt++) {
        if (tt + 1 < T) {
            load_stage(tt + 1, (tt + 1) & 1);
            CPC();
            asm volatile("cp.async.wait_group 1;" ::: "memory");
        } else {
            asm volatile("cp.async.wait_group 0;" ::: "memory");
        }
        __syncthreads();

        uint32_t base = sb + (tt & 1) * 49152;
        #pragma unroll
        for (int ks = 0; ks < 4; ks++) {
            uint32_t ahf[4][4], alf[4][4], bhf[4], blf[4];
            int ch = ks * 2 + kh;
            #pragma unroll
            for (int mi = 0; mi < 4; mi++) {
                int r = m0 + mi * 16 + lr;
                uint32_t a = base + r * 128 + ((ch ^ (r & 7)) << 4);
                LDSM4(ahf[mi][0], ahf[mi][1], ahf[mi][2], ahf[mi][3], a);
                LDSM4(alf[mi][0], alf[mi][1], alf[mi][2], alf[mi][3], a + 16384);
            }
            int bch = ks * 2 + bko;
            uint32_t ba = base + 32768 + brow * 128 + ((bch ^ (brow & 7)) << 4);
            LDSM4(bhf[0], bhf[1], bhf[2], bhf[3], ba);
            LDSM4(blf[0], blf[1], blf[2], blf[3], ba + 8192);

            #pragma unroll
            for (int mi = 0; mi < 4; mi++) {
                #pragma unroll
                for (int nf = 0; nf < 2; nf++) {
                    MMA16816(acc[mi][nf], ahf[mi], bhf + 2 * nf);
                    MMA16816(acc[mi][nf], ahf[mi], blf + 2 * nf);
                    MMA16816(acc[mi][nf], alf[mi], bhf + 2 * nf);
                }
            }
        }
        __syncthreads();
    }

    #pragma unroll
    for (int mi = 0; mi < 4; mi++) {
        #pragma unroll
        for (int nf = 0; nf < 2; nf++) {
            int ocl = col0 + n0 + nf * 8 + (lane & 3) * 2;   // local col
            float b0, b1;
            if (LAYER == 1) {
                b0 = (ocl < 256) ? biasA[ocl] : biasB[ocl - 256];
                b1 = (ocl + 1 < 256) ? biasA[ocl + 1] : biasB[ocl + 1 - 256];
            } else {
                const float* bb = z ? biasB : biasA;
                b0 = bb[ocl]; b1 = bb[ocl + 1];
            }
            int ocg = (LAYER == 1) ? ocl : z * 256 + ocl;
            #pragma unroll
            for (int h = 0; h < 2; h++) {
                int row = row0 + m0 + mi * 16 + (lane >> 2) + h * 8;
                float v0 = fmaxf(acc[mi][nf][h * 2 + 0] + b0, 0.f);
                float v1 = fmaxf(acc[mi][nf][h * 2 + 1] + b1, 0.f);
                size_t idx = (size_t)row * 512 + ocg;
                if (LAYER == 2) {
                    *(float2*)(g_m2 + idx) = make_float2(v0, v1);
                } else {
                    __nv_bfloat16 h0, l0, h1, l1;
                    bsplit(v0, h0, l0);
                    bsplit(v1, h1, l1);
                    *(__nv_bfloat162*)(g_mh + idx) = __halves2bfloat162(h0, h1);
                    *(__nv_bfloat162*)(g_ml + idx) = __halves2bfloat162(l0, l1);
                }
            }
        }
    }
}

// ---------------- weight split kernels ----------------
__global__ void wsplit0(const float* __restrict__ w, int n)
{
    int i = blockIdx.x * 256 + threadIdx.x;
    if (i >= n) return;
    __nv_bfloat16 hh, ll;
    bsplit(w[i], hh, ll);
    g_fwh[i] = hh;
    g_fwl[i] = ll;
}
__global__ void wsplit4(const float* __restrict__ w0, const float* __restrict__ w1,
                        const float* __restrict__ w2, const float* __restrict__ w3)
{
    int i = blockIdx.x * 256 + threadIdx.x;
    int which = i >> 16, j = i & 65535;
    const float* src = (which == 0) ? w0 : (which == 1) ? w1 : (which == 2) ? w2 : w3;
    __nv_bfloat16 hh, ll;
    bsplit(src[j], hh, ll);
    g_qwh[i] = hh;
    g_qwl[i] = ll;
}

// ============ fused conv1(SIMT) + conv2(bf16x3 MMA), fp32 out ============
#define CV_SMEM 56960
#define CV_SCAN 0
#define CV_W1   1024
#define CV_B1   1664
#define CV_B2   1792
#define CV_H1H  2048
#define CV_H1L  22848
#define CV_W2H  43648
#define CV_W2L  50304

__global__ void __launch_bounds__(256, 2) conv_kernel(
    const float* __restrict__ scan,
    const float* __restrict__ w1, const float* __restrict__ b1,
    const float* __restrict__ w2, const float* __restrict__ b2)
{
    extern __shared__ char smem[];
    const uint32_t sb = smem_u32(smem);
    float* s_scan = (float*)(smem + CV_SCAN);
    float* s_w1   = (float*)(smem + CV_W1);
    float* s_b1   = (float*)(smem + CV_B1);
    float* s_b2   = (float*)(smem + CV_B2);
    __nv_bfloat16* s_h1h = (__nv_bfloat16*)(smem + CV_H1H);
    __nv_bfloat16* s_h1l = (__nv_bfloat16*)(smem + CV_H1L);
    __nv_bfloat16* s_w2h = (__nv_bfloat16*)(smem + CV_W2H);
    __nv_bfloat16* s_w2l = (__nv_bfloat16*)(smem + CV_W2L);

    const int t = threadIdx.x, lane = t & 31, wid = t >> 5;
    const int row = blockIdx.x;

    s_scan[t] = scan[(size_t)row * 256 + t];
    if (t < 160) s_w1[t] = w1[t];
    if (t < 32) { s_b1[t] = b1[t]; s_b2[t] = b2[t]; }
    for (int idx = t; idx < 3072; idx += 256) {
        int oc = idx / 96, rem = idx % 96;
        int ic = rem / 3, tap = rem % 3;
        __nv_bfloat16 hh, ll;
        bsplit(w2[idx], hh, ll);
        int o = oc * 104 + tap * 32 + ic;
        s_w2h[o] = hh;
        s_w2l[o] = ll;
    }
    __syncthreads();

    for (int idx = t; idx < 8064; idx += 256) {
        int p = idx >> 5, ic = idx & 31;
        float a = s_b1[ic];
        #pragma unroll
        for (int tap = 0; tap < 5; tap++)
            a += s_w1[ic * 5 + tap] * s_scan[p + tap];
        a = fmaxf(a, 0.f);
        __nv_bfloat16 hh, ll;
        bsplit(a, hh, ll);
        s_h1h[p * 40 + ic] = hh;
        s_h1l[p * 40 + ic] = ll;
    }
    {
        int p = 252 + (t >> 5), ic = t & 31;
        s_h1h[p * 40 + ic] = __float2bfloat16(0.f);
        s_h1l[p * 40 + ic] = __float2bfloat16(0.f);
    }
    __syncthreads();

    const int n0 = wid * 32;
    const int lr = lane & 15;
    const int kh = lane >> 4;
    const int browl = (lane & 7) + ((lane >> 4) << 3);
    const int bko = (lane >> 3) & 1;

    float acc[2][4][4];
    #pragma unroll
    for (int a = 0; a < 2; a++)
        #pragma unroll
        for (int b = 0; b < 4; b++)
            #pragma unroll
            for (int c = 0; c < 4; c++) acc[a][b][c] = 0.f;

    #pragma unroll
    for (int ks = 0; ks < 6; ks++) {
        int tap = ks >> 1;
        int ic16 = (ks & 1) * 32;

        uint32_t awh[2][4], awl[2][4];
        #pragma unroll
        for (int mi = 0; mi < 2; mi++) {
            uint32_t a = sb + CV_W2H + (mi * 16 + lr) * 208 + ks * 32 + kh * 16;
            LDSM4(awh[mi][0], awh[mi][1], awh[mi][2], awh[mi][3], a);
            LDSM4(awl[mi][0], awl[mi][1], awl[mi][2], awl[mi][3], a + 6656);
        }
        uint32_t bh[2][4], bl[2][4];
        #pragma unroll
        for (int nt = 0; nt < 2; nt++) {
            int nrow = n0 + nt * 16 + browl + tap;
            uint32_t b = sb + CV_H1H + nrow * 80 + ic16 + bko * 16;
            LDSM4(bh[nt][0], bh[nt][1], bh[nt][2], bh[nt][3], b);
            LDSM4(bl[nt][0], bl[nt][1], bl[nt][2], bl[nt][3], b + 20800);
        }
        #pragma unroll
        for (int mi = 0; mi < 2; mi++) {
            #pragma unroll
            for (int nj = 0; nj < 4; nj++) {
                int nt = nj >> 1, hf = (nj & 1) * 2;
                MMA16816(acc[mi][nj], awh[mi], &bh[nt][hf]);
                MMA16816(acc[mi][nj], awh[mi], &bl[nt][hf]);
                MMA16816(acc[mi][nj], awl[mi], &bh[nt][hf]);
            }
        }
    }

    float* orow = g_h2 + (size_t)row * 8000;
    #pragma unroll
    for (int mi = 0; mi < 2; mi++) {
        #pragma unroll
        for (int nj = 0; nj < 4; nj++) {
            int p0 = n0 + nj * 8 + (lane & 3) * 2;
            if (p0 < 250) {
                #pragma unroll
                for (int h = 0; h < 2; h++) {
                    int oc = mi * 16 + (lane >> 2) + h * 8;
                    float bb = s_b2[oc];
                    float v0 = fmaxf(acc[mi][nj][h * 2 + 0] + bb, 0.f);
                    float v1 = fmaxf(acc[mi][nj][h * 2 + 1] + bb, 0.f);
                    *(float2*)(orow + oc * 250 + p0) = make_float2(v0, v1);
                }
            }
        }
    }
}

// -------- fc1 combine + fc2 (256->10) + concat[obs,acts,feats] -> g_inps --------
__global__ void __launch_bounds__(256) fc2_concat(
    const float* __restrict__ w2, const float* __restrict__ b2,
    const float* __restrict__ b1,
    const float* __restrict__ obs, const float* __restrict__ acts)
{
    __shared__ float fs[8][10];
    int warp = threadIdx.x >> 5, lane = threadIdx.x & 31;
    int r = blockIdx.x * 8 + warp;

    const float* p0 = g_part + (size_t)r * 256;
    const float* p1 = p0 + (size_t)NROW * 256;
    const float* p2 = p1 + (size_t)NROW * 256;
    float x[8];
    #pragma unroll
    for (int i = 0; i < 8; i++) {
        int c = lane + 32 * i;
        x[i] = fmaxf(p0[c] + p1[c] + p2[c] + b1[c], 0.f);
    }

    #pragma unroll
    for (int j = 0; j < 10; j++) {
        float s = 0.f;
        #pragma unroll
        for (int i = 0; i < 8; i++) s += x[i] * w2[j * 256 + lane + 32 * i];
        #pragma unroll
        for (int off = 16; off; off >>= 1) s += __shfl_xor_sync(0xffffffffu, s, off);
        if (lane == 0) fs[warp][j] = s + b2[j];
    }
    __syncwarp();

    float* ir = g_inps + (size_t)r * 60;
    for (int c = lane; c < 60; c += 32) {
        float v;
        if (c < 48)      v = obs[(size_t)r * 48 + c];
        else if (c < 50) v = acts[(size_t)r * 2 + (c - 48)];
        else             v = fs[warp][c - 50];
        ir[c] = v;
    }
}

// ---------------- batch stats ----------------
__global__ void __launch_bounds__(256) stats_kernel()
{
    int c = blockIdx.x, t = threadIdx.x;
    float s = 0.f, sq = 0.f;
    for (int r = t; r < NROW; r += 256) {
        float v = g_inps[(size_t)r * 60 + c];
        s += v; sq += v * v;
    }
    __shared__ float sh1[256], sh2[256];
    sh1[t] = s; sh2[t] = sq;
    __syncthreads();
    for (int st = 128; st; st >>= 1) {
        if (t < st) { sh1[t] += sh1[t + st]; sh2[t] += sh2[t + st]; }
        __syncthreads();
    }
    if (t == 0) {
        float mu = sh1[0] * (1.f / NROW);
        float var = sh2[0] * (1.f / NROW) - mu * mu;
        g_stats[c] = mu;
        g_stats[64 + c] = rsqrtf(var + 1e-5f);
    }
}

// -------- normalize + encoder(leaky) + keys/vals/q ----------
__global__ void __launch_bounds__(256) enc_kvq(
    const float* __restrict__ enc_w, const float* __restrict__ enc_b,
    const float* __restrict__ Wk, const float* __restrict__ Wv,
    const float* __restrict__ bv, const float* __restrict__ Wq)
{
    __shared__ float xn[32][60];
    __shared__ float sas[32][128];
    __shared__ float wch[32][129];
    __shared__ float mu_s[60], inv_s[60];

    int t = threadIdx.x;
    int row0 = blockIdx.x * 32;
    int g = row0 >> 12;

    if (t < 60) { mu_s[t] = g_stats[t]; inv_s[t] = g_stats[64 + t]; }
    __syncthreads();

    for (int idx = t; idx < 32 * 60; idx += 256) {
        int r = idx / 60, c = idx % 60;
        xn[r][c] = (g_inps[(size_t)(row0 + r) * 60 + c] - mu_s[c]) * inv_s[c];
    }
    __syncthreads();

    int jj = t & 31, rg = t >> 5;

    for (int jc = 0; jc < 4; jc++) {
        for (int idx = t; idx < 32 * 60; idx += 256) {
            int rr = idx / 60, c = idx % 60;
            wch[rr][c] = enc_w[(jc * 32 + rr) * 60 + c];
        }
        __syncthreads();

        float a0 = 0.f, a1 = 0.f, a2 = 0.f, a3 = 0.f;
        #pragma unroll
        for (int c = 0; c < 60; c++) {
            float w = wch[jj][c];
            a0 += xn[rg * 4 + 0][c] * w;
            a1 += xn[rg * 4 + 1][c] * w;
            a2 += xn[rg * 4 + 2][c] * w;
            a3 += xn[rg * 4 + 3][c] * w;
        }
        float bb = enc_b[jc * 32 + jj];
        float v[4] = {a0 + bb, a1 + bb, a2 + bb, a3 + bb};
        int col = jc * 32 + jj;
        #pragma unroll
        for (int q = 0; q < 4; q++) {
            float vv = (v[q] >= 0.f) ? v[q] : 0.01f * v[q];
            sas[rg * 4 + q][col] = vv;
            __nv_bfloat16 hh, ll;
            bsplit(vv, hh, ll);
            size_t idx = (size_t)(row0 + rg * 4 + q) * 256 + col;
            g_embh[idx] = hh;
            g_embl[idx] = ll;
        }
        __syncthreads();
    }

    for (int m = 0; m < 3; m++) {
        const float* W = (m == 0) ? Wk : (m == 1) ? Wv : (Wq + (size_t)g * 128 * 128);
        float* Out     = (m == 0) ? g_keys : (m == 1) ? g_vals : g_q;
        for (int jc = 0; jc < 4; jc++) {
            for (int idx = t; idx < 32 * 128; idx += 256) {
                int rr = idx >> 7, c = idx & 127;
                wch[rr][c] = W[(jc * 32 + rr) * 128 + c];
            }
            __syncthreads();

            float a0 = 0.f, a1 = 0.f, a2 = 0.f, a3 = 0.f;
            #pragma unroll
            for (int c = 0; c < 128; c++) {
                float w = wch[jj][c];
                a0 += sas[rg * 4 + 0][c] * w;
                a1 += sas[rg * 4 + 1][c] * w;
                a2 += sas[rg * 4 + 2][c] * w;
                a3 += sas[rg * 4 + 3][c] * w;
            }
            int col = jc * 32 + jj;
            if (m == 1) {
                float bb = bv[col];
                a0 += bb; a1 += bb; a2 += bb; a3 += bb;
                a0 = (a0 >= 0.f) ? a0 : 0.01f * a0;
                a1 = (a1 >= 0.f) ? a1 : 0.01f * a1;
                a2 = (a2 >= 0.f) ? a2 : 0.01f * a2;
                a3 = (a3 >= 0.f) ? a3 : 0.01f * a3;
            }
            Out[(size_t)(row0 + rg * 4 + 0) * 128 + col] = a0;
            Out[(size_t)(row0 + rg * 4 + 1) * 128 + col] = a1;
            Out[(size_t)(row0 + rg * 4 + 2) * 128 + col] = a2;
            Out[(size_t)(row0 + rg * 4 + 3) * 128 + col] = a3;
            __syncthreads();
        }
    }
}

// ---------------- tiny 3-agent cross-attention ----------------
__global__ void __launch_bounds__(128) attn_kernel()
{
    __shared__ float qs[3][128], ks[3][128], vs[3][128];
    int b = blockIdx.x;
    int t = threadIdx.x;

    #pragma unroll
    for (int g = 0; g < 3; g++) {
        size_t roff = (size_t)(g * BSZ + b) * 128 + t;
        qs[g][t] = g_q[roff];
        ks[g][t] = g_keys[roff];
        vs[g][t] = g_vals[roff];
    }
    __syncthreads();

    const float scale = 0.25f;
    #pragma unroll
    for (int g = 0; g < 3; g++) {
        int o1 = (g == 0) ? 1 : 0;
        int o2 = (g == 2) ? 1 : 2;
        float q = qs[g][t];
        float p1 = q * ks[o1][t];
        float p2 = q * ks[o2][t];
        #pragma unroll
        for (int off = 8; off; off >>= 1) {
            p1 += __shfl_xor_sync(0xffffffffu, p1, off);
            p2 += __shfl_xor_sync(0xffffffffu, p2, off);
        }
        float l1 = p1 * scale, l2 = p2 * scale;
        float mx = fmaxf(l1, l2);
        float e1 = expf(l1 - mx), e2 = expf(l2 - mx);
        float inv = 1.f / (e1 + e2);
        float other = (e1 * vs[o1][t] + e2 * vs[o2][t]) * inv;
        __nv_bfloat16 hh, ll;
        bsplit(other, hh, ll);
        size_t idx = (size_t)(g * BSZ + b) * 256 + 128 + t;
        g_embh[idx] = hh;
        g_embl[idx] = ll;
    }
}

// ---------------- fused final dots (q1 & q2) ----------------
__global__ void __launch_bounds__(256) final_dot2(
    const float* __restrict__ w3a, const float* __restrict__ b3a,
    const float* __restrict__ w3b, const float* __restrict__ b3b,
    float* __restrict__ out)
{
    int warp = threadIdx.x >> 5, lane = threadIdx.x & 31;
    int r = blockIdx.x * 8 + warp;
    const float* xr = g_m2 + (size_t)r * 512;
    float s1 = 0.f, s2 = 0.f;
    #pragma unroll
    for (int i = 0; i < 8; i++) {
        int c = lane + 32 * i;
        s1 += xr[c] * w3a[c];
        s2 += xr[256 + c] * w3b[c];
    }
    #pragma unroll
    for (int off = 16; off; off >>= 1) {
        s1 += __shfl_xor_sync(0xffffffffu, s1, off);
        s2 += __shfl_xor_sync(0xffffffffu, s2, off);
    }
    if (lane == 0) {
        out[r] = s1 + b3a[0];
        out[NROW + r] = s2 + b3b[0];
    }
}

// ---------------- launch ----------------
extern "C" void kernel_launch(void* const* d_in, const int* in_sizes, int n_in,
                              void* d_out, int out_size)
{
    const float* obs     = (const float*)d_in[0];
    const float* acts    = (const float*)d_in[1];
    const float* scan    = (const float*)d_in[2];
    const float* conv_w1 = (const float*)d_in[3];
    const float* conv_b1 = (const float*)d_in[4];
    const float* conv_w2 = (const float*)d_in[5];
    const float* conv_b2 = (const float*)d_in[6];
    const float* fc_w1   = (const float*)d_in[7];
    const float* fc_b1   = (const float*)d_in[8];
    const float* fc_w2   = (const float*)d_in[9];
    const float* fc_b2   = (const float*)d_in[10];
    const float* enc_w   = (const float*)d_in[11];
    const float* enc_b   = (const float*)d_in[12];
    const float* Wk      = (const float*)d_in[13];
    const float* Wv      = (const float*)d_in[14];
    const float* bv      = (const float*)d_in[15];
    const float* Wq      = (const float*)d_in[16];
    const float* q1_w1   = (const float*)d_in[17];
    const float* q1_b1   = (const float*)d_in[18];
    const float* q1_w2   = (const float*)d_in[19];
    const float* q1_b2   = (const float*)d_in[20];
    const float* q1_w3   = (const float*)d_in[21];
    const float* q1_b3   = (const float*)d_in[22];
    const float* q2_w1   = (const float*)d_in[23];
    const float* q2_b1   = (const float*)d_in[24];
    const float* q2_w2   = (const float*)d_in[25];
    const float* q2_b2   = (const float*)d_in[26];
    const float* q2_w3   = (const float*)d_in[27];
    const float* q2_b3   = (const float*)d_in[28];
    float* out = (float*)d_out;

    cudaFuncSetAttribute(fc1_gemm, cudaFuncAttributeMaxDynamicSharedMemorySize, FSMEM);
    cudaFuncSetAttribute(mlp_gemm<1>, cudaFuncAttributeMaxDynamicSharedMemorySize, GSMEM);
    cudaFuncSetAttribute(mlp_gemm<2>, cudaFuncAttributeMaxDynamicSharedMemorySize, GSMEM);
    cudaFuncSetAttribute(conv_kernel, cudaFuncAttributeMaxDynamicSharedMemorySize, CV_SMEM);

    // weight splits (slots: 0=q1_w1, 1=q2_w1, 2=q1_w2, 3=q2_w2)
    wsplit0<<<(256 * 8000 + 255) / 256, 256>>>(fc_w1, 256 * 8000);
    wsplit4<<<1024, 256>>>(q1_w1, q2_w1, q1_w2, q2_w2);

    conv_kernel<<<NROW, 256, CV_SMEM>>>(scan, conv_w1, conv_b1, conv_w2, conv_b2);
    fc1_gemm<<<dim3(2, 96, 3), 256, FSMEM>>>();
    fc2_concat<<<NROW / 8, 256>>>(fc_w2, fc_b2, fc_b1, obs, acts);
    stats_kernel<<<60, 256>>>();
    enc_kvq<<<NROW / 32, 256>>>(enc_w, enc_b, Wk, Wv, bv, Wq);
    attn_kernel<<<BSZ, 128>>>();

    mlp_gemm<1><<<dim3(8, 96), 256, GSMEM>>>(q1_b1, q2_b1);
    mlp_gemm<2><<<dim3(4, 96, 2), 256, GSMEM>>>(q1_b2, q2_b2);
    final_dot2<<<NROW / 8, 256>>>(q1_w3, q1_b3, q2_w3, q2_b3, out);
}

// round 6
// speedup vs baseline: 4.0455x; 1.0239x over previous
#include <cuda_runtime.h>
#include <cuda_bf16.h>
#include <math.h>
#include <cstdint>

#define NROW 12288
#define BSZ  4096

// ---------------- scratch (device globals; no allocations) ----------------
__device__ __nv_bfloat16 g_ah[(size_t)NROW * 8000];  // conv output hi
__device__ __nv_bfloat16 g_al[(size_t)NROW * 8000];  // conv output lo
__device__ __nv_bfloat16 g_fwh[256 * 8000];          // fc_w1 hi
__device__ __nv_bfloat16 g_fwl[256 * 8000];          // fc_w1 lo
__device__ __nv_bfloat16 g_qwh[4 * 256 * 256];       // q1_w1,q2_w1,q1_w2,q2_w2 hi
__device__ __nv_bfloat16 g_qwl[4 * 256 * 256];       // lo
__device__ __nv_bfloat16 g_cw2h[32 * 104];           // conv w2 pre-split (smem layout)
__device__ __nv_bfloat16 g_cw2l[32 * 104];
__device__ float g_part[3 * (size_t)NROW * 256];     // fc1 K-split partials
__device__ float g_inps[NROW * 60];
__device__ float g_stats[128];
__device__ __nv_bfloat16 g_embh[NROW * 256];
__device__ __nv_bfloat16 g_embl[NROW * 256];
__device__ __nv_bfloat16 g_mh[(size_t)NROW * 512];
__device__ __nv_bfloat16 g_ml[(size_t)NROW * 512];
__device__ float g_m2[(size_t)NROW * 512];
__device__ float g_keys[NROW * 128];
__device__ float g_vals[NROW * 128];
__device__ float g_q[NROW * 128];

// ====================== helpers ======================
__device__ __forceinline__ uint32_t smem_u32(const void* p) {
    uint32_t a;
    asm("{ .reg .u64 t; cvta.to.shared.u64 t, %1; cvt.u32.u64 %0, t; }"
        : "=r"(a) : "l"(p));
    return a;
}
__device__ __forceinline__ void bsplit(float v, __nv_bfloat16& h, __nv_bfloat16& l) {
    h = __float2bfloat16(v);
    l = __float2bfloat16(v - __bfloat162float(h));
}
#define CPA16(s, g) \
    asm volatile("cp.async.cg.shared.global [%0], [%1], 16;" :: "r"(s), "l"(g))
#define CPC() asm volatile("cp.async.commit_group;" ::: "memory")
#define LDSM4(r0, r1, r2, r3, a) \
    asm volatile("ldmatrix.sync.aligned.m8n8.x4.shared.b16 {%0,%1,%2,%3}, [%4];" \
                 : "=r"(r0), "=r"(r1), "=r"(r2), "=r"(r3) : "r"(a))
#define MMA16816(d, a, b) \
    asm volatile("mma.sync.aligned.m16n8k16.row.col.f32.bf16.bf16.f32 " \
                 "{%0,%1,%2,%3},{%4,%5,%6,%7},{%8,%9},{%0,%1,%2,%3};" \
                 : "+f"((d)[0]), "+f"((d)[1]), "+f"((d)[2]), "+f"((d)[3]) \
                 : "r"((a)[0]), "r"((a)[1]), "r"((a)[2]), "r"((a)[3]), \
                   "r"((b)[0]), "r"((b)[1]))

// ================= fc1: bf16x3 GEMM, BM128/BN128/BK32, 3-stage, K-split =========
// A = g_ah/g_al; B = g_fwh/g_fwl (all pre-split, pure cp.async fills).
// grid (2, 96, 3); 8 warps as 2M x 4N (warp tile 64x32). Out fp32 partials.
#define FSMEM (3 * 32768)
__global__ void __launch_bounds__(256, 2) fc1_gemm()
{
    extern __shared__ char smem[];
    const uint32_t sb = smem_u32(smem);

    const int t = threadIdx.x, lane = t & 31, wid = t >> 5;
    const int bn = blockIdx.x, bm = blockIdx.y, z = blockIdx.z;
    const int kt0 = (z == 0) ? 0 : (z == 1) ? 84 : 167;
    const int T   = (z == 0) ? 84 : 83;
    const int row0 = bm * 128, col0 = bn * 128;

    const int fr = t >> 1;
    const int c0 = (t & 1) * 2;
    const __nv_bfloat16* gAh = g_ah + (size_t)(row0 + fr) * 8000 + kt0 * 32;
    const __nv_bfloat16* gAl = g_al + (size_t)(row0 + fr) * 8000 + kt0 * 32;
    const __nv_bfloat16* gBh = g_fwh + (size_t)(col0 + fr) * 8000 + kt0 * 32;
    const __nv_bfloat16* gBl = g_fwl + (size_t)(col0 + fr) * 8000 + kt0 * 32;
    const int fsw = (fr >> 1) & 3;

    const int mw = wid & 1, nw = wid >> 1;

    float acc[4][4][4];
    #pragma unroll
    for (int a = 0; a < 4; a++)
        #pragma unroll
        for (int b = 0; b < 4; b++)
            #pragma unroll
            for (int c = 0; c < 4; c++) acc[a][b][c] = 0.f;

    auto fill = [&](int tt, int s) {
        uint32_t base = sb + s * 32768;
        const __nv_bfloat16* pAh = gAh + (size_t)tt * 32;
        const __nv_bfloat16* pAl = gAl + (size_t)tt * 32;
        const __nv_bfloat16* pBh = gBh + (size_t)tt * 32;
        const __nv_bfloat16* pBl = gBl + (size_t)tt * 32;
        #pragma unroll
        for (int j = 0; j < 2; j++) {
            int c = c0 + j;
            uint32_t off = fr * 64 + ((c ^ fsw) << 4);
            CPA16(base + off,         pAh + c * 8);
            CPA16(base + 8192 + off,  pAl + c * 8);
            CPA16(base + 16384 + off, pBh + c * 8);
            CPA16(base + 24576 + off, pBl + c * 8);
        }
    };

    fill(0, 0); CPC();
    fill(1, 1); CPC();

    for (int tt = 0; tt < T; tt++) {
        asm volatile("cp.async.wait_group 1;" ::: "memory");
        __syncthreads();

        const uint32_t stu = sb + (tt % 3) * 32768;
        #pragma unroll
        for (int ks = 0; ks < 2; ks++) {
            uint32_t bhf[2][4], blf[2][4];
            #pragma unroll
            for (int nt = 0; nt < 2; nt++) {
                int nr = nw * 32 + nt * 16 + (lane & 7) + ((lane >> 4) << 3);
                int cs = (ks * 2 + ((lane >> 3) & 1)) ^ ((nr >> 1) & 3);
                uint32_t ba = stu + 16384 + nr * 64 + cs * 16;
                LDSM4(bhf[nt][0], bhf[nt][1], bhf[nt][2], bhf[nt][3], ba);
                LDSM4(blf[nt][0], blf[nt][1], blf[nt][2], blf[nt][3], ba + 8192);
            }
            #pragma unroll
            for (int mi = 0; mi < 4; mi++) {
                int r = mw * 64 + mi * 16 + (lane & 15);
                int cs = (ks * 2 + (lane >> 4)) ^ ((r >> 1) & 3);
                uint32_t aa = stu + r * 64 + cs * 16;
                uint32_t ah[4], al[4];
                LDSM4(ah[0], ah[1], ah[2], ah[3], aa);
                LDSM4(al[0], al[1], al[2], al[3], aa + 8192);
                #pragma unroll
                for (int nj = 0; nj < 4; nj++) {
                    int nt = nj >> 1, hf = (nj & 1) * 2;
                    MMA16816(acc[mi][nj], ah, &bhf[nt][hf]);
                    MMA16816(acc[mi][nj], ah, &blf[nt][hf]);
                    MMA16816(acc[mi][nj], al, &bhf[nt][hf]);
                }
            }
        }

        if (tt + 2 < T) fill(tt + 2, (tt + 2) % 3);
        CPC();
    }

    float* P = g_part + (size_t)z * NROW * 256;
    #pragma unroll
    for (int mi = 0; mi < 4; mi++) {
        #pragma unroll
        for (int nj = 0; nj < 4; nj++) {
            int col = col0 + nw * 32 + nj * 8 + (lane & 3) * 2;
            #pragma unroll
            for (int h = 0; h < 2; h++) {
                int row = row0 + mw * 64 + mi * 16 + (lane >> 2) + h * 8;
                *(float2*)(P + (size_t)row * 256 + col) =
                    make_float2(acc[mi][nj][h * 2], acc[mi][nj][h * 2 + 1]);
            }
        }
    }
}

// ============ MLP GEMM (K=256): BM128/BN64/BK64, 2-stage, bf16x3 ============
#define GSMEM 98304
template <int LAYER>
__global__ void __launch_bounds__(256, 2) mlp_gemm(
    const float* __restrict__ biasA, const float* __restrict__ biasB)
{
    const int K = 256;
    const int z = (LAYER == 2) ? blockIdx.z : 0;
    const __nv_bfloat16* Ah = (LAYER == 1) ? g_embh : g_mh + z * 256;
    const __nv_bfloat16* Al = (LAYER == 1) ? g_embl : g_ml + z * 256;
    const int AS = (LAYER == 1) ? 256 : 512;
    const __nv_bfloat16* Bh = (LAYER == 1) ? g_qwh : g_qwh + (2 + z) * 65536;
    const __nv_bfloat16* Bl = (LAYER == 1) ? g_qwl : g_qwl + (2 + z) * 65536;

    extern __shared__ char smem[];
    const uint32_t sb = smem_u32(smem);

    const int t = threadIdx.x, lane = t & 31, wid = t >> 5;
    const int row0 = blockIdx.y * 128, col0 = blockIdx.x * 64;

    const int ar = t >> 1, ac0 = (t & 1) * 4;
    const int br = t >> 2, bc0 = (t & 3) * 2;
    const __nv_bfloat16* gAh = Ah + (size_t)(row0 + ar) * AS;
    const __nv_bfloat16* gAl = Al + (size_t)(row0 + ar) * AS;
    const __nv_bfloat16* gBh = Bh + (size_t)(col0 + br) * K;
    const __nv_bfloat16* gBl = Bl + (size_t)(col0 + br) * K;

    const int m0 = (wid & 1) * 64;
    const int n0 = (wid >> 1) * 16;
    const int lr = lane & 15;
    const int kh = lane >> 4;
    const int brow = n0 + (lane & 7) + ((lane >> 4) << 3);
    const int bko = (lane >> 3) & 1;

    const int T = K / 64;
    float acc[4][2][4];
    #pragma unroll
    for (int a = 0; a < 4; a++)
        #pragma unroll
        for (int b = 0; b < 2; b++)
            #pragma unroll
            for (int c = 0; c < 4; c++) acc[a][b][c] = 0.f;

    auto load_stage = [&](int tt, int s) {
        uint32_t base = sb + s * 49152;
        const __nv_bfloat16* pAh = gAh + tt * 64;
        const __nv_bfloat16* pAl = gAl + tt * 64;
        const __nv_bfloat16* pBh = gBh + tt * 64;
        const __nv_bfloat16* pBl = gBl + tt * 64;
        #pragma unroll
        for (int q = 0; q < 4; q++) {
            int c = ac0 + q;
            uint32_t off = ar * 128 + ((c ^ (ar & 7)) << 4);
            CPA16(base + off,         pAh + c * 8);
            CPA16(base + 16384 + off, pAl + c * 8);
        }
        #pragma unroll
        for (int q = 0; q < 2; q++) {
            int c = bc0 + q;
            uint32_t off = br * 128 + ((c ^ (br & 7)) << 4);
            CPA16(base + 32768 + off, pBh + c * 8);
            CPA16(base + 40960 + off, pBl + c * 8);
        }
    };

    load_stage(0, 0);
    CPC();

    for (int tt = 0; tt < T; tt++) {
        if (tt + 1 < T) {
            load_stage(tt + 1, (tt + 1) & 1);
            CPC();
            asm volatile("cp.async.wait_group 1;" ::: "memory");
        } else {
            asm volatile("cp.async.wait_group 0;" ::: "memory");
        }
        __syncthreads();

        uint32_t base = sb + (tt & 1) * 49152;
        #pragma unroll
        for (int ks = 0; ks < 4; ks++) {
            uint32_t ahf[4][4], alf[4][4], bhf[4], blf[4];
            int ch = ks * 2 + kh;
            #pragma unroll
            for (int mi = 0; mi < 4; mi++) {
                int r = m0 + mi * 16 + lr;
                uint32_t a = base + r * 128 + ((ch ^ (r & 7)) << 4);
                LDSM4(ahf[mi][0], ahf[mi][1], ahf[mi][2], ahf[mi][3], a);
                LDSM4(alf[mi][0], alf[mi][1], alf[mi][2], alf[mi][3], a + 16384);
            }
            int bch = ks * 2 + bko;
            uint32_t ba = base + 32768 + brow * 128 + ((bch ^ (brow & 7)) << 4);
            LDSM4(bhf[0], bhf[1], bhf[2], bhf[3], ba);
            LDSM4(blf[0], blf[1], blf[2], blf[3], ba + 8192);

            #pragma unroll
            for (int mi = 0; mi < 4; mi++) {
                #pragma unroll
                for (int nf = 0; nf < 2; nf++) {
                    MMA16816(acc[mi][nf], ahf[mi], bhf + 2 * nf);
                    MMA16816(acc[mi][nf], ahf[mi], blf + 2 * nf);
                    MMA16816(acc[mi][nf], alf[mi], bhf + 2 * nf);
                }
            }
        }
        __syncthreads();
    }

    #pragma unroll
    for (int mi = 0; mi < 4; mi++) {
        #pragma unroll
        for (int nf = 0; nf < 2; nf++) {
            int ocl = col0 + n0 + nf * 8 + (lane & 3) * 2;
            float b0, b1;
            if (LAYER == 1) {
                b0 = (ocl < 256) ? biasA[ocl] : biasB[ocl - 256];
                b1 = (ocl + 1 < 256) ? biasA[ocl + 1] : biasB[ocl + 1 - 256];
            } else {
                const float* bb = z ? biasB : biasA;
                b0 = bb[ocl]; b1 = bb[ocl + 1];
            }
            int ocg = (LAYER == 1) ? ocl : z * 256 + ocl;
            #pragma unroll
            for (int h = 0; h < 2; h++) {
                int row = row0 + m0 + mi * 16 + (lane >> 2) + h * 8;
                float v0 = fmaxf(acc[mi][nf][h * 2 + 0] + b0, 0.f);
                float v1 = fmaxf(acc[mi][nf][h * 2 + 1] + b1, 0.f);
                size_t idx = (size_t)row * 512 + ocg;
                if (LAYER == 2) {
                    *(float2*)(g_m2 + idx) = make_float2(v0, v1);
                } else {
                    __nv_bfloat16 h0, l0, h1, l1;
                    bsplit(v0, h0, l0);
                    bsplit(v1, h1, l1);
                    *(__nv_bfloat162*)(g_mh + idx) = __halves2bfloat162(h0, h1);
                    *(__nv_bfloat162*)(g_ml + idx) = __halves2bfloat162(l0, l1);
                }
            }
        }
    }
}

// ---------------- weight split kernels ----------------
__global__ void wsplit0(const float* __restrict__ w, int n)
{
    int i = blockIdx.x * 256 + threadIdx.x;
    if (i >= n) return;
    __nv_bfloat16 hh, ll;
    bsplit(w[i], hh, ll);
    g_fwh[i] = hh;
    g_fwl[i] = ll;
}
__global__ void wsplit4(const float* __restrict__ w0, const float* __restrict__ w1,
                        const float* __restrict__ w2, const float* __restrict__ w3)
{
    int i = blockIdx.x * 256 + threadIdx.x;
    int which = i >> 16, j = i & 65535;
    const float* src = (which == 0) ? w0 : (which == 1) ? w1 : (which == 2) ? w2 : w3;
    __nv_bfloat16 hh, ll;
    bsplit(src[j], hh, ll);
    g_qwh[i] = hh;
    g_qwl[i] = ll;
}
// conv w2 pre-split into smem layout [oc stride 104]: k = tap*32+ic
__global__ void wsplit_cv(const float* __restrict__ w2)
{
    int idx = threadIdx.x + blockIdx.x * 256;   // grid 12 x 256 = 3072
    if (idx >= 3072) return;
    int oc = idx / 96, rem = idx % 96;
    int ic = rem / 3, tap = rem % 3;
    __nv_bfloat16 hh, ll;
    bsplit(w2[idx], hh, ll);
    int o = oc * 104 + tap * 32 + ic;
    g_cw2h[o] = hh;
    g_cw2l[o] = ll;
}

// ============ fused conv1(SIMT) + conv2(bf16x3 MMA), split out ============
#define CV_SMEM 56960
#define CV_SCAN 0
#define CV_W1   1024
#define CV_B1   1664
#define CV_B2   1792
#define CV_H1H  2048
#define CV_H1L  22848
#define CV_W2H  43648
#define CV_W2L  50304

__global__ void __launch_bounds__(256, 2) conv_kernel(
    const float* __restrict__ scan,
    const float* __restrict__ w1, const float* __restrict__ b1,
    const float* __restrict__ b2)
{
    extern __shared__ char smem[];
    const uint32_t sb = smem_u32(smem);
    float* s_scan = (float*)(smem + CV_SCAN);
    float* s_w1   = (float*)(smem + CV_W1);
    float* s_b1   = (float*)(smem + CV_B1);
    float* s_b2   = (float*)(smem + CV_B2);
    __nv_bfloat16* s_h1h = (__nv_bfloat16*)(smem + CV_H1H);
    __nv_bfloat16* s_h1l = (__nv_bfloat16*)(smem + CV_H1L);

    const int t = threadIdx.x, lane = t & 31, wid = t >> 5;
    const int row = blockIdx.x;

    // copy pre-split w2 (6656B per array = 416 x 16B)
    for (int i = t; i < 416; i += 256) {
        CPA16(sb + CV_W2H + i * 16, (const char*)g_cw2h + i * 16);
        CPA16(sb + CV_W2L + i * 16, (const char*)g_cw2l + i * 16);
    }
    CPC();

    s_scan[t] = scan[(size_t)row * 256 + t];
    if (t < 160) s_w1[t] = w1[t];
    if (t < 32) { s_b1[t] = b1[t]; s_b2[t] = b2[t]; }
    asm volatile("cp.async.wait_group 0;" ::: "memory");
    __syncthreads();

    // conv1 (fp32) -> split h1 [pos][ic], stride 40 bf16 (80B)
    for (int idx = t; idx < 8064; idx += 256) {
        int p = idx >> 5, ic = idx & 31;
        float a = s_b1[ic];
        #pragma unroll
        for (int tap = 0; tap < 5; tap++)
            a += s_w1[ic * 5 + tap] * s_scan[p + tap];
        a = fmaxf(a, 0.f);
        __nv_bfloat16 hh, ll;
        bsplit(a, hh, ll);
        s_h1h[p * 40 + ic] = hh;
        s_h1l[p * 40 + ic] = ll;
    }
    {
        int p = 252 + (t >> 5), ic = t & 31;
        s_h1h[p * 40 + ic] = __float2bfloat16(0.f);
        s_h1l[p * 40 + ic] = __float2bfloat16(0.f);
    }
    __syncthreads();

    const int n0 = wid * 32;
    const int lr = lane & 15;
    const int kh = lane >> 4;
    const int browl = (lane & 7) + ((lane >> 4) << 3);
    const int bko = (lane >> 3) & 1;

    float acc[2][4][4];
    #pragma unroll
    for (int a = 0; a < 2; a++)
        #pragma unroll
        for (int b = 0; b < 4; b++)
            #pragma unroll
            for (int c = 0; c < 4; c++) acc[a][b][c] = 0.f;

    #pragma unroll
    for (int ks = 0; ks < 6; ks++) {
        int tap = ks >> 1;
        int ic16 = (ks & 1) * 32;

        uint32_t awh[2][4], awl[2][4];
        #pragma unroll
        for (int mi = 0; mi < 2; mi++) {
            uint32_t a = sb + CV_W2H + (mi * 16 + lr) * 208 + ks * 32 + kh * 16;
            LDSM4(awh[mi][0], awh[mi][1], awh[mi][2], awh[mi][3], a);
            LDSM4(awl[mi][0], awl[mi][1], awl[mi][2], awl[mi][3], a + 6656);
        }
        uint32_t bh[2][4], bl[2][4];
        #pragma unroll
        for (int nt = 0; nt < 2; nt++) {
            int nrow = n0 + nt * 16 + browl + tap;
            uint32_t b = sb + CV_H1H + nrow * 80 + ic16 + bko * 16;
            LDSM4(bh[nt][0], bh[nt][1], bh[nt][2], bh[nt][3], b);
            LDSM4(bl[nt][0], bl[nt][1], bl[nt][2], bl[nt][3], b + 20800);
        }
        #pragma unroll
        for (int mi = 0; mi < 2; mi++) {
            #pragma unroll
            for (int nj = 0; nj < 4; nj++) {
                int nt = nj >> 1, hf = (nj & 1) * 2;
                MMA16816(acc[mi][nj], awh[mi], &bh[nt][hf]);
                MMA16816(acc[mi][nj], awh[mi], &bl[nt][hf]);
                MMA16816(acc[mi][nj], awl[mi], &bh[nt][hf]);
            }
        }
    }

    __nv_bfloat16* oh = g_ah + (size_t)row * 8000;
    __nv_bfloat16* ol = g_al + (size_t)row * 8000;
    #pragma unroll
    for (int mi = 0; mi < 2; mi++) {
        #pragma unroll
        for (int nj = 0; nj < 4; nj++) {
            int p0 = n0 + nj * 8 + (lane & 3) * 2;
            if (p0 < 250) {
                #pragma unroll
                for (int h = 0; h < 2; h++) {
                    int oc = mi * 16 + (lane >> 2) + h * 8;
                    float bb = s_b2[oc];
                    float v0 = fmaxf(acc[mi][nj][h * 2 + 0] + bb, 0.f);
                    float v1 = fmaxf(acc[mi][nj][h * 2 + 1] + bb, 0.f);
                    __nv_bfloat16 h0, l0, h1, l1;
                    bsplit(v0, h0, l0);
                    bsplit(v1, h1, l1);
                    int o = oc * 250 + p0;
                    *(__nv_bfloat162*)(oh + o) = __halves2bfloat162(h0, h1);
                    *(__nv_bfloat162*)(ol + o) = __halves2bfloat162(l0, l1);
                }
            }
        }
    }
}

// -------- fc1 combine + fc2 (256->10) + concat -> g_inps --------
__global__ void __launch_bounds__(256) fc2_concat(
    const float* __restrict__ w2, const float* __restrict__ b2,
    const float* __restrict__ b1,
    const float* __restrict__ obs, const float* __restrict__ acts)
{
    __shared__ float fs[8][10];
    int warp = threadIdx.x >> 5, lane = threadIdx.x & 31;
    int r = blockIdx.x * 8 + warp;

    const float* p0 = g_part + (size_t)r * 256;
    const float* p1 = p0 + (size_t)NROW * 256;
    const float* p2 = p1 + (size_t)NROW * 256;
    float x[8];
    #pragma unroll
    for (int i = 0; i < 8; i++) {
        int c = lane + 32 * i;
        x[i] = fmaxf(p0[c] + p1[c] + p2[c] + b1[c], 0.f);
    }

    #pragma unroll
    for (int j = 0; j < 10; j++) {
        float s = 0.f;
        #pragma unroll
        for (int i = 0; i < 8; i++) s += x[i] * w2[j * 256 + lane + 32 * i];
        #pragma unroll
        for (int off = 16; off; off >>= 1) s += __shfl_xor_sync(0xffffffffu, s, off);
        if (lane == 0) fs[warp][j] = s + b2[j];
    }
    __syncwarp();

    float* ir = g_inps + (size_t)r * 60;
    for (int c = lane; c < 60; c += 32) {
        float v;
        if (c < 48)      v = obs[(size_t)r * 48 + c];
        else if (c < 50) v = acts[(size_t)r * 2 + (c - 48)];
        else             v = fs[warp][c - 50];
        ir[c] = v;
    }
}

// ---------------- batch stats ----------------
__global__ void __launch_bounds__(256) stats_kernel()
{
    int c = blockIdx.x, t = threadIdx.x;
    float s = 0.f, sq = 0.f;
    for (int r = t; r < NROW; r += 256) {
        float v = g_inps[(size_t)r * 60 + c];
        s += v; sq += v * v;
    }
    __shared__ float sh1[256], sh2[256];
    sh1[t] = s; sh2[t] = sq;
    __syncthreads();
    for (int st = 128; st; st >>= 1) {
        if (t < st) { sh1[t] += sh1[t + st]; sh2[t] += sh2[t + st]; }
        __syncthreads();
    }
    if (t == 0) {
        float mu = sh1[0] * (1.f / NROW);
        float var = sh2[0] * (1.f / NROW) - mu * mu;
        g_stats[c] = mu;
        g_stats[64 + c] = rsqrtf(var + 1e-5f);
    }
}

// -------- normalize + encoder(leaky) + keys/vals/q ----------
__global__ void __launch_bounds__(256) enc_kvq(
    const float* __restrict__ enc_w, const float* __restrict__ enc_b,
    const float* __restrict__ Wk, const float* __restrict__ Wv,
    const float* __restrict__ bv, const float* __restrict__ Wq)
{
    __shared__ float xn[32][60];
    __shared__ float sas[32][128];
    __shared__ float wch[32][129];
    __shared__ float mu_s[60], inv_s[60];

    int t = threadIdx.x;
    int row0 = blockIdx.x * 32;
    int g = row0 >> 12;

    if (t < 60) { mu_s[t] = g_stats[t]; inv_s[t] = g_stats[64 + t]; }
    __syncthreads();

    for (int idx = t; idx < 32 * 60; idx += 256) {
        int r = idx / 60, c = idx % 60;
        xn[r][c] = (g_inps[(size_t)(row0 + r) * 60 + c] - mu_s[c]) * inv_s[c];
    }
    __syncthreads();

    int jj = t & 31, rg = t >> 5;

    for (int jc = 0; jc < 4; jc++) {
        for (int idx = t; idx < 32 * 60; idx += 256) {
            int rr = idx / 60, c = idx % 60;
            wch[rr][c] = enc_w[(jc * 32 + rr) * 60 + c];
        }
        __syncthreads();

        float a0 = 0.f, a1 = 0.f, a2 = 0.f, a3 = 0.f;
        #pragma unroll
        for (int c = 0; c < 60; c++) {
            float w = wch[jj][c];
            a0 += xn[rg * 4 + 0][c] * w;
            a1 += xn[rg * 4 + 1][c] * w;
            a2 += xn[rg * 4 + 2][c] * w;
            a3 += xn[rg * 4 + 3][c] * w;
        }
        float bb = enc_b[jc * 32 + jj];
        float v[4] = {a0 + bb, a1 + bb, a2 + bb, a3 + bb};
        int col = jc * 32 + jj;
        #pragma unroll
        for (int q = 0; q < 4; q++) {
            float vv = (v[q] >= 0.f) ? v[q] : 0.01f * v[q];
            sas[rg * 4 + q][col] = vv;
            __nv_bfloat16 hh, ll;
            bsplit(vv, hh, ll);
            size_t idx = (size_t)(row0 + rg * 4 + q) * 256 + col;
            g_embh[idx] = hh;
            g_embl[idx] = ll;
        }
        __syncthreads();
    }

    for (int m = 0; m < 3; m++) {
        const float* W = (m == 0) ? Wk : (m == 1) ? Wv : (Wq + (size_t)g * 128 * 128);
        float* Out     = (m == 0) ? g_keys : (m == 1) ? g_vals : g_q;
        for (int jc = 0; jc < 4; jc++) {
            for (int idx = t; idx < 32 * 128; idx += 256) {
                int rr = idx >> 7, c = idx & 127;
                wch[rr][c] = W[(jc * 32 + rr) * 128 + c];
            }
            __syncthreads();

            float a0 = 0.f, a1 = 0.f, a2 = 0.f, a3 = 0.f;
            #pragma unroll
            for (int c = 0; c < 128; c++) {
                float w = wch[jj][c];
                a0 += sas[rg * 4 + 0][c] * w;
                a1 += sas[rg * 4 + 1][c] * w;
                a2 += sas[rg * 4 + 2][c] * w;
                a3 += sas[rg * 4 + 3][c] * w;
            }
            int col = jc * 32 + jj;
            if (m == 1) {
                float bb = bv[col];
                a0 += bb; a1 += bb; a2 += bb; a3 += bb;
                a0 = (a0 >= 0.f) ? a0 : 0.01f * a0;
                a1 = (a1 >= 0.f) ? a1 : 0.01f * a1;
                a2 = (a2 >= 0.f) ? a2 : 0.01f * a2;
                a3 = (a3 >= 0.f) ? a3 : 0.01f * a3;
            }
            Out[(size_t)(row0 + rg * 4 + 0) * 128 + col] = a0;
            Out[(size_t)(row0 + rg * 4 + 1) * 128 + col] = a1;
            Out[(size_t)(row0 + rg * 4 + 2) * 128 + col] = a2;
            Out[(size_t)(row0 + rg * 4 + 3) * 128 + col] = a3;
            __syncthreads();
        }
    }
}

// ---------------- tiny 3-agent cross-attention ----------------
__global__ void __launch_bounds__(128) attn_kernel()
{
    __shared__ float qs[3][128], ks[3][128], vs[3][128];
    int b = blockIdx.x;
    int t = threadIdx.x;

    #pragma unroll
    for (int g = 0; g < 3; g++) {
        size_t roff = (size_t)(g * BSZ + b) * 128 + t;
        qs[g][t] = g_q[roff];
        ks[g][t] = g_keys[roff];
        vs[g][t] = g_vals[roff];
    }
    __syncthreads();

    const float scale = 0.25f;
    #pragma unroll
    for (int g = 0; g < 3; g++) {
        int o1 = (g == 0) ? 1 : 0;
        int o2 = (g == 2) ? 1 : 2;
        float q = qs[g][t];
        float p1 = q * ks[o1][t];
        float p2 = q * ks[o2][t];
        #pragma unroll
        for (int off = 8; off; off >>= 1) {
            p1 += __shfl_xor_sync(0xffffffffu, p1, off);
            p2 += __shfl_xor_sync(0xffffffffu, p2, off);
        }
        float l1 = p1 * scale, l2 = p2 * scale;
        float mx = fmaxf(l1, l2);
        float e1 = expf(l1 - mx), e2 = expf(l2 - mx);
        float inv = 1.f / (e1 + e2);
        float other = (e1 * vs[o1][t] + e2 * vs[o2][t]) * inv;
        __nv_bfloat16 hh, ll;
        bsplit(other, hh, ll);
        size_t idx = (size_t)(g * BSZ + b) * 256 + 128 + t;
        g_embh[idx] = hh;
        g_embl[idx] = ll;
    }
}

// ---------------- fused final dots (q1 & q2) ----------------
__global__ void __launch_bounds__(256) final_dot2(
    const float* __restrict__ w3a, const float* __restrict__ b3a,
    const float* __restrict__ w3b, const float* __restrict__ b3b,
    float* __restrict__ out)
{
    int warp = threadIdx.x >> 5, lane = threadIdx.x & 31;
    int r = blockIdx.x * 8 + warp;
    const float* xr = g_m2 + (size_t)r * 512;
    float s1 = 0.f, s2 = 0.f;
    #pragma unroll
    for (int i = 0; i < 8; i++) {
        int c = lane + 32 * i;
        s1 += xr[c] * w3a[c];
        s2 += xr[256 + c] * w3b[c];
    }
    #pragma unroll
    for (int off = 16; off; off >>= 1) {
        s1 += __shfl_xor_sync(0xffffffffu, s1, off);
        s2 += __shfl_xor_sync(0xffffffffu, s2, off);
    }
    if (lane == 0) {
        out[r] = s1 + b3a[0];
        out[NROW + r] = s2 + b3b[0];
    }
}

// ---------------- launch ----------------
extern "C" void kernel_launch(void* const* d_in, const int* in_sizes, int n_in,
                              void* d_out, int out_size)
{
    const float* obs     = (const float*)d_in[0];
    const float* acts    = (const float*)d_in[1];
    const float* scan    = (const float*)d_in[2];
    const float* conv_w1 = (const float*)d_in[3];
    const float* conv_b1 = (const float*)d_in[4];
    const float* conv_w2 = (const float*)d_in[5];
    const float* conv_b2 = (const float*)d_in[6];
    const float* fc_w1   = (const float*)d_in[7];
    const float* fc_b1   = (const float*)d_in[8];
    const float* fc_w2   = (const float*)d_in[9];
    const float* fc_b2   = (const float*)d_in[10];
    const float* enc_w   = (const float*)d_in[11];
    const float* enc_b   = (const float*)d_in[12];
    const float* Wk      = (const float*)d_in[13];
    const float* Wv      = (const float*)d_in[14];
    const float* bv      = (const float*)d_in[15];
    const float* Wq      = (const float*)d_in[16];
    const float* q1_w1   = (const float*)d_in[17];
    const float* q1_b1   = (const float*)d_in[18];
    const float* q1_w2   = (const float*)d_in[19];
    const float* q1_b2   = (const float*)d_in[20];
    const float* q1_w3   = (const float*)d_in[21];
    const float* q1_b3   = (const float*)d_in[22];
    const float* q2_w1   = (const float*)d_in[23];
    const float* q2_b1   = (const float*)d_in[24];
    const float* q2_w2   = (const float*)d_in[25];
    const float* q2_b2   = (const float*)d_in[26];
    const float* q2_w3   = (const float*)d_in[27];
    const float* q2_b3   = (const float*)d_in[28];
    float* out = (float*)d_out;

    cudaFuncSetAttribute(fc1_gemm, cudaFuncAttributeMaxDynamicSharedMemorySize, FSMEM);
    cudaFuncSetAttribute(mlp_gemm<1>, cudaFuncAttributeMaxDynamicSharedMemorySize, GSMEM);
    cudaFuncSetAttribute(mlp_gemm<2>, cudaFuncAttributeMaxDynamicSharedMemorySize, GSMEM);
    cudaFuncSetAttribute(conv_kernel, cudaFuncAttributeMaxDynamicSharedMemorySize, CV_SMEM);

    // weight splits
    wsplit_cv<<<12, 256>>>(conv_w2);
    wsplit0<<<(256 * 8000 + 255) / 256, 256>>>(fc_w1, 256 * 8000);
    wsplit4<<<1024, 256>>>(q1_w1, q2_w1, q1_w2, q2_w2);

    conv_kernel<<<NROW, 256, CV_SMEM>>>(scan, conv_w1, conv_b1, conv_b2);
    fc1_gemm<<<dim3(2, 96, 3), 256, FSMEM>>>();
    fc2_concat<<<NROW / 8, 256>>>(fc_w2, fc_b2, fc_b1, obs, acts);
    stats_kernel<<<60, 256>>>();
    enc_kvq<<<NROW / 32, 256>>>(enc_w, enc_b, Wk, Wv, bv, Wq);
    attn_kernel<<<BSZ, 128>>>();

    mlp_gemm<1><<<dim3(8, 96), 256, GSMEM>>>(q1_b1, q2_b1);
    mlp_gemm<2><<<dim3(4, 96, 2), 256, GSMEM>>>(q1_b2, q2_b2);
    final_dot2<<<NROW / 8, 256>>>(q1_w3, q1_b3, q2_w3, q2_b3, out);
}

// round 7
// speedup vs baseline: 4.4455x; 1.0989x over previous
#include <cuda_runtime.h>
#include <cuda_bf16.h>
#include <math.h>
#include <cstdint>

#define NROW 12288
#define BSZ  4096

// ---------------- scratch (device globals; no allocations) ----------------
__device__ __nv_bfloat16 g_ah[(size_t)NROW * 8000];  // conv output hi
__device__ __nv_bfloat16 g_al[(size_t)NROW * 8000];  // conv output lo
__device__ __nv_bfloat16 g_fwh[256 * 8000];          // fc_w1 hi
__device__ __nv_bfloat16 g_fwl[256 * 8000];          // fc_w1 lo
__device__ __nv_bfloat16 g_qwh[4 * 256 * 256];       // q1_w1,q2_w1,q1_w2,q2_w2 hi
__device__ __nv_bfloat16 g_qwl[4 * 256 * 256];       // lo
__device__ __nv_bfloat16 g_cw2h[32 * 104];           // conv w2 pre-split (smem layout)
__device__ __nv_bfloat16 g_cw2l[32 * 104];
__device__ float g_part[3 * (size_t)NROW * 256];     // fc1 K-split partials
__device__ float g_inps[NROW * 60];
__device__ float g_stats[128];
__device__ __nv_bfloat16 g_embh[NROW * 256];
__device__ __nv_bfloat16 g_embl[NROW * 256];
__device__ __nv_bfloat16 g_mh[(size_t)NROW * 512];
__device__ __nv_bfloat16 g_ml[(size_t)NROW * 512];
__device__ float g_m2[(size_t)NROW * 512];
__device__ float g_keys[NROW * 128];
__device__ float g_vals[NROW * 128];
__device__ float g_q[NROW * 128];

// ====================== helpers ======================
__device__ __forceinline__ uint32_t smem_u32(const void* p) {
    uint32_t a;
    asm("{ .reg .u64 t; cvta.to.shared.u64 t, %1; cvt.u32.u64 %0, t; }"
        : "=r"(a) : "l"(p));
    return a;
}
__device__ __forceinline__ void bsplit(float v, __nv_bfloat16& h, __nv_bfloat16& l) {
    h = __float2bfloat16(v);
    l = __float2bfloat16(v - __bfloat162float(h));
}
#define CPA16(s, g) \
    asm volatile("cp.async.cg.shared.global [%0], [%1], 16;" :: "r"(s), "l"(g))
#define CPC() asm volatile("cp.async.commit_group;" ::: "memory")
#define LDSM4(r0, r1, r2, r3, a) \
    asm volatile("ldmatrix.sync.aligned.m8n8.x4.shared.b16 {%0,%1,%2,%3}, [%4];" \
                 : "=r"(r0), "=r"(r1), "=r"(r2), "=r"(r3) : "r"(a))
#define MMA16816(d, a, b) \
    asm volatile("mma.sync.aligned.m16n8k16.row.col.f32.bf16.bf16.f32 " \
                 "{%0,%1,%2,%3},{%4,%5,%6,%7},{%8,%9},{%0,%1,%2,%3};" \
                 : "+f"((d)[0]), "+f"((d)[1]), "+f"((d)[2]), "+f"((d)[3]) \
                 : "r"((a)[0]), "r"((a)[1]), "r"((a)[2]), "r"((a)[3]), \
                   "r"((b)[0]), "r"((b)[1]))

// ================= fc1: bf16x3 GEMM, BM128/BN128/BK32, 3-stage, K-split =========
#define FSMEM (3 * 32768)
__global__ void __launch_bounds__(256, 2) fc1_gemm()
{
    extern __shared__ char smem[];
    const uint32_t sb = smem_u32(smem);

    const int t = threadIdx.x, lane = t & 31, wid = t >> 5;
    const int bn = blockIdx.x, bm = blockIdx.y, z = blockIdx.z;
    const int kt0 = (z == 0) ? 0 : (z == 1) ? 84 : 167;
    const int T   = (z == 0) ? 84 : 83;
    const int row0 = bm * 128, col0 = bn * 128;

    const int fr = t >> 1;
    const int c0 = (t & 1) * 2;
    const __nv_bfloat16* gAh = g_ah + (size_t)(row0 + fr) * 8000 + kt0 * 32;
    const __nv_bfloat16* gAl = g_al + (size_t)(row0 + fr) * 8000 + kt0 * 32;
    const __nv_bfloat16* gBh = g_fwh + (size_t)(col0 + fr) * 8000 + kt0 * 32;
    const __nv_bfloat16* gBl = g_fwl + (size_t)(col0 + fr) * 8000 + kt0 * 32;
    const int fsw = (fr >> 1) & 3;

    const int mw = wid & 1, nw = wid >> 1;

    float acc[4][4][4];
    #pragma unroll
    for (int a = 0; a < 4; a++)
        #pragma unroll
        for (int b = 0; b < 4; b++)
            #pragma unroll
            for (int c = 0; c < 4; c++) acc[a][b][c] = 0.f;

    auto fill = [&](int tt, int s) {
        uint32_t base = sb + s * 32768;
        const __nv_bfloat16* pAh = gAh + (size_t)tt * 32;
        const __nv_bfloat16* pAl = gAl + (size_t)tt * 32;
        const __nv_bfloat16* pBh = gBh + (size_t)tt * 32;
        const __nv_bfloat16* pBl = gBl + (size_t)tt * 32;
        #pragma unroll
        for (int j = 0; j < 2; j++) {
            int c = c0 + j;
            uint32_t off = fr * 64 + ((c ^ fsw) << 4);
            CPA16(base + off,         pAh + c * 8);
            CPA16(base + 8192 + off,  pAl + c * 8);
            CPA16(base + 16384 + off, pBh + c * 8);
            CPA16(base + 24576 + off, pBl + c * 8);
        }
    };

    fill(0, 0); CPC();
    fill(1, 1); CPC();

    for (int tt = 0; tt < T; tt++) {
        asm volatile("cp.async.wait_group 1;" ::: "memory");
        __syncthreads();

        const uint32_t stu = sb + (tt % 3) * 32768;
        #pragma unroll
        for (int ks = 0; ks < 2; ks++) {
            uint32_t bhf[2][4], blf[2][4];
            #pragma unroll
            for (int nt = 0; nt < 2; nt++) {
                int nr = nw * 32 + nt * 16 + (lane & 7) + ((lane >> 4) << 3);
                int cs = (ks * 2 + ((lane >> 3) & 1)) ^ ((nr >> 1) & 3);
                uint32_t ba = stu + 16384 + nr * 64 + cs * 16;
                LDSM4(bhf[nt][0], bhf[nt][1], bhf[nt][2], bhf[nt][3], ba);
                LDSM4(blf[nt][0], blf[nt][1], blf[nt][2], blf[nt][3], ba + 8192);
            }
            #pragma unroll
            for (int mi = 0; mi < 4; mi++) {
                int r = mw * 64 + mi * 16 + (lane & 15);
                int cs = (ks * 2 + (lane >> 4)) ^ ((r >> 1) & 3);
                uint32_t aa = stu + r * 64 + cs * 16;
                uint32_t ah[4], al[4];
                LDSM4(ah[0], ah[1], ah[2], ah[3], aa);
                LDSM4(al[0], al[1], al[2], al[3], aa + 8192);
                #pragma unroll
                for (int nj = 0; nj < 4; nj++) {
                    int nt = nj >> 1, hf = (nj & 1) * 2;
                    MMA16816(acc[mi][nj], ah, &bhf[nt][hf]);
                    MMA16816(acc[mi][nj], ah, &blf[nt][hf]);
                    MMA16816(acc[mi][nj], al, &bhf[nt][hf]);
                }
            }
        }

        if (tt + 2 < T) fill(tt + 2, (tt + 2) % 3);
        CPC();
    }

    float* P = g_part + (size_t)z * NROW * 256;
    #pragma unroll
    for (int mi = 0; mi < 4; mi++) {
        #pragma unroll
        for (int nj = 0; nj < 4; nj++) {
            int col = col0 + nw * 32 + nj * 8 + (lane & 3) * 2;
            #pragma unroll
            for (int h = 0; h < 2; h++) {
                int row = row0 + mw * 64 + mi * 16 + (lane >> 2) + h * 8;
                *(float2*)(P + (size_t)row * 256 + col) =
                    make_float2(acc[mi][nj][h * 2], acc[mi][nj][h * 2 + 1]);
            }
        }
    }
}

// ============ MLP GEMM (K=256): BM128/BN64/BK64, 2-stage, bf16x3 ============
#define GSMEM 98304
template <int LAYER>
__global__ void __launch_bounds__(256, 2) mlp_gemm(
    const float* __restrict__ biasA, const float* __restrict__ biasB)
{
    const int K = 256;
    const int z = (LAYER == 2) ? blockIdx.z : 0;
    const __nv_bfloat16* Ah = (LAYER == 1) ? g_embh : g_mh + z * 256;
    const __nv_bfloat16* Al = (LAYER == 1) ? g_embl : g_ml + z * 256;
    const int AS = (LAYER == 1) ? 256 : 512;
    const __nv_bfloat16* Bh = (LAYER == 1) ? g_qwh : g_qwh + (2 + z) * 65536;
    const __nv_bfloat16* Bl = (LAYER == 1) ? g_qwl : g_qwl + (2 + z) * 65536;

    extern __shared__ char smem[];
    const uint32_t sb = smem_u32(smem);

    const int t = threadIdx.x, lane = t & 31, wid = t >> 5;
    const int row0 = blockIdx.y * 128, col0 = blockIdx.x * 64;

    const int ar = t >> 1, ac0 = (t & 1) * 4;
    const int br = t >> 2, bc0 = (t & 3) * 2;
    const __nv_bfloat16* gAh = Ah + (size_t)(row0 + ar) * AS;
    const __nv_bfloat16* gAl = Al + (size_t)(row0 + ar) * AS;
    const __nv_bfloat16* gBh = Bh + (size_t)(col0 + br) * K;
    const __nv_bfloat16* gBl = Bl + (size_t)(col0 + br) * K;

    const int m0 = (wid & 1) * 64;
    const int n0 = (wid >> 1) * 16;
    const int lr = lane & 15;
    const int kh = lane >> 4;
    const int brow = n0 + (lane & 7) + ((lane >> 4) << 3);
    const int bko = (lane >> 3) & 1;

    const int T = K / 64;
    float acc[4][2][4];
    #pragma unroll
    for (int a = 0; a < 4; a++)
        #pragma unroll
        for (int b = 0; b < 2; b++)
            #pragma unroll
            for (int c = 0; c < 4; c++) acc[a][b][c] = 0.f;

    auto load_stage = [&](int tt, int s) {
        uint32_t base = sb + s * 49152;
        const __nv_bfloat16* pAh = gAh + tt * 64;
        const __nv_bfloat16* pAl = gAl + tt * 64;
        const __nv_bfloat16* pBh = gBh + tt * 64;
        const __nv_bfloat16* pBl = gBl + tt * 64;
        #pragma unroll
        for (int q = 0; q < 4; q++) {
            int c = ac0 + q;
            uint32_t off = ar * 128 + ((c ^ (ar & 7)) << 4);
            CPA16(base + off,         pAh + c * 8);
            CPA16(base + 16384 + off, pAl + c * 8);
        }
        #pragma unroll
        for (int q = 0; q < 2; q++) {
            int c = bc0 + q;
            uint32_t off = br * 128 + ((c ^ (br & 7)) << 4);
            CPA16(base + 32768 + off, pBh + c * 8);
            CPA16(base + 40960 + off, pBl + c * 8);
        }
    };

    load_stage(0, 0);
    CPC();

    for (int tt = 0; tt < T; tt++) {
        if (tt + 1 < T) {
            load_stage(tt + 1, (tt + 1) & 1);
            CPC();
            asm volatile("cp.async.wait_group 1;" ::: "memory");
        } else {
            asm volatile("cp.async.wait_group 0;" ::: "memory");
        }
        __syncthreads();

        uint32_t base = sb + (tt & 1) * 49152;
        #pragma unroll
        for (int ks = 0; ks < 4; ks++) {
            uint32_t ahf[4][4], alf[4][4], bhf[4], blf[4];
            int ch = ks * 2 + kh;
            #pragma unroll
            for (int mi = 0; mi < 4; mi++) {
                int r = m0 + mi * 16 + lr;
                uint32_t a = base + r * 128 + ((ch ^ (r & 7)) << 4);
                LDSM4(ahf[mi][0], ahf[mi][1], ahf[mi][2], ahf[mi][3], a);
                LDSM4(alf[mi][0], alf[mi][1], alf[mi][2], alf[mi][3], a + 16384);
            }
            int bch = ks * 2 + bko;
            uint32_t ba = base + 32768 + brow * 128 + ((bch ^ (brow & 7)) << 4);
            LDSM4(bhf[0], bhf[1], bhf[2], bhf[3], ba);
            LDSM4(blf[0], blf[1], blf[2], blf[3], ba + 8192);

            #pragma unroll
            for (int mi = 0; mi < 4; mi++) {
                #pragma unroll
                for (int nf = 0; nf < 2; nf++) {
                    MMA16816(acc[mi][nf], ahf[mi], bhf + 2 * nf);
                    MMA16816(acc[mi][nf], ahf[mi], blf + 2 * nf);
                    MMA16816(acc[mi][nf], alf[mi], bhf + 2 * nf);
                }
            }
        }
        __syncthreads();
    }

    #pragma unroll
    for (int mi = 0; mi < 4; mi++) {
        #pragma unroll
        for (int nf = 0; nf < 2; nf++) {
            int ocl = col0 + n0 + nf * 8 + (lane & 3) * 2;
            float b0, b1;
            if (LAYER == 1) {
                b0 = (ocl < 256) ? biasA[ocl] : biasB[ocl - 256];
                b1 = (ocl + 1 < 256) ? biasA[ocl + 1] : biasB[ocl + 1 - 256];
            } else {
                const float* bb = z ? biasB : biasA;
                b0 = bb[ocl]; b1 = bb[ocl + 1];
            }
            int ocg = (LAYER == 1) ? ocl : z * 256 + ocl;
            #pragma unroll
            for (int h = 0; h < 2; h++) {
                int row = row0 + m0 + mi * 16 + (lane >> 2) + h * 8;
                float v0 = fmaxf(acc[mi][nf][h * 2 + 0] + b0, 0.f);
                float v1 = fmaxf(acc[mi][nf][h * 2 + 1] + b1, 0.f);
                size_t idx = (size_t)row * 512 + ocg;
                if (LAYER == 2) {
                    *(float2*)(g_m2 + idx) = make_float2(v0, v1);
                } else {
                    __nv_bfloat16 h0, l0, h1, l1;
                    bsplit(v0, h0, l0);
                    bsplit(v1, h1, l1);
                    *(__nv_bfloat162*)(g_mh + idx) = __halves2bfloat162(h0, h1);
                    *(__nv_bfloat162*)(g_ml + idx) = __halves2bfloat162(l0, l1);
                }
            }
        }
    }
}

// ---------------- weight split kernels ----------------
__global__ void wsplit0(const float* __restrict__ w, int n)
{
    int i = blockIdx.x * 256 + threadIdx.x;
    if (i >= n) return;
    __nv_bfloat16 hh, ll;
    bsplit(w[i], hh, ll);
    g_fwh[i] = hh;
    g_fwl[i] = ll;
}
__global__ void wsplit4(const float* __restrict__ w0, const float* __restrict__ w1,
                        const float* __restrict__ w2, const float* __restrict__ w3)
{
    int i = blockIdx.x * 256 + threadIdx.x;
    int which = i >> 16, j = i & 65535;
    const float* src = (which == 0) ? w0 : (which == 1) ? w1 : (which == 2) ? w2 : w3;
    __nv_bfloat16 hh, ll;
    bsplit(src[j], hh, ll);
    g_qwh[i] = hh;
    g_qwl[i] = ll;
}
// conv w2 pre-split + zero g_stats accumulators (needed fresh per graph replay)
__global__ void wsplit_cv(const float* __restrict__ w2)
{
    int idx = threadIdx.x + blockIdx.x * 256;
    if (idx < 128) g_stats[idx] = 0.f;
    if (idx >= 3072) return;
    int oc = idx / 96, rem = idx % 96;
    int ic = rem / 3, tap = rem % 3;
    __nv_bfloat16 hh, ll;
    bsplit(w2[idx], hh, ll);
    int o = oc * 104 + tap * 32 + ic;
    g_cw2h[o] = hh;
    g_cw2l[o] = ll;
}

// ============ fused conv1(SIMT) + conv2(bf16x3 MMA), split out ============
#define CV_SMEM 56960
#define CV_SCAN 0
#define CV_W1   1024
#define CV_B1   1664
#define CV_B2   1792
#define CV_H1H  2048
#define CV_H1L  22848
#define CV_W2H  43648
#define CV_W2L  50304

__global__ void __launch_bounds__(256, 3) conv_kernel(
    const float* __restrict__ scan,
    const float* __restrict__ w1, const float* __restrict__ b1,
    const float* __restrict__ b2)
{
    extern __shared__ char smem[];
    const uint32_t sb = smem_u32(smem);
    float* s_scan = (float*)(smem + CV_SCAN);
    float* s_w1   = (float*)(smem + CV_W1);
    float* s_b1   = (float*)(smem + CV_B1);
    float* s_b2   = (float*)(smem + CV_B2);
    __nv_bfloat16* s_h1h = (__nv_bfloat16*)(smem + CV_H1H);
    __nv_bfloat16* s_h1l = (__nv_bfloat16*)(smem + CV_H1L);

    const int t = threadIdx.x, lane = t & 31, wid = t >> 5;
    const int row = blockIdx.x;

    // copy pre-split w2 (6656B per array = 416 x 16B)
    for (int i = t; i < 416; i += 256) {
        CPA16(sb + CV_W2H + i * 16, (const char*)g_cw2h + i * 16);
        CPA16(sb + CV_W2L + i * 16, (const char*)g_cw2l + i * 16);
    }
    CPC();

    s_scan[t] = scan[(size_t)row * 256 + t];
    if (t < 160) s_w1[t] = w1[t];
    if (t < 32) { s_b1[t] = b1[t]; s_b2[t] = b2[t]; }
    asm volatile("cp.async.wait_group 0;" ::: "memory");
    __syncthreads();

    // conv1 (fp32, rolling register window; 1 broadcast LDS per step)
    // warp w owns positions [w*32, w*32+32); lane = ic
    {
        const int ic = lane;
        const int pbase = wid * 32;
        float wv[5];
        #pragma unroll
        for (int k = 0; k < 5; k++) wv[k] = s_w1[ic * 5 + k];
        const float bb = s_b1[ic];
        float win[5];
        #pragma unroll
        for (int k = 0; k < 4; k++) win[k] = s_scan[pbase + k];
        #pragma unroll
        for (int i = 0; i < 32; i++) {
            int p = pbase + i;
            win[4] = s_scan[(p + 4) & 255];
            float a = bb + wv[0] * win[0] + wv[1] * win[1] + wv[2] * win[2]
                         + wv[3] * win[3] + wv[4] * win[4];
            a = fmaxf(a, 0.f);
            if (p >= 252) a = 0.f;
            __nv_bfloat16 hh, ll;
            bsplit(a, hh, ll);
            s_h1h[p * 40 + ic] = hh;
            s_h1l[p * 40 + ic] = ll;
            win[0] = win[1]; win[1] = win[2]; win[2] = win[3]; win[3] = win[4];
        }
    }
    // zero-pad positions 256..259 (ldsm B-frags read rows up to 257)
    if (t < 128) {
        int p = 256 + (t >> 5), ic = t & 31;
        s_h1h[p * 40 + ic] = __float2bfloat16(0.f);
        s_h1l[p * 40 + ic] = __float2bfloat16(0.f);
    }
    __syncthreads();

    const int n0 = wid * 32;
    const int lr = lane & 15;
    const int kh = lane >> 4;
    const int browl = (lane & 7) + ((lane >> 4) << 3);
    const int bko = (lane >> 3) & 1;

    float acc[2][4][4];
    #pragma unroll
    for (int a = 0; a < 2; a++)
        #pragma unroll
        for (int b = 0; b < 4; b++)
            #pragma unroll
            for (int c = 0; c < 4; c++) acc[a][b][c] = 0.f;

    #pragma unroll
    for (int ks = 0; ks < 6; ks++) {
        int tap = ks >> 1;
        int ic16 = (ks & 1) * 32;

        uint32_t awh[2][4], awl[2][4];
        #pragma unroll
        for (int mi = 0; mi < 2; mi++) {
            uint32_t a = sb + CV_W2H + (mi * 16 + lr) * 208 + ks * 32 + kh * 16;
            LDSM4(awh[mi][0], awh[mi][1], awh[mi][2], awh[mi][3], a);
            LDSM4(awl[mi][0], awl[mi][1], awl[mi][2], awl[mi][3], a + 6656);
        }
        uint32_t bh[2][4], bl[2][4];
        #pragma unroll
        for (int nt = 0; nt < 2; nt++) {
            int nrow = n0 + nt * 16 + browl + tap;
            uint32_t b = sb + CV_H1H + nrow * 80 + ic16 + bko * 16;
            LDSM4(bh[nt][0], bh[nt][1], bh[nt][2], bh[nt][3], b);
            LDSM4(bl[nt][0], bl[nt][1], bl[nt][2], bl[nt][3], b + 20800);
        }
        #pragma unroll
        for (int mi = 0; mi < 2; mi++) {
            #pragma unroll
            for (int nj = 0; nj < 4; nj++) {
                int nt = nj >> 1, hf = (nj & 1) * 2;
                MMA16816(acc[mi][nj], awh[mi], &bh[nt][hf]);
                MMA16816(acc[mi][nj], awh[mi], &bl[nt][hf]);
                MMA16816(acc[mi][nj], awl[mi], &bh[nt][hf]);
            }
        }
    }

    __nv_bfloat16* oh = g_ah + (size_t)row * 8000;
    __nv_bfloat16* ol = g_al + (size_t)row * 8000;
    #pragma unroll
    for (int mi = 0; mi < 2; mi++) {
        #pragma unroll
        for (int nj = 0; nj < 4; nj++) {
            int p0 = n0 + nj * 8 + (lane & 3) * 2;
            if (p0 < 250) {
                #pragma unroll
                for (int h = 0; h < 2; h++) {
                    int oc = mi * 16 + (lane >> 2) + h * 8;
                    float bb = s_b2[oc];
                    float v0 = fmaxf(acc[mi][nj][h * 2 + 0] + bb, 0.f);
                    float v1 = fmaxf(acc[mi][nj][h * 2 + 1] + bb, 0.f);
                    __nv_bfloat16 h0, l0, h1, l1;
                    bsplit(v0, h0, l0);
                    bsplit(v1, h1, l1);
                    int o = oc * 250 + p0;
                    *(__nv_bfloat162*)(oh + o) = __halves2bfloat162(h0, h1);
                    *(__nv_bfloat162*)(ol + o) = __halves2bfloat162(l0, l1);
                }
            }
        }
    }
}

// -------- fc1 combine + fc2 (256->10) + concat -> g_inps --------
__global__ void __launch_bounds__(256) fc2_concat(
    const float* __restrict__ w2, const float* __restrict__ b2,
    const float* __restrict__ b1,
    const float* __restrict__ obs, const float* __restrict__ acts)
{
    __shared__ float fs[8][10];
    int warp = threadIdx.x >> 5, lane = threadIdx.x & 31;
    int r = blockIdx.x * 8 + warp;

    const float* p0 = g_part + (size_t)r * 256;
    const float* p1 = p0 + (size_t)NROW * 256;
    const float* p2 = p1 + (size_t)NROW * 256;
    float x[8];
    #pragma unroll
    for (int i = 0; i < 8; i++) {
        int c = lane + 32 * i;
        x[i] = fmaxf(p0[c] + p1[c] + p2[c] + b1[c], 0.f);
    }

    #pragma unroll
    for (int j = 0; j < 10; j++) {
        float s = 0.f;
        #pragma unroll
        for (int i = 0; i < 8; i++) s += x[i] * w2[j * 256 + lane + 32 * i];
        #pragma unroll
        for (int off = 16; off; off >>= 1) s += __shfl_xor_sync(0xffffffffu, s, off);
        if (lane == 0) fs[warp][j] = s + b2[j];
    }
    __syncwarp();

    float* ir = g_inps + (size_t)r * 60;
    for (int c = lane; c < 60; c += 32) {
        float v;
        if (c < 48)      v = obs[(size_t)r * 48 + c];
        else if (c < 50) v = acts[(size_t)r * 2 + (c - 48)];
        else             v = fs[warp][c - 50];
        ir[c] = v;
    }
}

// ---------------- batch stats: coalesced partial pass + finalize ----------------
__global__ void __launch_bounds__(256) stats_part()
{
    __shared__ float sh_s[64], sh_q[64];
    int t = threadIdx.x;
    if (t < 64) { sh_s[t] = 0.f; sh_q[t] = 0.f; }
    __syncthreads();

    const float* base = g_inps + (size_t)blockIdx.x * 128 * 60;
    for (int i = t; i < 128 * 60; i += 256) {
        float v = base[i];
        int c = i % 60;
        atomicAdd(&sh_s[c], v);
        atomicAdd(&sh_q[c], v * v);
    }
    __syncthreads();
    if (t < 60) {
        atomicAdd(&g_stats[t], sh_s[t]);
        atomicAdd(&g_stats[64 + t], sh_q[t]);
    }
}
__global__ void stats_fin()
{
    int c = threadIdx.x;
    if (c < 60) {
        float mu = g_stats[c] * (1.f / NROW);
        float var = g_stats[64 + c] * (1.f / NROW) - mu * mu;
        g_stats[c] = mu;
        g_stats[64 + c] = rsqrtf(var + 1e-5f);
    }
}

// -------- normalize + encoder(leaky) + keys/vals/q ----------
__global__ void __launch_bounds__(256) enc_kvq(
    const float* __restrict__ enc_w, const float* __restrict__ enc_b,
    const float* __restrict__ Wk, const float* __restrict__ Wv,
    const float* __restrict__ bv, const float* __restrict__ Wq)
{
    __shared__ float xn[32][60];
    __shared__ float sas[32][128];
    __shared__ float wch[32][129];
    __shared__ float mu_s[60], inv_s[60];

    int t = threadIdx.x;
    int row0 = blockIdx.x * 32;
    int g = row0 >> 12;

    if (t < 60) { mu_s[t] = g_stats[t]; inv_s[t] = g_stats[64 + t]; }
    __syncthreads();

    for (int idx = t; idx < 32 * 60; idx += 256) {
        int r = idx / 60, c = idx % 60;
        xn[r][c] = (g_inps[(size_t)(row0 + r) * 60 + c] - mu_s[c]) * inv_s[c];
    }
    __syncthreads();

    int jj = t & 31, rg = t >> 5;

    for (int jc = 0; jc < 4; jc++) {
        for (int idx = t; idx < 32 * 60; idx += 256) {
            int rr = idx / 60, c = idx % 60;
            wch[rr][c] = enc_w[(jc * 32 + rr) * 60 + c];
        }
        __syncthreads();

        float a0 = 0.f, a1 = 0.f, a2 = 0.f, a3 = 0.f;
        #pragma unroll
        for (int c = 0; c < 60; c++) {
            float w = wch[jj][c];
            a0 += xn[rg * 4 + 0][c] * w;
            a1 += xn[rg * 4 + 1][c] * w;
            a2 += xn[rg * 4 + 2][c] * w;
            a3 += xn[rg * 4 + 3][c] * w;
        }
        float bb = enc_b[jc * 32 + jj];
        float v[4] = {a0 + bb, a1 + bb, a2 + bb, a3 + bb};
        int col = jc * 32 + jj;
        #pragma unroll
        for (int q = 0; q < 4; q++) {
            float vv = (v[q] >= 0.f) ? v[q] : 0.01f * v[q];
            sas[rg * 4 + q][col] = vv;
            __nv_bfloat16 hh, ll;
            bsplit(vv, hh, ll);
            size_t idx = (size_t)(row0 + rg * 4 + q) * 256 + col;
            g_embh[idx] = hh;
            g_embl[idx] = ll;
        }
        __syncthreads();
    }

    for (int m = 0; m < 3; m++) {
        const float* W = (m == 0) ? Wk : (m == 1) ? Wv : (Wq + (size_t)g * 128 * 128);
        float* Out     = (m == 0) ? g_keys : (m == 1) ? g_vals : g_q;
        for (int jc = 0; jc < 4; jc++) {
            for (int idx = t; idx < 32 * 128; idx += 256) {
                int rr = idx >> 7, c = idx & 127;
                wch[rr][c] = W[(jc * 32 + rr) * 128 + c];
            }
            __syncthreads();

            float a0 = 0.f, a1 = 0.f, a2 = 0.f, a3 = 0.f;
            #pragma unroll
            for (int c = 0; c < 128; c++) {
                float w = wch[jj][c];
                a0 += sas[rg * 4 + 0][c] * w;
                a1 += sas[rg * 4 + 1][c] * w;
                a2 += sas[rg * 4 + 2][c] * w;
                a3 += sas[rg * 4 + 3][c] * w;
            }
            int col = jc * 32 + jj;
            if (m == 1) {
                float bb = bv[col];
                a0 += bb; a1 += bb; a2 += bb; a3 += bb;
                a0 = (a0 >= 0.f) ? a0 : 0.01f * a0;
                a1 = (a1 >= 0.f) ? a1 : 0.01f * a1;
                a2 = (a2 >= 0.f) ? a2 : 0.01f * a2;
                a3 = (a3 >= 0.f) ? a3 : 0.01f * a3;
            }
            Out[(size_t)(row0 + rg * 4 + 0) * 128 + col] = a0;
            Out[(size_t)(row0 + rg * 4 + 1) * 128 + col] = a1;
            Out[(size_t)(row0 + rg * 4 + 2) * 128 + col] = a2;
            Out[(size_t)(row0 + rg * 4 + 3) * 128 + col] = a3;
            __syncthreads();
        }
    }
}

// ---------------- tiny 3-agent cross-attention ----------------
__global__ void __launch_bounds__(128) attn_kernel()
{
    __shared__ float qs[3][128], ks[3][128], vs[3][128];
    int b = blockIdx.x;
    int t = threadIdx.x;

    #pragma unroll
    for (int g = 0; g < 3; g++) {
        size_t roff = (size_t)(g * BSZ + b) * 128 + t;
        qs[g][t] = g_q[roff];
        ks[g][t] = g_keys[roff];
        vs[g][t] = g_vals[roff];
    }
    __syncthreads();

    const float scale = 0.25f;
    #pragma unroll
    for (int g = 0; g < 3; g++) {
        int o1 = (g == 0) ? 1 : 0;
        int o2 = (g == 2) ? 1 : 2;
        float q = qs[g][t];
        float p1 = q * ks[o1][t];
        float p2 = q * ks[o2][t];
        #pragma unroll
        for (int off = 8; off; off >>= 1) {
            p1 += __shfl_xor_sync(0xffffffffu, p1, off);
            p2 += __shfl_xor_sync(0xffffffffu, p2, off);
        }
        float l1 = p1 * scale, l2 = p2 * scale;
        float mx = fmaxf(l1, l2);
        float e1 = expf(l1 - mx), e2 = expf(l2 - mx);
        float inv = 1.f / (e1 + e2);
        float other = (e1 * vs[o1][t] + e2 * vs[o2][t]) * inv;
        __nv_bfloat16 hh, ll;
        bsplit(other, hh, ll);
        size_t idx = (size_t)(g * BSZ + b) * 256 + 128 + t;
        g_embh[idx] = hh;
        g_embl[idx] = ll;
    }
}

// ---------------- fused final dots (q1 & q2) ----------------
__global__ void __launch_bounds__(256) final_dot2(
    const float* __restrict__ w3a, const float* __restrict__ b3a,
    const float* __restrict__ w3b, const float* __restrict__ b3b,
    float* __restrict__ out)
{
    int warp = threadIdx.x >> 5, lane = threadIdx.x & 31;
    int r = blockIdx.x * 8 + warp;
    const float* xr = g_m2 + (size_t)r * 512;
    float s1 = 0.f, s2 = 0.f;
    #pragma unroll
    for (int i = 0; i < 8; i++) {
        int c = lane + 32 * i;
        s1 += xr[c] * w3a[c];
        s2 += xr[256 + c] * w3b[c];
    }
    #pragma unroll
    for (int off = 16; off; off >>= 1) {
        s1 += __shfl_xor_sync(0xffffffffu, s1, off);
        s2 += __shfl_xor_sync(0xffffffffu, s2, off);
    }
    if (lane == 0) {
        out[r] = s1 + b3a[0];
        out[NROW + r] = s2 + b3b[0];
    }
}

// ---------------- launch ----------------
extern "C" void kernel_launch(void* const* d_in, const int* in_sizes, int n_in,
                              void* d_out, int out_size)
{
    const float* obs     = (const float*)d_in[0];
    const float* acts    = (const float*)d_in[1];
    const float* scan    = (const float*)d_in[2];
    const float* conv_w1 = (const float*)d_in[3];
    const float* conv_b1 = (const float*)d_in[4];
    const float* conv_w2 = (const float*)d_in[5];
    const float* conv_b2 = (const float*)d_in[6];
    const float* fc_w1   = (const float*)d_in[7];
    const float* fc_b1   = (const float*)d_in[8];
    const float* fc_w2   = (const float*)d_in[9];
    const float* fc_b2   = (const float*)d_in[10];
    const float* enc_w   = (const float*)d_in[11];
    const float* enc_b   = (const float*)d_in[12];
    const float* Wk      = (const float*)d_in[13];
    const float* Wv      = (const float*)d_in[14];
    const float* bv      = (const float*)d_in[15];
    const float* Wq      = (const float*)d_in[16];
    const float* q1_w1   = (const float*)d_in[17];
    const float* q1_b1   = (const float*)d_in[18];
    const float* q1_w2   = (const float*)d_in[19];
    const float* q1_b2   = (const float*)d_in[20];
    const float* q1_w3   = (const float*)d_in[21];
    const float* q1_b3   = (const float*)d_in[22];
    const float* q2_w1   = (const float*)d_in[23];
    const float* q2_b1   = (const float*)d_in[24];
    const float* q2_w2   = (const float*)d_in[25];
    const float* q2_b2   = (const float*)d_in[26];
    const float* q2_w3   = (const float*)d_in[27];
    const float* q2_b3   = (const float*)d_in[28];
    float* out = (float*)d_out;

    cudaFuncSetAttribute(fc1_gemm, cudaFuncAttributeMaxDynamicSharedMemorySize, FSMEM);
    cudaFuncSetAttribute(mlp_gemm<1>, cudaFuncAttributeMaxDynamicSharedMemorySize, GSMEM);
    cudaFuncSetAttribute(mlp_gemm<2>, cudaFuncAttributeMaxDynamicSharedMemorySize, GSMEM);
    cudaFuncSetAttribute(conv_kernel, cudaFuncAttributeMaxDynamicSharedMemorySize, CV_SMEM);

    // weight splits (wsplit_cv also zeroes g_stats accumulators)
    wsplit_cv<<<12, 256>>>(conv_w2);
    wsplit0<<<(256 * 8000 + 255) / 256, 256>>>(fc_w1, 256 * 8000);
    wsplit4<<<1024, 256>>>(q1_w1, q2_w1, q1_w2, q2_w2);

    conv_kernel<<<NROW, 256, CV_SMEM>>>(scan, conv_w1, conv_b1, conv_b2);
    fc1_gemm<<<dim3(2, 96, 3), 256, FSMEM>>>();
    fc2_concat<<<NROW / 8, 256>>>(fc_w2, fc_b2, fc_b1, obs, acts);
    stats_part<<<96, 256>>>();
    stats_fin<<<1, 64>>>();
    enc_kvq<<<NROW / 32, 256>>>(enc_w, enc_b, Wk, Wv, bv, Wq);
    attn_kernel<<<BSZ, 128>>>();

    mlp_gemm<1><<<dim3(8, 96), 256, GSMEM>>>(q1_b1, q2_b1);
    mlp_gemm<2><<<dim3(4, 96, 2), 256, GSMEM>>>(q1_b2, q2_b2);
    final_dot2<<<NROW / 8, 256>>>(q1_w3, q1_b3, q2_w3, q2_b3, out);
}

// round 8
// speedup vs baseline: 4.6949x; 1.0561x over previous
#include <cuda_runtime.h>
#include <cuda_bf16.h>
#include <math.h>
#include <cstdint>

#define NROW 12288
#define BSZ  4096
#define KPAD 8192

// ---------------- scratch (device globals; no allocations) ----------------
__device__ __nv_bfloat16 g_ah[(size_t)NROW * KPAD];  // conv output hi (permuted K)
__device__ __nv_bfloat16 g_al[(size_t)NROW * KPAD];  // conv output lo
__device__ __nv_bfloat16 g_fwh[256 * KPAD];          // fc_w1 hi (same permutation)
__device__ __nv_bfloat16 g_fwl[256 * KPAD];          // fc_w1 lo
__device__ __nv_bfloat16 g_qwh[4 * 256 * 256];       // q1_w1,q2_w1,q1_w2,q2_w2 hi
__device__ __nv_bfloat16 g_qwl[4 * 256 * 256];       // lo
__device__ __nv_bfloat16 g_cw2h[32 * 104];           // conv w2 pre-split (smem layout)
__device__ __nv_bfloat16 g_cw2l[32 * 104];
__device__ float g_part[3 * (size_t)NROW * 256];     // fc1 K-split partials
__device__ float g_inps[NROW * 60];
__device__ float g_stats[128];
__device__ __nv_bfloat16 g_embh[NROW * 256];
__device__ __nv_bfloat16 g_embl[NROW * 256];
__device__ __nv_bfloat16 g_mh[(size_t)NROW * 512];
__device__ __nv_bfloat16 g_ml[(size_t)NROW * 512];
__device__ float g_m2[(size_t)NROW * 512];
__device__ float g_keys[NROW * 128];
__device__ float g_vals[NROW * 128];
__device__ float g_q[NROW * 128];

// ====================== helpers ======================
__device__ __forceinline__ uint32_t smem_u32(const void* p) {
    uint32_t a;
    asm("{ .reg .u64 t; cvta.to.shared.u64 t, %1; cvt.u32.u64 %0, t; }"
        : "=r"(a) : "l"(p));
    return a;
}
__device__ __forceinline__ void bsplit(float v, __nv_bfloat16& h, __nv_bfloat16& l) {
    h = __float2bfloat16(v);
    l = __float2bfloat16(v - __bfloat162float(h));
}
#define CPA16(s, g) \
    asm volatile("cp.async.cg.shared.global [%0], [%1], 16;" :: "r"(s), "l"(g))
#define CPC() asm volatile("cp.async.commit_group;" ::: "memory")
#define LDSM4(r0, r1, r2, r3, a) \
    asm volatile("ldmatrix.sync.aligned.m8n8.x4.shared.b16 {%0,%1,%2,%3}, [%4];" \
                 : "=r"(r0), "=r"(r1), "=r"(r2), "=r"(r3) : "r"(a))
#define MMA16816(d, a, b) \
    asm volatile("mma.sync.aligned.m16n8k16.row.col.f32.bf16.bf16.f32 " \
                 "{%0,%1,%2,%3},{%4,%5,%6,%7},{%8,%9},{%0,%1,%2,%3};" \
                 : "+f"((d)[0]), "+f"((d)[1]), "+f"((d)[2]), "+f"((d)[3]) \
                 : "r"((a)[0]), "r"((a)[1]), "r"((a)[2]), "r"((a)[3]), \
                   "r"((b)[0]), "r"((b)[1]))

// ================= fc1: bf16x3 GEMM, BM128/BN128/BK32, 3-stage, K-split =========
// K = 8192 (permuted, padded). 256 k-tiles split 86/85/85 across blockIdx.z.
#define FSMEM (3 * 32768)
__global__ void __launch_bounds__(256, 2) fc1_gemm()
{
    extern __shared__ char smem[];
    const uint32_t sb = smem_u32(smem);

    const int t = threadIdx.x, lane = t & 31, wid = t >> 5;
    const int bn = blockIdx.x, bm = blockIdx.y, z = blockIdx.z;
    const int kt0 = (z == 0) ? 0 : (z == 1) ? 86 : 171;
    const int T   = (z == 0) ? 86 : 85;
    const int row0 = bm * 128, col0 = bn * 128;

    const int fr = t >> 1;
    const int c0 = (t & 1) * 2;
    const __nv_bfloat16* gAh = g_ah + (size_t)(row0 + fr) * KPAD + kt0 * 32;
    const __nv_bfloat16* gAl = g_al + (size_t)(row0 + fr) * KPAD + kt0 * 32;
    const __nv_bfloat16* gBh = g_fwh + (size_t)(col0 + fr) * KPAD + kt0 * 32;
    const __nv_bfloat16* gBl = g_fwl + (size_t)(col0 + fr) * KPAD + kt0 * 32;
    const int fsw = (fr >> 1) & 3;

    const int mw = wid & 1, nw = wid >> 1;

    float acc[4][4][4];
    #pragma unroll
    for (int a = 0; a < 4; a++)
        #pragma unroll
        for (int b = 0; b < 4; b++)
            #pragma unroll
            for (int c = 0; c < 4; c++) acc[a][b][c] = 0.f;

    auto fill = [&](int tt, int s) {
        uint32_t base = sb + s * 32768;
        const __nv_bfloat16* pAh = gAh + (size_t)tt * 32;
        const __nv_bfloat16* pAl = gAl + (size_t)tt * 32;
        const __nv_bfloat16* pBh = gBh + (size_t)tt * 32;
        const __nv_bfloat16* pBl = gBl + (size_t)tt * 32;
        #pragma unroll
        for (int j = 0; j < 2; j++) {
            int c = c0 + j;
            uint32_t off = fr * 64 + ((c ^ fsw) << 4);
            CPA16(base + off,         pAh + c * 8);
            CPA16(base + 8192 + off,  pAl + c * 8);
            CPA16(base + 16384 + off, pBh + c * 8);
            CPA16(base + 24576 + off, pBl + c * 8);
        }
    };

    fill(0, 0); CPC();
    fill(1, 1); CPC();

    for (int tt = 0; tt < T; tt++) {
        asm volatile("cp.async.wait_group 1;" ::: "memory");
        __syncthreads();

        const uint32_t stu = sb + (tt % 3) * 32768;
        #pragma unroll
        for (int ks = 0; ks < 2; ks++) {
            uint32_t bhf[2][4], blf[2][4];
            #pragma unroll
            for (int nt = 0; nt < 2; nt++) {
                int nr = nw * 32 + nt * 16 + (lane & 7) + ((lane >> 4) << 3);
                int cs = (ks * 2 + ((lane >> 3) & 1)) ^ ((nr >> 1) & 3);
                uint32_t ba = stu + 16384 + nr * 64 + cs * 16;
                LDSM4(bhf[nt][0], bhf[nt][1], bhf[nt][2], bhf[nt][3], ba);
                LDSM4(blf[nt][0], blf[nt][1], blf[nt][2], blf[nt][3], ba + 8192);
            }
            #pragma unroll
            for (int mi = 0; mi < 4; mi++) {
                int r = mw * 64 + mi * 16 + (lane & 15);
                int cs = (ks * 2 + (lane >> 4)) ^ ((r >> 1) & 3);
                uint32_t aa = stu + r * 64 + cs * 16;
                uint32_t ah[4], al[4];
                LDSM4(ah[0], ah[1], ah[2], ah[3], aa);
                LDSM4(al[0], al[1], al[2], al[3], aa + 8192);
                #pragma unroll
                for (int nj = 0; nj < 4; nj++) {
                    int nt = nj >> 1, hf = (nj & 1) * 2;
                    MMA16816(acc[mi][nj], ah, &bhf[nt][hf]);
                    MMA16816(acc[mi][nj], ah, &blf[nt][hf]);
                    MMA16816(acc[mi][nj], al, &bhf[nt][hf]);
                }
            }
        }

        if (tt + 2 < T) fill(tt + 2, (tt + 2) % 3);
        CPC();
    }

    float* P = g_part + (size_t)z * NROW * 256;
    #pragma unroll
    for (int mi = 0; mi < 4; mi++) {
        #pragma unroll
        for (int nj = 0; nj < 4; nj++) {
            int col = col0 + nw * 32 + nj * 8 + (lane & 3) * 2;
            #pragma unroll
            for (int h = 0; h < 2; h++) {
                int row = row0 + mw * 64 + mi * 16 + (lane >> 2) + h * 8;
                *(float2*)(P + (size_t)row * 256 + col) =
                    make_float2(acc[mi][nj][h * 2], acc[mi][nj][h * 2 + 1]);
            }
        }
    }
}

// ============ MLP GEMM (K=256): BM128/BN64/BK64, 2-stage, bf16x3 ============
#define GSMEM 98304
template <int LAYER>
__global__ void __launch_bounds__(256, 2) mlp_gemm(
    const float* __restrict__ biasA, const float* __restrict__ biasB)
{
    const int K = 256;
    const int z = (LAYER == 2) ? blockIdx.z : 0;
    const __nv_bfloat16* Ah = (LAYER == 1) ? g_embh : g_mh + z * 256;
    const __nv_bfloat16* Al = (LAYER == 1) ? g_embl : g_ml + z * 256;
    const int AS = (LAYER == 1) ? 256 : 512;
    const __nv_bfloat16* Bh = (LAYER == 1) ? g_qwh : g_qwh + (2 + z) * 65536;
    const __nv_bfloat16* Bl = (LAYER == 1) ? g_qwl : g_qwl + (2 + z) * 65536;

    extern __shared__ char smem[];
    const uint32_t sb = smem_u32(smem);

    const int t = threadIdx.x, lane = t & 31, wid = t >> 5;
    const int row0 = blockIdx.y * 128, col0 = blockIdx.x * 64;

    const int ar = t >> 1, ac0 = (t & 1) * 4;
    const int br = t >> 2, bc0 = (t & 3) * 2;
    const __nv_bfloat16* gAh = Ah + (size_t)(row0 + ar) * AS;
    const __nv_bfloat16* gAl = Al + (size_t)(row0 + ar) * AS;
    const __nv_bfloat16* gBh = Bh + (size_t)(col0 + br) * K;
    const __nv_bfloat16* gBl = Bl + (size_t)(col0 + br) * K;

    const int m0 = (wid & 1) * 64;
    const int n0 = (wid >> 1) * 16;
    const int lr = lane & 15;
    const int kh = lane >> 4;
    const int brow = n0 + (lane & 7) + ((lane >> 4) << 3);
    const int bko = (lane >> 3) & 1;

    const int T = K / 64;
    float acc[4][2][4];
    #pragma unroll
    for (int a = 0; a < 4; a++)
        #pragma unroll
        for (int b = 0; b < 2; b++)
            #pragma unroll
            for (int c = 0; c < 4; c++) acc[a][b][c] = 0.f;

    auto load_stage = [&](int tt, int s) {
        uint32_t base = sb + s * 49152;
        const __nv_bfloat16* pAh = gAh + tt * 64;
        const __nv_bfloat16* pAl = gAl + tt * 64;
        const __nv_bfloat16* pBh = gBh + tt * 64;
        const __nv_bfloat16* pBl = gBl + tt * 64;
        #pragma unroll
        for (int q = 0; q < 4; q++) {
            int c = ac0 + q;
            uint32_t off = ar * 128 + ((c ^ (ar & 7)) << 4);
            CPA16(base + off,         pAh + c * 8);
            CPA16(base + 16384 + off, pAl + c * 8);
        }
        #pragma unroll
        for (int q = 0; q < 2; q++) {
            int c = bc0 + q;
            uint32_t off = br * 128 + ((c ^ (br & 7)) << 4);
            CPA16(base + 32768 + off, pBh + c * 8);
            CPA16(base + 40960 + off, pBl + c * 8);
        }
    };

    load_stage(0, 0);
    CPC();

    for (int tt = 0; tt < T; tt++) {
        if (tt + 1 < T) {
            load_stage(tt + 1, (tt + 1) & 1);
            CPC();
            asm volatile("cp.async.wait_group 1;" ::: "memory");
        } else {
            asm volatile("cp.async.wait_group 0;" ::: "memory");
        }
        __syncthreads();

        uint32_t base = sb + (tt & 1) * 49152;
        #pragma unroll
        for (int ks = 0; ks < 4; ks++) {
            uint32_t ahf[4][4], alf[4][4], bhf[4], blf[4];
            int ch = ks * 2 + kh;
            #pragma unroll
            for (int mi = 0; mi < 4; mi++) {
                int r = m0 + mi * 16 + lr;
                uint32_t a = base + r * 128 + ((ch ^ (r & 7)) << 4);
                LDSM4(ahf[mi][0], ahf[mi][1], ahf[mi][2], ahf[mi][3], a);
                LDSM4(alf[mi][0], alf[mi][1], alf[mi][2], alf[mi][3], a + 16384);
            }
            int bch = ks * 2 + bko;
            uint32_t ba = base + 32768 + brow * 128 + ((bch ^ (brow & 7)) << 4);
            LDSM4(bhf[0], bhf[1], bhf[2], bhf[3], ba);
            LDSM4(blf[0], blf[1], blf[2], blf[3], ba + 8192);

            #pragma unroll
            for (int mi = 0; mi < 4; mi++) {
                #pragma unroll
                for (int nf = 0; nf < 2; nf++) {
                    MMA16816(acc[mi][nf], ahf[mi], bhf + 2 * nf);
                    MMA16816(acc[mi][nf], ahf[mi], blf + 2 * nf);
                    MMA16816(acc[mi][nf], alf[mi], bhf + 2 * nf);
                }
            }
        }
        __syncthreads();
    }

    #pragma unroll
    for (int mi = 0; mi < 4; mi++) {
        #pragma unroll
        for (int nf = 0; nf < 2; nf++) {
            int ocl = col0 + n0 + nf * 8 + (lane & 3) * 2;
            float b0, b1;
            if (LAYER == 1) {
                b0 = (ocl < 256) ? biasA[ocl] : biasB[ocl - 256];
                b1 = (ocl + 1 < 256) ? biasA[ocl + 1] : biasB[ocl + 1 - 256];
            } else {
                const float* bb = z ? biasB : biasA;
                b0 = bb[ocl]; b1 = bb[ocl + 1];
            }
            int ocg = (LAYER == 1) ? ocl : z * 256 + ocl;
            #pragma unroll
            for (int h = 0; h < 2; h++) {
                int row = row0 + m0 + mi * 16 + (lane >> 2) + h * 8;
                float v0 = fmaxf(acc[mi][nf][h * 2 + 0] + b0, 0.f);
                float v1 = fmaxf(acc[mi][nf][h * 2 + 1] + b1, 0.f);
                size_t idx = (size_t)row * 512 + ocg;
                if (LAYER == 2) {
                    *(float2*)(g_m2 + idx) = make_float2(v0, v1);
                } else {
                    __nv_bfloat16 h0, l0, h1, l1;
                    bsplit(v0, h0, l0);
                    bsplit(v1, h1, l1);
                    *(__nv_bfloat162*)(g_mh + idx) = __halves2bfloat162(h0, h1);
                    *(__nv_bfloat162*)(g_ml + idx) = __halves2bfloat162(l0, l1);
                }
            }
        }
    }
}

// ---------------- weight split kernels ----------------
// fc_w1 split WITH the conv epilogue K-permutation; invalid (pos>=250) -> 0.
__global__ void wsplit0(const float* __restrict__ w)
{
    int i = blockIdx.x * 256 + threadIdx.x;    // grid 8192 -> 256*8192 threads
    int r  = i >> 13;
    int kp = i & (KPAD - 1);
    int wq  = kp >> 10;
    int rem = kp & 1023;
    int mi = rem >> 9;
    int c  = (rem >> 8) & 1;
    int l  = (rem >> 3) & 31;
    int e  = rem & 7;
    int idx = e & 3;
    int nj  = c * 2 + (e >> 2);
    int oc  = mi * 16 + (l >> 2) + (idx >> 1) * 8;
    int pos = wq * 32 + nj * 8 + (l & 3) * 2 + (e & 1);
    float v = (pos < 250) ? w[r * 8000 + oc * 250 + pos] : 0.f;
    __nv_bfloat16 hh, ll;
    bsplit(v, hh, ll);
    g_fwh[i] = hh;
    g_fwl[i] = ll;
}
__global__ void wsplit4(const float* __restrict__ w0, const float* __restrict__ w1,
                        const float* __restrict__ w2, const float* __restrict__ w3)
{
    int i = blockIdx.x * 256 + threadIdx.x;
    int which = i >> 16, j = i & 65535;
    const float* src = (which == 0) ? w0 : (which == 1) ? w1 : (which == 2) ? w2 : w3;
    __nv_bfloat16 hh, ll;
    bsplit(src[j], hh, ll);
    g_qwh[i] = hh;
    g_qwl[i] = ll;
}
// conv w2 pre-split + zero g_stats accumulators (needed fresh per graph replay)
__global__ void wsplit_cv(const float* __restrict__ w2)
{
    int idx = threadIdx.x + blockIdx.x * 256;
    if (idx < 128) g_stats[idx] = 0.f;
    if (idx >= 3072) return;
    int oc = idx / 96, rem = idx % 96;
    int ic = rem / 3, tap = rem % 3;
    __nv_bfloat16 hh, ll;
    bsplit(w2[idx], hh, ll);
    int o = oc * 104 + tap * 32 + ic;
    g_cw2h[o] = hh;
    g_cw2l[o] = ll;
}

// ============ fused conv1(SIMT) + conv2(bf16x3 MMA), permuted-K out ============
#define CV_SMEM 56960
#define CV_SCAN 0
#define CV_W1   1024
#define CV_B1   1664
#define CV_B2   1792
#define CV_H1H  2048
#define CV_H1L  22848
#define CV_W2H  43648
#define CV_W2L  50304

__global__ void __launch_bounds__(256, 3) conv_kernel(
    const float* __restrict__ scan,
    const float* __restrict__ w1, const float* __restrict__ b1,
    const float* __restrict__ b2)
{
    extern __shared__ char smem[];
    const uint32_t sb = smem_u32(smem);
    float* s_scan = (float*)(smem + CV_SCAN);
    float* s_w1   = (float*)(smem + CV_W1);
    float* s_b1   = (float*)(smem + CV_B1);
    float* s_b2   = (float*)(smem + CV_B2);
    __nv_bfloat16* s_h1h = (__nv_bfloat16*)(smem + CV_H1H);
    __nv_bfloat16* s_h1l = (__nv_bfloat16*)(smem + CV_H1L);

    const int t = threadIdx.x, lane = t & 31, wid = t >> 5;
    const int row = blockIdx.x;

    // copy pre-split w2 (6656B per array = 416 x 16B)
    for (int i = t; i < 416; i += 256) {
        CPA16(sb + CV_W2H + i * 16, (const char*)g_cw2h + i * 16);
        CPA16(sb + CV_W2L + i * 16, (const char*)g_cw2l + i * 16);
    }
    CPC();

    s_scan[t] = scan[(size_t)row * 256 + t];
    if (t < 160) s_w1[t] = w1[t];
    if (t < 32) { s_b1[t] = b1[t]; s_b2[t] = b2[t]; }
    asm volatile("cp.async.wait_group 0;" ::: "memory");
    __syncthreads();

    // conv1 (fp32, rolling register window; 1 broadcast LDS per step)
    {
        const int ic = lane;
        const int pbase = wid * 32;
        float wv[5];
        #pragma unroll
        for (int k = 0; k < 5; k++) wv[k] = s_w1[ic * 5 + k];
        const float bb = s_b1[ic];
        float win[5];
        #pragma unroll
        for (int k = 0; k < 4; k++) win[k] = s_scan[pbase + k];
        #pragma unroll
        for (int i = 0; i < 32; i++) {
            int p = pbase + i;
            win[4] = s_scan[(p + 4) & 255];
            float a = bb + wv[0] * win[0] + wv[1] * win[1] + wv[2] * win[2]
                         + wv[3] * win[3] + wv[4] * win[4];
            a = fmaxf(a, 0.f);
            if (p >= 252) a = 0.f;
            __nv_bfloat16 hh, ll;
            bsplit(a, hh, ll);
            s_h1h[p * 40 + ic] = hh;
            s_h1l[p * 40 + ic] = ll;
            win[0] = win[1]; win[1] = win[2]; win[2] = win[3]; win[3] = win[4];
        }
    }
    // zero-pad positions 256..259 (ldsm B-frags read rows up to 257)
    if (t < 128) {
        int p = 256 + (t >> 5), ic = t & 31;
        s_h1h[p * 40 + ic] = __float2bfloat16(0.f);
        s_h1l[p * 40 + ic] = __float2bfloat16(0.f);
    }
    __syncthreads();

    const int n0 = wid * 32;
    const int lr = lane & 15;
    const int kh = lane >> 4;
    const int browl = (lane & 7) + ((lane >> 4) << 3);
    const int bko = (lane >> 3) & 1;

    float acc[2][4][4];
    #pragma unroll
    for (int a = 0; a < 2; a++)
        #pragma unroll
        for (int b = 0; b < 4; b++)
            #pragma unroll
            for (int c = 0; c < 4; c++) acc[a][b][c] = 0.f;

    #pragma unroll
    for (int ks = 0; ks < 6; ks++) {
        int tap = ks >> 1;
        int ic16 = (ks & 1) * 32;

        uint32_t awh[2][4], awl[2][4];
        #pragma unroll
        for (int mi = 0; mi < 2; mi++) {
            uint32_t a = sb + CV_W2H + (mi * 16 + lr) * 208 + ks * 32 + kh * 16;
            LDSM4(awh[mi][0], awh[mi][1], awh[mi][2], awh[mi][3], a);
            LDSM4(awl[mi][0], awl[mi][1], awl[mi][2], awl[mi][3], a + 6656);
        }
        uint32_t bh[2][4], bl[2][4];
        #pragma unroll
        for (int nt = 0; nt < 2; nt++) {
            int nrow = n0 + nt * 16 + browl + tap;
            uint32_t b = sb + CV_H1H + nrow * 80 + ic16 + bko * 16;
            LDSM4(bh[nt][0], bh[nt][1], bh[nt][2], bh[nt][3], b);
            LDSM4(bl[nt][0], bl[nt][1], bl[nt][2], bl[nt][3], b + 20800);
        }
        #pragma unroll
        for (int mi = 0; mi < 2; mi++) {
            #pragma unroll
            for (int nj = 0; nj < 4; nj++) {
                int nt = nj >> 1, hf = (nj & 1) * 2;
                MMA16816(acc[mi][nj], awh[mi], &bh[nt][hf]);
                MMA16816(acc[mi][nj], awh[mi], &bl[nt][hf]);
                MMA16816(acc[mi][nj], awl[mi], &bh[nt][hf]);
            }
        }
    }

    // epilogue: permuted-K, fully coalesced 16B stores.
    // k' = wid*1024 + mi*512 + c*256 + lane*8 + e, e = u*2 + j,
    //   nj = c*2 + (u>>1), idx = ((u&1)*2) + j, h = u&1
    __nv_bfloat16* oh = g_ah + (size_t)row * KPAD;
    __nv_bfloat16* ol = g_al + (size_t)row * KPAD;
    #pragma unroll
    for (int mi = 0; mi < 2; mi++) {
        float b_lo = s_b2[mi * 16 + (lane >> 2)];
        float b_hi = s_b2[mi * 16 + (lane >> 2) + 8];
        #pragma unroll
        for (int c = 0; c < 2; c++) {
            uint32_t ph[4], pl[4];
            #pragma unroll
            for (int u = 0; u < 4; u++) {
                int nj = c * 2 + (u >> 1);
                int idx0 = (u & 1) * 2;
                float bb = (u & 1) ? b_hi : b_lo;
                float v0 = fmaxf(acc[mi][nj][idx0 + 0] + bb, 0.f);
                float v1 = fmaxf(acc[mi][nj][idx0 + 1] + bb, 0.f);
                __nv_bfloat16 h0, l0, h1, l1;
                bsplit(v0, h0, l0);
                bsplit(v1, h1, l1);
                __nv_bfloat162 hh = __halves2bfloat162(h0, h1);
                __nv_bfloat162 ll = __halves2bfloat162(l0, l1);
                ph[u] = *(uint32_t*)&hh;
                pl[u] = *(uint32_t*)&ll;
            }
            size_t off = (size_t)wid * 1024 + mi * 512 + c * 256 + lane * 8;
            *(uint4*)(oh + off) = make_uint4(ph[0], ph[1], ph[2], ph[3]);
            *(uint4*)(ol + off) = make_uint4(pl[0], pl[1], pl[2], pl[3]);
        }
    }
}

// -------- fc1 combine + fc2 (256->10) + concat -> g_inps --------
__global__ void __launch_bounds__(256) fc2_concat(
    const float* __restrict__ w2, const float* __restrict__ b2,
    const float* __restrict__ b1,
    const float* __restrict__ obs, const float* __restrict__ acts)
{
    __shared__ float fs[8][10];
    int warp = threadIdx.x >> 5, lane = threadIdx.x & 31;
    int r = blockIdx.x * 8 + warp;

    const float* p0 = g_part + (size_t)r * 256;
    const float* p1 = p0 + (size_t)NROW * 256;
    const float* p2 = p1 + (size_t)NROW * 256;
    float x[8];
    #pragma unroll
    for (int i = 0; i < 8; i++) {
        int c = lane + 32 * i;
        x[i] = fmaxf(p0[c] + p1[c] + p2[c] + b1[c], 0.f);
    }

    #pragma unroll
    for (int j = 0; j < 10; j++) {
        float s = 0.f;
        #pragma unroll
        for (int i = 0; i < 8; i++) s += x[i] * w2[j * 256 + lane + 32 * i];
        #pragma unroll
        for (int off = 16; off; off >>= 1) s += __shfl_xor_sync(0xffffffffu, s, off);
        if (lane == 0) fs[warp][j] = s + b2[j];
    }
    __syncwarp();

    float* ir = g_inps + (size_t)r * 60;
    for (int c = lane; c < 60; c += 32) {
        float v;
        if (c < 48)      v = obs[(size_t)r * 48 + c];
        else if (c < 50) v = acts[(size_t)r * 2 + (c - 48)];
        else             v = fs[warp][c - 50];
        ir[c] = v;
    }
}

// ---------------- batch stats: coalesced partial pass + finalize ----------------
__global__ void __launch_bounds__(256) stats_part()
{
    __shared__ float sh_s[64], sh_q[64];
    int t = threadIdx.x;
    if (t < 64) { sh_s[t] = 0.f; sh_q[t] = 0.f; }
    __syncthreads();

    const float* base = g_inps + (size_t)blockIdx.x * 128 * 60;
    for (int i = t; i < 128 * 60; i += 256) {
        float v = base[i];
        int c = i % 60;
        atomicAdd(&sh_s[c], v);
        atomicAdd(&sh_q[c], v * v);
    }
    __syncthreads();
    if (t < 60) {
        atomicAdd(&g_stats[t], sh_s[t]);
        atomicAdd(&g_stats[64 + t], sh_q[t]);
    }
}
__global__ void stats_fin()
{
    int c = threadIdx.x;
    if (c < 60) {
        float mu = g_stats[c] * (1.f / NROW);
        float var = g_stats[64 + c] * (1.f / NROW) - mu * mu;
        g_stats[c] = mu;
        g_stats[64 + c] = rsqrtf(var + 1e-5f);
    }
}

// -------- normalize + encoder(leaky) + keys/vals/q ----------
__global__ void __launch_bounds__(256) enc_kvq(
    const float* __restrict__ enc_w, const float* __restrict__ enc_b,
    const float* __restrict__ Wk, const float* __restrict__ Wv,
    const float* __restrict__ bv, const float* __restrict__ Wq)
{
    __shared__ float xn[32][60];
    __shared__ float sas[32][128];
    __shared__ float wch[32][129];
    __shared__ float mu_s[60], inv_s[60];

    int t = threadIdx.x;
    int row0 = blockIdx.x * 32;
    int g = row0 >> 12;

    if (t < 60) { mu_s[t] = g_stats[t]; inv_s[t] = g_stats[64 + t]; }
    __syncthreads();

    for (int idx = t; idx < 32 * 60; idx += 256) {
        int r = idx / 60, c = idx % 60;
        xn[r][c] = (g_inps[(size_t)(row0 + r) * 60 + c] - mu_s[c]) * inv_s[c];
    }
    __syncthreads();

    int jj = t & 31, rg = t >> 5;

    for (int jc = 0; jc < 4; jc++) {
        for (int idx = t; idx < 32 * 60; idx += 256) {
            int rr = idx / 60, c = idx % 60;
            wch[rr][c] = enc_w[(jc * 32 + rr) * 60 + c];
        }
        __syncthreads();

        float a0 = 0.f, a1 = 0.f, a2 = 0.f, a3 = 0.f;
        #pragma unroll
        for (int c = 0; c < 60; c++) {
            float w = wch[jj][c];
            a0 += xn[rg * 4 + 0][c] * w;
            a1 += xn[rg * 4 + 1][c] * w;
            a2 += xn[rg * 4 + 2][c] * w;
            a3 += xn[rg * 4 + 3][c] * w;
        }
        float bb = enc_b[jc * 32 + jj];
        float v[4] = {a0 + bb, a1 + bb, a2 + bb, a3 + bb};
        int col = jc * 32 + jj;
        #pragma unroll
        for (int q = 0; q < 4; q++) {
            float vv = (v[q] >= 0.f) ? v[q] : 0.01f * v[q];
            sas[rg * 4 + q][col] = vv;
            __nv_bfloat16 hh, ll;
            bsplit(vv, hh, ll);
            size_t idx = (size_t)(row0 + rg * 4 + q) * 256 + col;
            g_embh[idx] = hh;
            g_embl[idx] = ll;
        }
        __syncthreads();
    }

    for (int m = 0; m < 3; m++) {
        const float* W = (m == 0) ? Wk : (m == 1) ? Wv : (Wq + (size_t)g * 128 * 128);
        float* Out     = (m == 0) ? g_keys : (m == 1) ? g_vals : g_q;
        for (int jc = 0; jc < 4; jc++) {
            for (int idx = t; idx < 32 * 128; idx += 256) {
                int rr = idx >> 7, c = idx & 127;
                wch[rr][c] = W[(jc * 32 + rr) * 128 + c];
            }
            __syncthreads();

            float a0 = 0.f, a1 = 0.f, a2 = 0.f, a3 = 0.f;
            #pragma unroll
            for (int c = 0; c < 128; c++) {
                float w = wch[jj][c];
                a0 += sas[rg * 4 + 0][c] * w;
                a1 += sas[rg * 4 + 1][c] * w;
                a2 += sas[rg * 4 + 2][c] * w;
                a3 += sas[rg * 4 + 3][c] * w;
            }
            int col = jc * 32 + jj;
            if (m == 1) {
                float bb = bv[col];
                a0 += bb; a1 += bb; a2 += bb; a3 += bb;
                a0 = (a0 >= 0.f) ? a0 : 0.01f * a0;
                a1 = (a1 >= 0.f) ? a1 : 0.01f * a1;
                a2 = (a2 >= 0.f) ? a2 : 0.01f * a2;
                a3 = (a3 >= 0.f) ? a3 : 0.01f * a3;
            }
            Out[(size_t)(row0 + rg * 4 + 0) * 128 + col] = a0;
            Out[(size_t)(row0 + rg * 4 + 1) * 128 + col] = a1;
            Out[(size_t)(row0 + rg * 4 + 2) * 128 + col] = a2;
            Out[(size_t)(row0 + rg * 4 + 3) * 128 + col] = a3;
            __syncthreads();
        }
    }
}

// ---------------- tiny 3-agent cross-attention ----------------
__global__ void __launch_bounds__(128) attn_kernel()
{
    __shared__ float qs[3][128], ks[3][128], vs[3][128];
    int b = blockIdx.x;
    int t = threadIdx.x;

    #pragma unroll
    for (int g = 0; g < 3; g++) {
        size_t roff = (size_t)(g * BSZ + b) * 128 + t;
        qs[g][t] = g_q[roff];
        ks[g][t] = g_keys[roff];
        vs[g][t] = g_vals[roff];
    }
    __syncthreads();

    const float scale = 0.25f;
    #pragma unroll
    for (int g = 0; g < 3; g++) {
        int o1 = (g == 0) ? 1 : 0;
        int o2 = (g == 2) ? 1 : 2;
        float q = qs[g][t];
        float p1 = q * ks[o1][t];
        float p2 = q * ks[o2][t];
        #pragma unroll
        for (int off = 8; off; off >>= 1) {
            p1 += __shfl_xor_sync(0xffffffffu, p1, off);
            p2 += __shfl_xor_sync(0xffffffffu, p2, off);
        }
        float l1 = p1 * scale, l2 = p2 * scale;
        float mx = fmaxf(l1, l2);
        float e1 = expf(l1 - mx), e2 = expf(l2 - mx);
        float inv = 1.f / (e1 + e2);
        float other = (e1 * vs[o1][t] + e2 * vs[o2][t]) * inv;
        __nv_bfloat16 hh, ll;
        bsplit(other, hh, ll);
        size_t idx = (size_t)(g * BSZ + b) * 256 + 128 + t;
        g_embh[idx] = hh;
        g_embl[idx] = ll;
    }
}

// ---------------- fused final dots (q1 & q2) ----------------
__global__ void __launch_bounds__(256) final_dot2(
    const float* __restrict__ w3a, const float* __restrict__ b3a,
    const float* __restrict__ w3b, const float* __restrict__ b3b,
    float* __restrict__ out)
{
    int warp = threadIdx.x >> 5, lane = threadIdx.x & 31;
    int r = blockIdx.x * 8 + warp;
    const float* xr = g_m2 + (size_t)r * 512;
    float s1 = 0.f, s2 = 0.f;
    #pragma unroll
    for (int i = 0; i < 8; i++) {
        int c = lane + 32 * i;
        s1 += xr[c] * w3a[c];
        s2 += xr[256 + c] * w3b[c];
    }
    #pragma unroll
    for (int off = 16; off; off >>= 1) {
        s1 += __shfl_xor_sync(0xffffffffu, s1, off);
        s2 += __shfl_xor_sync(0xffffffffu, s2, off);
    }
    if (lane == 0) {
        out[r] = s1 + b3a[0];
        out[NROW + r] = s2 + b3b[0];
    }
}

// ---------------- launch ----------------
extern "C" void kernel_launch(void* const* d_in, const int* in_sizes, int n_in,
                              void* d_out, int out_size)
{
    const float* obs     = (const float*)d_in[0];
    const float* acts    = (const float*)d_in[1];
    const float* scan    = (const float*)d_in[2];
    const float* conv_w1 = (const float*)d_in[3];
    const float* conv_b1 = (const float*)d_in[4];
    const float* conv_w2 = (const float*)d_in[5];
    const float* conv_b2 = (const float*)d_in[6];
    const float* fc_w1   = (const float*)d_in[7];
    const float* fc_b1   = (const float*)d_in[8];
    const float* fc_w2   = (const float*)d_in[9];
    const float* fc_b2   = (const float*)d_in[10];
    const float* enc_w   = (const float*)d_in[11];
    const float* enc_b   = (const float*)d_in[12];
    const float* Wk      = (const float*)d_in[13];
    const float* Wv      = (const float*)d_in[14];
    const float* bv      = (const float*)d_in[15];
    const float* Wq      = (const float*)d_in[16];
    const float* q1_w1   = (const float*)d_in[17];
    const float* q1_b1   = (const float*)d_in[18];
    const float* q1_w2   = (const float*)d_in[19];
    const float* q1_b2   = (const float*)d_in[20];
    const float* q1_w3   = (const float*)d_in[21];
    const float* q1_b3   = (const float*)d_in[22];
    const float* q2_w1   = (const float*)d_in[23];
    const float* q2_b1   = (const float*)d_in[24];
    const float* q2_w2   = (const float*)d_in[25];
    const float* q2_b2   = (const float*)d_in[26];
    const float* q2_w3   = (const float*)d_in[27];
    const float* q2_b3   = (const float*)d_in[28];
    float* out = (float*)d_out;

    cudaFuncSetAttribute(fc1_gemm, cudaFuncAttributeMaxDynamicSharedMemorySize, FSMEM);
    cudaFuncSetAttribute(mlp_gemm<1>, cudaFuncAttributeMaxDynamicSharedMemorySize, GSMEM);
    cudaFuncSetAttribute(mlp_gemm<2>, cudaFuncAttributeMaxDynamicSharedMemorySize, GSMEM);
    cudaFuncSetAttribute(conv_kernel, cudaFuncAttributeMaxDynamicSharedMemorySize, CV_SMEM);

    // weight splits (wsplit_cv also zeroes g_stats accumulators)
    wsplit_cv<<<12, 256>>>(conv_w2);
    wsplit0<<<KPAD, 256>>>(fc_w1);
    wsplit4<<<1024, 256>>>(q1_w1, q2_w1, q1_w2, q2_w2);

    conv_kernel<<<NROW, 256, CV_SMEM>>>(scan, conv_w1, conv_b1, conv_b2);
    fc1_gemm<<<dim3(2, 96, 3), 256, FSMEM>>>();
    fc2_concat<<<NROW / 8, 256>>>(fc_w2, fc_b2, fc_b1, obs, acts);
    stats_part<<<96, 256>>>();
    stats_fin<<<1, 64>>>();
    enc_kvq<<<NROW / 32, 256>>>(enc_w, enc_b, Wk, Wv, bv, Wq);
    attn_kernel<<<BSZ, 128>>>();

    mlp_gemm<1><<<dim3(8, 96), 256, GSMEM>>>(q1_b1, q2_b1);
    mlp_gemm<2><<<dim3(4, 96, 2), 256, GSMEM>>>(q1_b2, q2_b2);
    final_dot2<<<NROW / 8, 256>>>(q1_w3, q1_b3, q2_w3, q2_b3, out);
}

// round 10
// speedup vs baseline: 4.7966x; 1.0217x over previous
#include <cuda_runtime.h>
#include <cuda_bf16.h>
#include <math.h>
#include <cstdint>

#define NROW 12288
#define BSZ  4096
#define KPAD 8192

// ---------------- scratch (device globals; no allocations) ----------------
__device__ __nv_bfloat16 g_ah[(size_t)NROW * KPAD];  // conv output hi (permuted K)
__device__ __nv_bfloat16 g_al[(size_t)NROW * KPAD];  // conv output lo
__device__ __nv_bfloat16 g_fwh[256 * KPAD];          // fc_w1 hi (same permutation)
__device__ __nv_bfloat16 g_fwl[256 * KPAD];          // fc_w1 lo
__device__ __nv_bfloat16 g_qwh[4 * 256 * 256];       // q1_w1,q2_w1,q1_w2,q2_w2 hi
__device__ __nv_bfloat16 g_qwl[4 * 256 * 256];       // lo
__device__ __nv_bfloat16 g_cw2h[32 * 104];           // conv w2 pre-split (smem layout)
__device__ __nv_bfloat16 g_cw2l[32 * 104];
__device__ float g_part[3 * (size_t)NROW * 256];     // fc1 K-split partials
__device__ float g_inps[NROW * 60];
__device__ float g_stats[128];
__device__ __nv_bfloat16 g_embh[NROW * 256];
__device__ __nv_bfloat16 g_embl[NROW * 256];
__device__ __nv_bfloat16 g_mh[(size_t)NROW * 512];
__device__ __nv_bfloat16 g_ml[(size_t)NROW * 512];
__device__ float g_m2[(size_t)NROW * 512];
__device__ float g_keys[NROW * 128];
__device__ float g_vals[NROW * 128];
__device__ float g_q[NROW * 128];

// ====================== helpers ======================
__device__ __forceinline__ uint32_t smem_u32(const void* p) {
    uint32_t a;
    asm("{ .reg .u64 t; cvta.to.shared.u64 t, %1; cvt.u32.u64 %0, t; }"
        : "=r"(a) : "l"(p));
    return a;
}
__device__ __forceinline__ void bsplit(float v, __nv_bfloat16& h, __nv_bfloat16& l) {
    h = __float2bfloat16(v);
    l = __float2bfloat16(v - __bfloat162float(h));
}
#define CPA16(s, g) \
    asm volatile("cp.async.cg.shared.global [%0], [%1], 16;" :: "r"(s), "l"(g))
#define CPC() asm volatile("cp.async.commit_group;" ::: "memory")
#define LDSM4(r0, r1, r2, r3, a) \
    asm volatile("ldmatrix.sync.aligned.m8n8.x4.shared.b16 {%0,%1,%2,%3}, [%4];" \
                 : "=r"(r0), "=r"(r1), "=r"(r2), "=r"(r3) : "r"(a))
#define MMA16816(d, a, b) \
    asm volatile("mma.sync.aligned.m16n8k16.row.col.f32.bf16.bf16.f32 " \
                 "{%0,%1,%2,%3},{%4,%5,%6,%7},{%8,%9},{%0,%1,%2,%3};" \
                 : "+f"((d)[0]), "+f"((d)[1]), "+f"((d)[2]), "+f"((d)[3]) \
                 : "r"((a)[0]), "r"((a)[1]), "r"((a)[2]), "r"((a)[3]), \
                   "r"((b)[0]), "r"((b)[1]))

// ================= fc1: bf16x3 GEMM, BM128/BN128/BK32, 3-stage, K-split =========
#define FSMEM (3 * 32768)
__global__ void __launch_bounds__(256, 2) fc1_gemm()
{
    extern __shared__ char smem[];
    const uint32_t sb = smem_u32(smem);

    const int t = threadIdx.x, lane = t & 31, wid = t >> 5;
    const int bn = blockIdx.x, bm = blockIdx.y, z = blockIdx.z;
    const int kt0 = (z == 0) ? 0 : (z == 1) ? 86 : 171;
    const int T   = (z == 0) ? 86 : 85;
    const int row0 = bm * 128, col0 = bn * 128;

    const int fr = t >> 1;
    const int c0 = (t & 1) * 2;
    const __nv_bfloat16* gAh = g_ah + (size_t)(row0 + fr) * KPAD + kt0 * 32;
    const __nv_bfloat16* gAl = g_al + (size_t)(row0 + fr) * KPAD + kt0 * 32;
    const __nv_bfloat16* gBh = g_fwh + (size_t)(col0 + fr) * KPAD + kt0 * 32;
    const __nv_bfloat16* gBl = g_fwl + (size_t)(col0 + fr) * KPAD + kt0 * 32;
    const int fsw = (fr >> 1) & 3;

    const int mw = wid & 1, nw = wid >> 1;

    float acc[4][4][4];
    #pragma unroll
    for (int a = 0; a < 4; a++)
        #pragma unroll
        for (int b = 0; b < 4; b++)
            #pragma unroll
            for (int c = 0; c < 4; c++) acc[a][b][c] = 0.f;

    auto fill = [&](int tt, int s) {
        uint32_t base = sb + s * 32768;
        const __nv_bfloat16* pAh = gAh + (size_t)tt * 32;
        const __nv_bfloat16* pAl = gAl + (size_t)tt * 32;
        const __nv_bfloat16* pBh = gBh + (size_t)tt * 32;
        const __nv_bfloat16* pBl = gBl + (size_t)tt * 32;
        #pragma unroll
        for (int j = 0; j < 2; j++) {
            int c = c0 + j;
            uint32_t off = fr * 64 + ((c ^ fsw) << 4);
            CPA16(base + off,         pAh + c * 8);
            CPA16(base + 8192 + off,  pAl + c * 8);
            CPA16(base + 16384 + off, pBh + c * 8);
            CPA16(base + 24576 + off, pBl + c * 8);
        }
    };

    fill(0, 0); CPC();
    fill(1, 1); CPC();

    for (int tt = 0; tt < T; tt++) {
        asm volatile("cp.async.wait_group 1;" ::: "memory");
        __syncthreads();

        const uint32_t stu = sb + (tt % 3) * 32768;
        #pragma unroll
        for (int ks = 0; ks < 2; ks++) {
            uint32_t bhf[2][4], blf[2][4];
            #pragma unroll
            for (int nt = 0; nt < 2; nt++) {
                int nr = nw * 32 + nt * 16 + (lane & 7) + ((lane >> 4) << 3);
                int cs = (ks * 2 + ((lane >> 3) & 1)) ^ ((nr >> 1) & 3);
                uint32_t ba = stu + 16384 + nr * 64 + cs * 16;
                LDSM4(bhf[nt][0], bhf[nt][1], bhf[nt][2], bhf[nt][3], ba);
                LDSM4(blf[nt][0], blf[nt][1], blf[nt][2], blf[nt][3], ba + 8192);
            }
            #pragma unroll
            for (int mi = 0; mi < 4; mi++) {
                int r = mw * 64 + mi * 16 + (lane & 15);
                int cs = (ks * 2 + (lane >> 4)) ^ ((r >> 1) & 3);
                uint32_t aa = stu + r * 64 + cs * 16;
                uint32_t ah[4], al[4];
                LDSM4(ah[0], ah[1], ah[2], ah[3], aa);
                LDSM4(al[0], al[1], al[2], al[3], aa + 8192);
                #pragma unroll
                for (int nj = 0; nj < 4; nj++) {
                    int nt = nj >> 1, hf = (nj & 1) * 2;
                    MMA16816(acc[mi][nj], ah, &bhf[nt][hf]);
                    MMA16816(acc[mi][nj], ah, &blf[nt][hf]);
                    MMA16816(acc[mi][nj], al, &bhf[nt][hf]);
                }
            }
        }

        if (tt + 2 < T) fill(tt + 2, (tt + 2) % 3);
        CPC();
    }

    float* P = g_part + (size_t)z * NROW * 256;
    #pragma unroll
    for (int mi = 0; mi < 4; mi++) {
        #pragma unroll
        for (int nj = 0; nj < 4; nj++) {
            int col = col0 + nw * 32 + nj * 8 + (lane & 3) * 2;
            #pragma unroll
            for (int h = 0; h < 2; h++) {
                int row = row0 + mw * 64 + mi * 16 + (lane >> 2) + h * 8;
                *(float2*)(P + (size_t)row * 256 + col) =
                    make_float2(acc[mi][nj][h * 2], acc[mi][nj][h * 2 + 1]);
            }
        }
    }
}

// ============ MLP GEMM: BM64/BN128/BK32, 3-stage, warp tile 32x32, bf16x3 ========
// LAYER 1: A=emb(256), B=q1_w1|q2_w1 (512 rows), out split -> g_mh/g_ml[512]
// LAYER 2: z: A=g_mh+z*256 (stride 512), B slot 2+z, out fp32 -> g_m2 col z*256+
#define GSMEM (3 * 24576)
template <int LAYER>
__global__ void __launch_bounds__(256, 2) mlp_gemm(
    const float* __restrict__ biasA, const float* __restrict__ biasB)
{
    const int z = (LAYER == 2) ? blockIdx.z : 0;
    const __nv_bfloat16* Ah = (LAYER == 1) ? g_embh : g_mh + z * 256;
    const __nv_bfloat16* Al = (LAYER == 1) ? g_embl : g_ml + z * 256;
    const int AS = (LAYER == 1) ? 256 : 512;
    const __nv_bfloat16* Bh = (LAYER == 1) ? g_qwh : g_qwh + (2 + z) * 65536;
    const __nv_bfloat16* Bl = (LAYER == 1) ? g_qwl : g_qwl + (2 + z) * 65536;

    extern __shared__ char smem[];
    const uint32_t sb = smem_u32(smem);

    const int t = threadIdx.x, lane = t & 31, wid = t >> 5;
    const int row0 = blockIdx.y * 64, col0 = blockIdx.x * 128;

    const int ar = t >> 2, ac = t & 3;          // A: 1 chunk/buf
    const int br = t >> 1, bc0 = (t & 1) * 2;   // B: 2 chunks/buf
    const __nv_bfloat16* gAh = Ah + (size_t)(row0 + ar) * AS + ac * 8;
    const __nv_bfloat16* gAl = Al + (size_t)(row0 + ar) * AS + ac * 8;
    const __nv_bfloat16* gBh = Bh + (size_t)(col0 + br) * 256;
    const __nv_bfloat16* gBl = Bl + (size_t)(col0 + br) * 256;
    const uint32_t aoff = ar * 64 + ((ac ^ ((ar >> 1) & 3)) << 4);
    const int bsw = (br >> 1) & 3;

    const int mw = wid & 1, nw = wid >> 1;

    float acc[2][4][4];
    #pragma unroll
    for (int a = 0; a < 2; a++)
        #pragma unroll
        for (int b = 0; b < 4; b++)
            #pragma unroll
            for (int c = 0; c < 4; c++) acc[a][b][c] = 0.f;

    auto fill = [&](int tt, int s) {
        uint32_t base = sb + s * 24576;
        CPA16(base + aoff,        gAh + tt * 32);
        CPA16(base + 4096 + aoff, gAl + tt * 32);
        #pragma unroll
        for (int j = 0; j < 2; j++) {
            int c = bc0 + j;
            uint32_t boff = br * 64 + ((c ^ bsw) << 4);
            CPA16(base + 8192 + boff,  gBh + tt * 32 + c * 8);
            CPA16(base + 16384 + boff, gBl + tt * 32 + c * 8);
        }
    };

    fill(0, 0); CPC();
    fill(1, 1); CPC();

    const int T = 8;
    for (int tt = 0; tt < T; tt++) {
        asm volatile("cp.async.wait_group 1;" ::: "memory");
        __syncthreads();

        const uint32_t stu = sb + (tt % 3) * 24576;
        #pragma unroll
        for (int ks = 0; ks < 2; ks++) {
            uint32_t bhf[2][4], blf[2][4];
            #pragma unroll
            for (int nt = 0; nt < 2; nt++) {
                int nr = nw * 32 + nt * 16 + (lane & 7) + ((lane >> 4) << 3);
                int cs = (ks * 2 + ((lane >> 3) & 1)) ^ ((nr >> 1) & 3);
                uint32_t ba = stu + 8192 + nr * 64 + cs * 16;
                LDSM4(bhf[nt][0], bhf[nt][1], bhf[nt][2], bhf[nt][3], ba);
                LDSM4(blf[nt][0], blf[nt][1], blf[nt][2], blf[nt][3], ba + 8192);
            }
            #pragma unroll
            for (int mi = 0; mi < 2; mi++) {
                int r = mw * 32 + mi * 16 + (lane & 15);
                int cs = (ks * 2 + (lane >> 4)) ^ ((r >> 1) & 3);
                uint32_t aa = stu + r * 64 + cs * 16;
                uint32_t ah[4], al[4];
                LDSM4(ah[0], ah[1], ah[2], ah[3], aa);
                LDSM4(al[0], al[1], al[2], al[3], aa + 4096);
                #pragma unroll
                for (int nj = 0; nj < 4; nj++) {
                    int nt = nj >> 1, hf = (nj & 1) * 2;
                    MMA16816(acc[mi][nj], ah, &bhf[nt][hf]);
                    MMA16816(acc[mi][nj], ah, &blf[nt][hf]);
                    MMA16816(acc[mi][nj], al, &bhf[nt][hf]);
                }
            }
        }

        if (tt + 2 < T) fill(tt + 2, (tt + 2) % 3);
        CPC();
    }

    #pragma unroll
    for (int mi = 0; mi < 2; mi++) {
        #pragma unroll
        for (int nj = 0; nj < 4; nj++) {
            int ocl = col0 + nw * 32 + nj * 8 + (lane & 3) * 2;
            float b0, b1;
            if (LAYER == 1) {
                b0 = (ocl < 256) ? biasA[ocl] : biasB[ocl - 256];
                b1 = (ocl + 1 < 256) ? biasA[ocl + 1] : biasB[ocl + 1 - 256];
            } else {
                const float* bb = z ? biasB : biasA;
                b0 = bb[ocl]; b1 = bb[ocl + 1];
            }
            int ocg = (LAYER == 1) ? ocl : z * 256 + ocl;
            #pragma unroll
            for (int h = 0; h < 2; h++) {
                int row = row0 + mw * 32 + mi * 16 + (lane >> 2) + h * 8;
                float v0 = fmaxf(acc[mi][nj][h * 2 + 0] + b0, 0.f);
                float v1 = fmaxf(acc[mi][nj][h * 2 + 1] + b1, 0.f);
                size_t idx = (size_t)row * 512 + ocg;
                if (LAYER == 2) {
                    *(float2*)(g_m2 + idx) = make_float2(v0, v1);
                } else {
                    __nv_bfloat16 h0, l0, h1, l1;
                    bsplit(v0, h0, l0);
                    bsplit(v1, h1, l1);
                    *(__nv_bfloat162*)(g_mh + idx) = __halves2bfloat162(h0, h1);
                    *(__nv_bfloat162*)(g_ml + idx) = __halves2bfloat162(l0, l1);
                }
            }
        }
    }
}

// ---------------- weight split kernels ----------------
__global__ void wsplit0(const float* __restrict__ w)
{
    int i = blockIdx.x * 256 + threadIdx.x;
    int r  = i >> 13;
    int kp = i & (KPAD - 1);
    int wq  = kp >> 10;
    int rem = kp & 1023;
    int mi = rem >> 9;
    int c  = (rem >> 8) & 1;
    int l  = (rem >> 3) & 31;
    int e  = rem & 7;
    int idx = e & 3;
    int nj  = c * 2 + (e >> 2);
    int oc  = mi * 16 + (l >> 2) + (idx >> 1) * 8;
    int pos = wq * 32 + nj * 8 + (l & 3) * 2 + (e & 1);
    float v = (pos < 250) ? w[r * 8000 + oc * 250 + pos] : 0.f;
    __nv_bfloat16 hh, ll;
    bsplit(v, hh, ll);
    g_fwh[i] = hh;
    g_fwl[i] = ll;
}
__global__ void wsplit4(const float* __restrict__ w0, const float* __restrict__ w1,
                        const float* __restrict__ w2, const float* __restrict__ w3)
{
    int i = blockIdx.x * 256 + threadIdx.x;
    int which = i >> 16, j = i & 65535;
    const float* src = (which == 0) ? w0 : (which == 1) ? w1 : (which == 2) ? w2 : w3;
    __nv_bfloat16 hh, ll;
    bsplit(src[j], hh, ll);
    g_qwh[i] = hh;
    g_qwl[i] = ll;
}
// conv w2 pre-split + zero g_stats accumulators (needed fresh per graph replay)
__global__ void wsplit_cv(const float* __restrict__ w2)
{
    int idx = threadIdx.x + blockIdx.x * 256;
    if (idx < 128) g_stats[idx] = 0.f;
    if (idx >= 3072) return;
    int oc = idx / 96, rem = idx % 96;
    int ic = rem / 3, tap = rem % 3;
    __nv_bfloat16 hh, ll;
    bsplit(w2[idx], hh, ll);
    int o = oc * 104 + tap * 32 + ic;
    g_cw2h[o] = hh;
    g_cw2l[o] = ll;
}

// ====== persistent fused conv1(SIMT) + conv2(bf16x3 MMA), permuted-K out ======
#define CV_SMEM 57984
#define CV_SCAN 0          // 2 x 1024B double buffer
#define CV_W1   2048
#define CV_B1   2688
#define CV_B2   2816
#define CV_H1H  3072
#define CV_H1L  23872
#define CV_W2H  44672
#define CV_W2L  51328

__global__ void __launch_bounds__(256, 3) conv_kernel(
    const float* __restrict__ scan,
    const float* __restrict__ w1, const float* __restrict__ b1,
    const float* __restrict__ b2)
{
    extern __shared__ char smem[];
    const uint32_t sb = smem_u32(smem);
    float* s_w1   = (float*)(smem + CV_W1);
    float* s_b1   = (float*)(smem + CV_B1);
    float* s_b2   = (float*)(smem + CV_B2);
    __nv_bfloat16* s_h1h = (__nv_bfloat16*)(smem + CV_H1H);
    __nv_bfloat16* s_h1l = (__nv_bfloat16*)(smem + CV_H1L);

    const int t = threadIdx.x, lane = t & 31, wid = t >> 5;
    const int b = blockIdx.x;
    const int nrows = (b < 300) ? 28 : 27;
    const int start = b * 27 + min(b, 300);

    // one-time setup: w2 (13KB) + first scan row via cp.async
    for (int i = t; i < 416; i += 256) {
        CPA16(sb + CV_W2H + i * 16, (const char*)g_cw2h + i * 16);
        CPA16(sb + CV_W2L + i * 16, (const char*)g_cw2l + i * 16);
    }
    if (t < 64)
        CPA16(sb + CV_SCAN + t * 16, (const char*)(scan + (size_t)start * 256) + t * 16);
    CPC();
    if (t < 160) s_w1[t] = w1[t];
    if (t < 32) { s_b1[t] = b1[t]; s_b2[t] = b2[t]; }
    asm volatile("cp.async.wait_group 0;" ::: "memory");
    __syncthreads();

    // per-thread loop-invariant constants
    const int ic = lane;
    const int pbase = wid * 32;
    float wv[5];
    #pragma unroll
    for (int k = 0; k < 5; k++) wv[k] = s_w1[ic * 5 + k];
    const float c1b = s_b1[ic];

    const int n0 = wid * 32;
    const int lr = lane & 15;
    const int kh = lane >> 4;
    const int browl = (lane & 7) + ((lane >> 4) << 3);
    const int bko = (lane >> 3) & 1;
    const float eb_lo0 = s_b2[(lane >> 2)];
    const float eb_hi0 = s_b2[(lane >> 2) + 8];
    const float eb_lo1 = s_b2[16 + (lane >> 2)];
    const float eb_hi1 = s_b2[16 + (lane >> 2) + 8];

    for (int i = 0; i < nrows; i++) {
        const int row = start + i;
        const float* sc = (const float*)(smem + CV_SCAN + (i & 1) * 1024);

        // prefetch next scan row into the other buffer (overlaps conv1+MMA)
        if (i + 1 < nrows && t < 64)
            CPA16(sb + CV_SCAN + ((i + 1) & 1) * 1024 + t * 16,
                  (const char*)(scan + (size_t)(row + 1) * 256) + t * 16);
        CPC();

        // conv1 (rolling register window, 1 broadcast LDS per step)
        {
            float win[5];
            #pragma unroll
            for (int k = 0; k < 4; k++) win[k] = sc[pbase + k];
            #pragma unroll
            for (int q = 0; q < 32; q++) {
                int p = pbase + q;
                win[4] = sc[(p + 4) & 255];
                float a = c1b + wv[0] * win[0] + wv[1] * win[1] + wv[2] * win[2]
                              + wv[3] * win[3] + wv[4] * win[4];
                a = fmaxf(a, 0.f);
                if (p >= 252) a = 0.f;
                __nv_bfloat16 hh, ll;
                bsplit(a, hh, ll);
                s_h1h[p * 40 + ic] = hh;
                s_h1l[p * 40 + ic] = ll;
                win[0] = win[1]; win[1] = win[2]; win[2] = win[3]; win[3] = win[4];
            }
        }
        if (t < 128) {
            int p = 256 + (t >> 5), icc = t & 31;
            s_h1h[p * 40 + icc] = __float2bfloat16(0.f);
            s_h1l[p * 40 + icc] = __float2bfloat16(0.f);
        }
        __syncthreads();

        float acc[2][4][4];
        #pragma unroll
        for (int a = 0; a < 2; a++)
            #pragma unroll
            for (int bq = 0; bq < 4; bq++)
                #pragma unroll
                for (int c = 0; c < 4; c++) acc[a][bq][c] = 0.f;

        #pragma unroll
        for (int ks = 0; ks < 6; ks++) {
            int tap = ks >> 1;
            int ic16 = (ks & 1) * 32;

            uint32_t awh[2][4], awl[2][4];
            #pragma unroll
            for (int mi = 0; mi < 2; mi++) {
                uint32_t a = sb + CV_W2H + (mi * 16 + lr) * 208 + ks * 32 + kh * 16;
                LDSM4(awh[mi][0], awh[mi][1], awh[mi][2], awh[mi][3], a);
                LDSM4(awl[mi][0], awl[mi][1], awl[mi][2], awl[mi][3], a + 6656);
            }
            uint32_t bh[2][4], bl[2][4];
            #pragma unroll
            for (int nt = 0; nt < 2; nt++) {
                int nrow = n0 + nt * 16 + browl + tap;
                uint32_t bb = sb + CV_H1H + nrow * 80 + ic16 + bko * 16;
                LDSM4(bh[nt][0], bh[nt][1], bh[nt][2], bh[nt][3], bb);
                LDSM4(bl[nt][0], bl[nt][1], bl[nt][2], bl[nt][3], bb + 20800);
            }
            #pragma unroll
            for (int mi = 0; mi < 2; mi++) {
                #pragma unroll
                for (int nj = 0; nj < 4; nj++) {
                    int nt = nj >> 1, hf = (nj & 1) * 2;
                    MMA16816(acc[mi][nj], awh[mi], &bh[nt][hf]);
                    MMA16816(acc[mi][nj], awh[mi], &bl[nt][hf]);
                    MMA16816(acc[mi][nj], awl[mi], &bh[nt][hf]);
                }
            }
        }

        // epilogue: permuted-K coalesced 16B stores
        __nv_bfloat16* oh = g_ah + (size_t)row * KPAD;
        __nv_bfloat16* ol = g_al + (size_t)row * KPAD;
        #pragma unroll
        for (int mi = 0; mi < 2; mi++) {
            float b_lo = mi ? eb_lo1 : eb_lo0;
            float b_hi = mi ? eb_hi1 : eb_hi0;
            #pragma unroll
            for (int c = 0; c < 2; c++) {
                uint32_t ph[4], pl[4];
                #pragma unroll
                for (int u = 0; u < 4; u++) {
                    int nj = c * 2 + (u >> 1);
                    int idx0 = (u & 1) * 2;
                    float bb = (u & 1) ? b_hi : b_lo;
                    float v0 = fmaxf(acc[mi][nj][idx0 + 0] + bb, 0.f);
                    float v1 = fmaxf(acc[mi][nj][idx0 + 1] + bb, 0.f);
                    __nv_bfloat16 h0, l0, h1, l1;
                    bsplit(v0, h0, l0);
                    bsplit(v1, h1, l1);
                    __nv_bfloat162 hh = __halves2bfloat162(h0, h1);
                    __nv_bfloat162 ll = __halves2bfloat162(l0, l1);
                    ph[u] = *(uint32_t*)&hh;
                    pl[u] = *(uint32_t*)&ll;
                }
                size_t off = (size_t)wid * 1024 + mi * 512 + c * 256 + lane * 8;
                *(uint4*)(oh + off) = make_uint4(ph[0], ph[1], ph[2], ph[3]);
                *(uint4*)(ol + off) = make_uint4(pl[0], pl[1], pl[2], pl[3]);
            }
        }

        asm volatile("cp.async.wait_group 0;" ::: "memory");
        __syncthreads();   // h1 consumed + next scan buffer visible
    }
}

// -------- fc1 combine + fc2 (256->10) + concat -> g_inps + stats accumulate --------
__global__ void __launch_bounds__(256) fc2_concat(
    const float* __restrict__ w2, const float* __restrict__ b2,
    const float* __restrict__ b1,
    const float* __restrict__ obs, const float* __restrict__ acts)
{
    __shared__ float fs[8][10];
    __shared__ float sh_s[64], sh_q[64];
    int warp = threadIdx.x >> 5, lane = threadIdx.x & 31;
    int r = blockIdx.x * 8 + warp;

    if (threadIdx.x < 64) { sh_s[threadIdx.x] = 0.f; sh_q[threadIdx.x] = 0.f; }
    __syncthreads();

    const float* p0 = g_part + (size_t)r * 256;
    const float* p1 = p0 + (size_t)NROW * 256;
    const float* p2 = p1 + (size_t)NROW * 256;
    float x[8];
    #pragma unroll
    for (int i = 0; i < 8; i++) {
        int c = lane + 32 * i;
        x[i] = fmaxf(p0[c] + p1[c] + p2[c] + b1[c], 0.f);
    }

    #pragma unroll
    for (int j = 0; j < 10; j++) {
        float s = 0.f;
        #pragma unroll
        for (int i = 0; i < 8; i++) s += x[i] * w2[j * 256 + lane + 32 * i];
        #pragma unroll
        for (int off = 16; off; off >>= 1) s += __shfl_xor_sync(0xffffffffu, s, off);
        if (lane == 0) fs[warp][j] = s + b2[j];
    }
    __syncwarp();

    float* ir = g_inps + (size_t)r * 60;
    for (int c = lane; c < 60; c += 32) {
        float v;
        if (c < 48)      v = obs[(size_t)r * 48 + c];
        else if (c < 50) v = acts[(size_t)r * 2 + (c - 48)];
        else             v = fs[warp][c - 50];
        ir[c] = v;
        atomicAdd(&sh_s[c], v);
        atomicAdd(&sh_q[c], v * v);
    }
    __syncthreads();
    if (threadIdx.x < 60) {
        atomicAdd(&g_stats[threadIdx.x], sh_s[threadIdx.x]);
        atomicAdd(&g_stats[64 + threadIdx.x], sh_q[threadIdx.x]);
    }
}

__global__ void stats_fin()
{
    int c = threadIdx.x;
    if (c < 60) {
        float mu = g_stats[c] * (1.f / NROW);
        float var = g_stats[64 + c] * (1.f / NROW) - mu * mu;
        g_stats[c] = mu;
        g_stats[64 + c] = rsqrtf(var + 1e-5f);
    }
}

// -------- normalize + encoder(leaky) + keys/vals/q ----------
__global__ void __launch_bounds__(256) enc_kvq(
    const float* __restrict__ enc_w, const float* __restrict__ enc_b,
    const float* __restrict__ Wk, const float* __restrict__ Wv,
    const float* __restrict__ bv, const float* __restrict__ Wq)
{
    __shared__ float xn[32][60];
    __shared__ float sas[32][128];
    __shared__ float wch[32][129];
    __shared__ float mu_s[60], inv_s[60];

    int t = threadIdx.x;
    int row0 = blockIdx.x * 32;
    int g = row0 >> 12;

    if (t < 60) { mu_s[t] = g_stats[t]; inv_s[t] = g_stats[64 + t]; }
    __syncthreads();

    for (int idx = t; idx < 32 * 60; idx += 256) {
        int r = idx / 60, c = idx % 60;
        xn[r][c] = (g_inps[(size_t)(row0 + r) * 60 + c] - mu_s[c]) * inv_s[c];
    }
    __syncthreads();

    int jj = t & 31, rg = t >> 5;

    for (int jc = 0; jc < 4; jc++) {
        for (int idx = t; idx < 32 * 60; idx += 256) {
            int rr = idx / 60, c = idx % 60;
            wch[rr][c] = enc_w[(jc * 32 + rr) * 60 + c];
        }
        __syncthreads();

        float a0 = 0.f, a1 = 0.f, a2 = 0.f, a3 = 0.f;
        #pragma unroll
        for (int c = 0; c < 60; c++) {
            float w = wch[jj][c];
            a0 += xn[rg * 4 + 0][c] * w;
            a1 += xn[rg * 4 + 1][c] * w;
            a2 += xn[rg * 4 + 2][c] * w;
            a3 += xn[rg * 4 + 3][c] * w;
        }
        float bb = enc_b[jc * 32 + jj];
        float v[4] = {a0 + bb, a1 + bb, a2 + bb, a3 + bb};
        int col = jc * 32 + jj;
        #pragma unroll
        for (int q = 0; q < 4; q++) {
            float vv = (v[q] >= 0.f) ? v[q] : 0.01f * v[q];
            sas[rg * 4 + q][col] = vv;
            __nv_bfloat16 hh, ll;
            bsplit(vv, hh, ll);
            size_t idx = (size_t)(row0 + rg * 4 + q) * 256 + col;
            g_embh[idx] = hh;
            g_embl[idx] = ll;
        }
        __syncthreads();
    }

    for (int m = 0; m < 3; m++) {
        const float* W = (m == 0) ? Wk : (m == 1) ? Wv : (Wq + (size_t)g * 128 * 128);
        float* Out     = (m == 0) ? g_keys : (m == 1) ? g_vals : g_q;
        for (int jc = 0; jc < 4; jc++) {
            for (int idx = t; idx < 32 * 128; idx += 256) {
                int rr = idx >> 7, c = idx & 127;
                wch[rr][c] = W[(jc * 32 + rr) * 128 + c];
            }
            __syncthreads();

            float a0 = 0.f, a1 = 0.f, a2 = 0.f, a3 = 0.f;
            #pragma unroll
            for (int c = 0; c < 128; c++) {
                float w = wch[jj][c];
                a0 += sas[rg * 4 + 0][c] * w;
                a1 += sas[rg * 4 + 1][c] * w;
                a2 += sas[rg * 4 + 2][c] * w;
                a3 += sas[rg * 4 + 3][c] * w;
            }
            int col = jc * 32 + jj;
            if (m == 1) {
                float bb = bv[col];
                a0 += bb; a1 += bb; a2 += bb; a3 += bb;
                a0 = (a0 >= 0.f) ? a0 : 0.01f * a0;
                a1 = (a1 >= 0.f) ? a1 : 0.01f * a1;
                a2 = (a2 >= 0.f) ? a2 : 0.01f * a2;
                a3 = (a3 >= 0.f) ? a3 : 0.01f * a3;
            }
            Out[(size_t)(row0 + rg * 4 + 0) * 128 + col] = a0;
            Out[(size_t)(row0 + rg * 4 + 1) * 128 + col] = a1;
            Out[(size_t)(row0 + rg * 4 + 2) * 128 + col] = a2;
            Out[(size_t)(row0 + rg * 4 + 3) * 128 + col] = a3;
            __syncthreads();
        }
    }
}

// ---------------- tiny 3-agent cross-attention ----------------
__global__ void __launch_bounds__(128) attn_kernel()
{
    __shared__ float qs[3][128], ks[3][128], vs[3][128];
    int b = blockIdx.x;
    int t = threadIdx.x;

    #pragma unroll
    for (int g = 0; g < 3; g++) {
        size_t roff = (size_t)(g * BSZ + b) * 128 + t;
        qs[g][t] = g_q[roff];
        ks[g][t] = g_keys[roff];
        vs[g][t] = g_vals[roff];
    }
    __syncthreads();

    const float scale = 0.25f;
    #pragma unroll
    for (int g = 0; g < 3; g++) {
        int o1 = (g == 0) ? 1 : 0;
        int o2 = (g == 2) ? 1 : 2;
        float q = qs[g][t];
        float p1 = q * ks[o1][t];
        float p2 = q * ks[o2][t];
        #pragma unroll
        for (int off = 8; off; off >>= 1) {
            p1 += __shfl_xor_sync(0xffffffffu, p1, off);
            p2 += __shfl_xor_sync(0xffffffffu, p2, off);
        }
        float l1 = p1 * scale, l2 = p2 * scale;
        float mx = fmaxf(l1, l2);
        float e1 = expf(l1 - mx), e2 = expf(l2 - mx);
        float inv = 1.f / (e1 + e2);
        float other = (e1 * vs[o1][t] + e2 * vs[o2][t]) * inv;
        __nv_bfloat16 hh, ll;
        bsplit(other, hh, ll);
        size_t idx = (size_t)(g * BSZ + b) * 256 + 128 + t;
        g_embh[idx] = hh;
        g_embl[idx] = ll;
    }
}

// ---------------- fused final dots (q1 & q2) ----------------
__global__ void __launch_bounds__(256) final_dot2(
    const float* __restrict__ w3a, const float* __restrict__ b3a,
    const float* __restrict__ w3b, const float* __restrict__ b3b,
    float* __restrict__ out)
{
    int warp = threadIdx.x >> 5, lane = threadIdx.x & 31;
    int r = blockIdx.x * 8 + warp;
    const float* xr = g_m2 + (size_t)r * 512;
    float s1 = 0.f, s2 = 0.f;
    #pragma unroll
    for (int i = 0; i < 8; i++) {
        int c = lane + 32 * i;
        s1 += xr[c] * w3a[c];
        s2 += xr[256 + c] * w3b[c];
    }
    #pragma unroll
    for (int off = 16; off; off >>= 1) {
        s1 += __shfl_xor_sync(0xffffffffu, s1, off);
        s2 += __shfl_xor_sync(0xffffffffu, s2, off);
    }
    if (lane == 0) {
        out[r] = s1 + b3a[0];
        out[NROW + r] = s2 + b3b[0];
    }
}

// ---------------- launch ----------------
extern "C" void kernel_launch(void* const* d_in, const int* in_sizes, int n_in,
                              void* d_out, int out_size)
{
    const float* obs     = (const float*)d_in[0];
    const float* acts    = (const float*)d_in[1];
    const float* scan    = (const float*)d_in[2];
    const float* conv_w1 = (const float*)d_in[3];
    const float* conv_b1 = (const float*)d_in[4];
    const float* conv_w2 = (const float*)d_in[5];
    const float* conv_b2 = (const float*)d_in[6];
    const float* fc_w1   = (const float*)d_in[7];
    const float* fc_b1   = (const float*)d_in[8];
    const float* fc_w2   = (const float*)d_in[9];
    const float* fc_b2   = (const float*)d_in[10];
    const float* enc_w   = (const float*)d_in[11];
    const float* enc_b   = (const float*)d_in[12];
    const float* Wk      = (const float*)d_in[13];
    const float* Wv      = (const float*)d_in[14];
    const float* bv      = (const float*)d_in[15];
    const float* Wq      = (const float*)d_in[16];
    const float* q1_w1   = (const float*)d_in[17];
    const float* q1_b1   = (const float*)d_in[18];
    const float* q1_w2   = (const float*)d_in[19];
    const float* q1_b2   = (const float*)d_in[20];
    const float* q1_w3   = (const float*)d_in[21];
    const float* q1_b3   = (const float*)d_in[22];
    const float* q2_w1   = (const float*)d_in[23];
    const float* q2_b1   = (const float*)d_in[24];
    const float* q2_w2   = (const float*)d_in[25];
    const float* q2_b2   = (const float*)d_in[26];
    const float* q2_w3   = (const float*)d_in[27];
    const float* q2_b3   = (const float*)d_in[28];
    float* out = (float*)d_out;

    cudaFuncSetAttribute(fc1_gemm, cudaFuncAttributeMaxDynamicSharedMemorySize, FSMEM);
    cudaFuncSetAttribute(mlp_gemm<1>, cudaFuncAttributeMaxDynamicSharedMemorySize, GSMEM);
    cudaFuncSetAttribute(mlp_gemm<2>, cudaFuncAttributeMaxDynamicSharedMemorySize, GSMEM);
    cudaFuncSetAttribute(conv_kernel, cudaFuncAttributeMaxDynamicSharedMemorySize, CV_SMEM);

    // weight splits (wsplit_cv also zeroes g_stats accumulators)
    wsplit_cv<<<12, 256>>>(conv_w2);
    wsplit0<<<KPAD, 256>>>(fc_w1);
    wsplit4<<<1024, 256>>>(q1_w1, q2_w1, q1_w2, q2_w2);

    conv_kernel<<<444, 256, CV_SMEM>>>(scan, conv_w1, conv_b1, conv_b2);
    fc1_gemm<<<dim3(2, 96, 3), 256, FSMEM>>>();
    fc2_concat<<<NROW / 8, 256>>>(fc_w2, fc_b2, fc_b1, obs, acts);
    stats_fin<<<1, 64>>>();
    enc_kvq<<<NROW / 32, 256>>>(enc_w, enc_b, Wk, Wv, bv, Wq);
    attn_kernel<<<BSZ, 128>>>();

    mlp_gemm<1><<<dim3(4, 192), 256, GSMEM>>>(q1_b1, q2_b1);
    mlp_gemm<2><<<dim3(2, 192, 2), 256, GSMEM>>>(q1_b2, q2_b2);
    final_dot2<<<NROW / 8, 256>>>(q1_w3, q1_b3, q2_w3, q2_b3, out);
}

// round 11
// speedup vs baseline: 5.2404x; 1.0925x over previous
#include <cuda_runtime.h>
#include <cuda_bf16.h>
#include <math.h>
#include <cstdint>

#define NROW 12288
#define BSZ  4096
#define KPAD 8192

// ---------------- scratch (device globals; no allocations) ----------------
__device__ __nv_bfloat16 g_ah[(size_t)NROW * KPAD];  // conv output hi (permuted K)
__device__ __nv_bfloat16 g_al[(size_t)NROW * KPAD];  // conv output lo
__device__ __nv_bfloat16 g_fwh[256 * KPAD];          // fc_w1 hi (same permutation)
__device__ __nv_bfloat16 g_fwl[256 * KPAD];          // fc_w1 lo
__device__ __nv_bfloat16 g_qwh[4 * 256 * 256];       // q1_w1,q2_w1,q1_w2,q2_w2 hi
__device__ __nv_bfloat16 g_qwl[4 * 256 * 256];       // lo
__device__ __nv_bfloat16 g_kvh[3 * 384 * 128];       // per-agent [Wk;Wv;Wq_g] hi
__device__ __nv_bfloat16 g_kvl[3 * 384 * 128];       // lo
__device__ __nv_bfloat16 g_cw2h[32 * 104];           // conv w2 pre-split (smem layout)
__device__ __nv_bfloat16 g_cw2l[32 * 104];
__device__ float g_part[3 * (size_t)NROW * 256];     // fc1 K-split partials
__device__ float g_inps[NROW * 60];
__device__ float g_stats[128];
__device__ __nv_bfloat16 g_embh[NROW * 256];
__device__ __nv_bfloat16 g_embl[NROW * 256];
__device__ __nv_bfloat16 g_mh[(size_t)NROW * 512];
__device__ __nv_bfloat16 g_ml[(size_t)NROW * 512];
__device__ float g_keys[NROW * 128];
__device__ float g_vals[NROW * 128];
__device__ float g_q[NROW * 128];

// ====================== helpers ======================
__device__ __forceinline__ uint32_t smem_u32(const void* p) {
    uint32_t a;
    asm("{ .reg .u64 t; cvta.to.shared.u64 t, %1; cvt.u32.u64 %0, t; }"
        : "=r"(a) : "l"(p));
    return a;
}
__device__ __forceinline__ void bsplit(float v, __nv_bfloat16& h, __nv_bfloat16& l) {
    h = __float2bfloat16(v);
    l = __float2bfloat16(v - __bfloat162float(h));
}
#define CPA16(s, g) \
    asm volatile("cp.async.cg.shared.global [%0], [%1], 16;" :: "r"(s), "l"(g))
#define CPC() asm volatile("cp.async.commit_group;" ::: "memory")
#define LDSM4(r0, r1, r2, r3, a) \
    asm volatile("ldmatrix.sync.aligned.m8n8.x4.shared.b16 {%0,%1,%2,%3}, [%4];" \
                 : "=r"(r0), "=r"(r1), "=r"(r2), "=r"(r3) : "r"(a))
#define MMA16816(d, a, b) \
    asm volatile("mma.sync.aligned.m16n8k16.row.col.f32.bf16.bf16.f32 " \
                 "{%0,%1,%2,%3},{%4,%5,%6,%7},{%8,%9},{%0,%1,%2,%3};" \
                 : "+f"((d)[0]), "+f"((d)[1]), "+f"((d)[2]), "+f"((d)[3]) \
                 : "r"((a)[0]), "r"((a)[1]), "r"((a)[2]), "r"((a)[3]), \
                   "r"((b)[0]), "r"((b)[1]))

// ================= fc1: bf16x3 GEMM, BM128/BN128/BK32, 3-stage, K-split =========
#define FSMEM (3 * 32768)
__global__ void __launch_bounds__(256, 2) fc1_gemm()
{
    extern __shared__ char smem[];
    const uint32_t sb = smem_u32(smem);

    const int t = threadIdx.x, lane = t & 31, wid = t >> 5;
    const int bn = blockIdx.x, bm = blockIdx.y, z = blockIdx.z;
    const int kt0 = (z == 0) ? 0 : (z == 1) ? 86 : 171;
    const int T   = (z == 0) ? 86 : 85;
    const int row0 = bm * 128, col0 = bn * 128;

    const int fr = t >> 1;
    const int c0 = (t & 1) * 2;
    const __nv_bfloat16* gAh = g_ah + (size_t)(row0 + fr) * KPAD + kt0 * 32;
    const __nv_bfloat16* gAl = g_al + (size_t)(row0 + fr) * KPAD + kt0 * 32;
    const __nv_bfloat16* gBh = g_fwh + (size_t)(col0 + fr) * KPAD + kt0 * 32;
    const __nv_bfloat16* gBl = g_fwl + (size_t)(col0 + fr) * KPAD + kt0 * 32;
    const int fsw = (fr >> 1) & 3;

    const int mw = wid & 1, nw = wid >> 1;

    float acc[4][4][4];
    #pragma unroll
    for (int a = 0; a < 4; a++)
        #pragma unroll
        for (int b = 0; b < 4; b++)
            #pragma unroll
            for (int c = 0; c < 4; c++) acc[a][b][c] = 0.f;

    auto fill = [&](int tt, int s) {
        uint32_t base = sb + s * 32768;
        const __nv_bfloat16* pAh = gAh + (size_t)tt * 32;
        const __nv_bfloat16* pAl = gAl + (size_t)tt * 32;
        const __nv_bfloat16* pBh = gBh + (size_t)tt * 32;
        const __nv_bfloat16* pBl = gBl + (size_t)tt * 32;
        #pragma unroll
        for (int j = 0; j < 2; j++) {
            int c = c0 + j;
            uint32_t off = fr * 64 + ((c ^ fsw) << 4);
            CPA16(base + off,         pAh + c * 8);
            CPA16(base + 8192 + off,  pAl + c * 8);
            CPA16(base + 16384 + off, pBh + c * 8);
            CPA16(base + 24576 + off, pBl + c * 8);
        }
    };

    fill(0, 0); CPC();
    fill(1, 1); CPC();

    for (int tt = 0; tt < T; tt++) {
        asm volatile("cp.async.wait_group 1;" ::: "memory");
        __syncthreads();

        const uint32_t stu = sb + (tt % 3) * 32768;
        #pragma unroll
        for (int ks = 0; ks < 2; ks++) {
            uint32_t bhf[2][4], blf[2][4];
            #pragma unroll
            for (int nt = 0; nt < 2; nt++) {
                int nr = nw * 32 + nt * 16 + (lane & 7) + ((lane >> 4) << 3);
                int cs = (ks * 2 + ((lane >> 3) & 1)) ^ ((nr >> 1) & 3);
                uint32_t ba = stu + 16384 + nr * 64 + cs * 16;
                LDSM4(bhf[nt][0], bhf[nt][1], bhf[nt][2], bhf[nt][3], ba);
                LDSM4(blf[nt][0], blf[nt][1], blf[nt][2], blf[nt][3], ba + 8192);
            }
            #pragma unroll
            for (int mi = 0; mi < 4; mi++) {
                int r = mw * 64 + mi * 16 + (lane & 15);
                int cs = (ks * 2 + (lane >> 4)) ^ ((r >> 1) & 3);
                uint32_t aa = stu + r * 64 + cs * 16;
                uint32_t ah[4], al[4];
                LDSM4(ah[0], ah[1], ah[2], ah[3], aa);
                LDSM4(al[0], al[1], al[2], al[3], aa + 8192);
                #pragma unroll
                for (int nj = 0; nj < 4; nj++) {
                    int nt = nj >> 1, hf = (nj & 1) * 2;
                    MMA16816(acc[mi][nj], ah, &bhf[nt][hf]);
                    MMA16816(acc[mi][nj], ah, &blf[nt][hf]);
                    MMA16816(acc[mi][nj], al, &bhf[nt][hf]);
                }
            }
        }

        if (tt + 2 < T) fill(tt + 2, (tt + 2) % 3);
        CPC();
    }

    float* P = g_part + (size_t)z * NROW * 256;
    #pragma unroll
    for (int mi = 0; mi < 4; mi++) {
        #pragma unroll
        for (int nj = 0; nj < 4; nj++) {
            int col = col0 + nw * 32 + nj * 8 + (lane & 3) * 2;
            #pragma unroll
            for (int h = 0; h < 2; h++) {
                int row = row0 + mw * 64 + mi * 16 + (lane >> 2) + h * 8;
                *(float2*)(P + (size_t)row * 256 + col) =
                    make_float2(acc[mi][nj][h * 2], acc[mi][nj][h * 2 + 1]);
            }
        }
    }
}

// ============ MLP GEMM: BM64/BN128/BK32, 3-stage, warp tile 32x32, bf16x3 ========
// LAYER 1: A=emb(256), B=q1_w1|q2_w1 (512 rows), out split -> g_mh/g_ml[512]
// LAYER 2: z: A=g_mh+z*256 (stride 512), B slot 2+z; epilogue computes partial
//          final dot (relu(x)·w3) and atomicAdds into out[z*NROW + row].
#define GSMEM1 (3 * 24576)
#define GSMEM2 (3 * 24576 + 1024)
template <int LAYER>
__global__ void __launch_bounds__(256, 2) mlp_gemm(
    const float* __restrict__ biasA, const float* __restrict__ biasB,
    const float* __restrict__ w3a, const float* __restrict__ w3b,
    float* __restrict__ out)
{
    const int z = (LAYER == 2) ? blockIdx.z : 0;
    const __nv_bfloat16* Ah = (LAYER == 1) ? g_embh : g_mh + z * 256;
    const __nv_bfloat16* Al = (LAYER == 1) ? g_embl : g_ml + z * 256;
    const int AS = (LAYER == 1) ? 256 : 512;
    const __nv_bfloat16* Bh = (LAYER == 1) ? g_qwh : g_qwh + (2 + z) * 65536;
    const __nv_bfloat16* Bl = (LAYER == 1) ? g_qwl : g_qwl + (2 + z) * 65536;

    extern __shared__ char smem[];
    const uint32_t sb = smem_u32(smem);
    float* w3s = (float*)(smem + 73728);

    const int t = threadIdx.x, lane = t & 31, wid = t >> 5;
    const int row0 = blockIdx.y * 64, col0 = blockIdx.x * 128;

    if (LAYER == 2) {
        if (t < 256) w3s[t] = (z ? w3b : w3a)[t];
    }

    const int ar = t >> 2, ac = t & 3;
    const int br = t >> 1, bc0 = (t & 1) * 2;
    const __nv_bfloat16* gAh = Ah + (size_t)(row0 + ar) * AS + ac * 8;
    const __nv_bfloat16* gAl = Al + (size_t)(row0 + ar) * AS + ac * 8;
    const __nv_bfloat16* gBh = Bh + (size_t)(col0 + br) * 256;
    const __nv_bfloat16* gBl = Bl + (size_t)(col0 + br) * 256;
    const uint32_t aoff = ar * 64 + ((ac ^ ((ar >> 1) & 3)) << 4);
    const int bsw = (br >> 1) & 3;

    const int mw = wid & 1, nw = wid >> 1;

    float acc[2][4][4];
    #pragma unroll
    for (int a = 0; a < 2; a++)
        #pragma unroll
        for (int b = 0; b < 4; b++)
            #pragma unroll
            for (int c = 0; c < 4; c++) acc[a][b][c] = 0.f;

    auto fill = [&](int tt, int s) {
        uint32_t base = sb + s * 24576;
        CPA16(base + aoff,        gAh + tt * 32);
        CPA16(base + 4096 + aoff, gAl + tt * 32);
        #pragma unroll
        for (int j = 0; j < 2; j++) {
            int c = bc0 + j;
            uint32_t boff = br * 64 + ((c ^ bsw) << 4);
            CPA16(base + 8192 + boff,  gBh + tt * 32 + c * 8);
            CPA16(base + 16384 + boff, gBl + tt * 32 + c * 8);
        }
    };

    fill(0, 0); CPC();
    fill(1, 1); CPC();

    const int T = 8;
    for (int tt = 0; tt < T; tt++) {
        asm volatile("cp.async.wait_group 1;" ::: "memory");
        __syncthreads();

        const uint32_t stu = sb + (tt % 3) * 24576;
        #pragma unroll
        for (int ks = 0; ks < 2; ks++) {
            uint32_t bhf[2][4], blf[2][4];
            #pragma unroll
            for (int nt = 0; nt < 2; nt++) {
                int nr = nw * 32 + nt * 16 + (lane & 7) + ((lane >> 4) << 3);
                int cs = (ks * 2 + ((lane >> 3) & 1)) ^ ((nr >> 1) & 3);
                uint32_t ba = stu + 8192 + nr * 64 + cs * 16;
                LDSM4(bhf[nt][0], bhf[nt][1], bhf[nt][2], bhf[nt][3], ba);
                LDSM4(blf[nt][0], blf[nt][1], blf[nt][2], blf[nt][3], ba + 8192);
            }
            #pragma unroll
            for (int mi = 0; mi < 2; mi++) {
                int r = mw * 32 + mi * 16 + (lane & 15);
                int cs = (ks * 2 + (lane >> 4)) ^ ((r >> 1) & 3);
                uint32_t aa = stu + r * 64 + cs * 16;
                uint32_t ah[4], al[4];
                LDSM4(ah[0], ah[1], ah[2], ah[3], aa);
                LDSM4(al[0], al[1], al[2], al[3], aa + 4096);
                #pragma unroll
                for (int nj = 0; nj < 4; nj++) {
                    int nt = nj >> 1, hf = (nj & 1) * 2;
                    MMA16816(acc[mi][nj], ah, &bhf[nt][hf]);
                    MMA16816(acc[mi][nj], ah, &blf[nt][hf]);
                    MMA16816(acc[mi][nj], al, &bhf[nt][hf]);
                }
            }
        }

        if (tt + 2 < T) fill(tt + 2, (tt + 2) % 3);
        CPC();
    }

    if (LAYER == 1) {
        #pragma unroll
        for (int mi = 0; mi < 2; mi++) {
            #pragma unroll
            for (int nj = 0; nj < 4; nj++) {
                int ocl = col0 + nw * 32 + nj * 8 + (lane & 3) * 2;
                float b0 = (ocl < 256) ? biasA[ocl] : biasB[ocl - 256];
                float b1 = (ocl + 1 < 256) ? biasA[ocl + 1] : biasB[ocl + 1 - 256];
                #pragma unroll
                for (int h = 0; h < 2; h++) {
                    int row = row0 + mw * 32 + mi * 16 + (lane >> 2) + h * 8;
                    float v0 = fmaxf(acc[mi][nj][h * 2 + 0] + b0, 0.f);
                    float v1 = fmaxf(acc[mi][nj][h * 2 + 1] + b1, 0.f);
                    size_t idx = (size_t)row * 512 + ocl;
                    __nv_bfloat16 h0, l0, h1, l1;
                    bsplit(v0, h0, l0);
                    bsplit(v1, h1, l1);
                    *(__nv_bfloat162*)(g_mh + idx) = __halves2bfloat162(h0, h1);
                    *(__nv_bfloat162*)(g_ml + idx) = __halves2bfloat162(l0, l1);
                }
            }
        }
    } else {
        const float* bb = z ? biasB : biasA;
        #pragma unroll
        for (int mi = 0; mi < 2; mi++) {
            #pragma unroll
            for (int h = 0; h < 2; h++) {
                int row = row0 + mw * 32 + mi * 16 + (lane >> 2) + h * 8;
                float s = 0.f;
                #pragma unroll
                for (int nj = 0; nj < 4; nj++) {
                    int ocl = col0 + nw * 32 + nj * 8 + (lane & 3) * 2;
                    float v0 = fmaxf(acc[mi][nj][h * 2 + 0] + bb[ocl], 0.f);
                    float v1 = fmaxf(acc[mi][nj][h * 2 + 1] + bb[ocl + 1], 0.f);
                    s += v0 * w3s[ocl] + v1 * w3s[ocl + 1];
                }
                s += __shfl_xor_sync(0xffffffffu, s, 1);
                s += __shfl_xor_sync(0xffffffffu, s, 2);
                if ((lane & 3) == 0) atomicAdd(&out[z * NROW + row], s);
            }
        }
    }
}

// ========= kvq_gemm: keys/vals/q via bf16x3, BM64/BN128/BK32, K=128 =========
// grid (3 colblocks = k/v/q, 64 row-tiles, 3 agents). A = emb split (sa half).
__global__ void __launch_bounds__(256, 2) kvq_gemm(const float* __restrict__ bv)
{
    const int m = blockIdx.x;                 // 0=keys 1=vals 2=q
    const int g = blockIdx.z;
    const int row0 = g * 4096 + blockIdx.y * 64;
    const int col0 = m * 128;

    extern __shared__ char smem[];
    const uint32_t sb = smem_u32(smem);

    const int t = threadIdx.x, lane = t & 31, wid = t >> 5;

    const int ar = t >> 2, ac = t & 3;
    const int br = t >> 1, bc0 = (t & 1) * 2;
    const __nv_bfloat16* gAh = g_embh + (size_t)(row0 + ar) * 256 + ac * 8;
    const __nv_bfloat16* gAl = g_embl + (size_t)(row0 + ar) * 256 + ac * 8;
    const __nv_bfloat16* gBh = g_kvh + (size_t)g * 49152 + (size_t)(col0 + br) * 128;
    const __nv_bfloat16* gBl = g_kvl + (size_t)g * 49152 + (size_t)(col0 + br) * 128;
    const uint32_t aoff = ar * 64 + ((ac ^ ((ar >> 1) & 3)) << 4);
    const int bsw = (br >> 1) & 3;

    const int mw = wid & 1, nw = wid >> 1;

    float acc[2][4][4];
    #pragma unroll
    for (int a = 0; a < 2; a++)
        #pragma unroll
        for (int b = 0; b < 4; b++)
            #pragma unroll
            for (int c = 0; c < 4; c++) acc[a][b][c] = 0.f;

    auto fill = [&](int tt, int s) {
        uint32_t base = sb + s * 24576;
        CPA16(base + aoff,        gAh + tt * 32);
        CPA16(base + 4096 + aoff, gAl + tt * 32);
        #pragma unroll
        for (int j = 0; j < 2; j++) {
            int c = bc0 + j;
            uint32_t boff = br * 64 + ((c ^ bsw) << 4);
            CPA16(base + 8192 + boff,  gBh + tt * 32 + c * 8);
            CPA16(base + 16384 + boff, gBl + tt * 32 + c * 8);
        }
    };

    fill(0, 0); CPC();
    fill(1, 1); CPC();

    const int T = 4;
    for (int tt = 0; tt < T; tt++) {
        if (tt == T - 1)
            asm volatile("cp.async.wait_group 0;" ::: "memory");
        else
            asm volatile("cp.async.wait_group 1;" ::: "memory");
        __syncthreads();

        const uint32_t stu = sb + (tt % 3) * 24576;
        #pragma unroll
        for (int ks = 0; ks < 2; ks++) {
            uint32_t bhf[2][4], blf[2][4];
            #pragma unroll
            for (int nt = 0; nt < 2; nt++) {
                int nr = nw * 32 + nt * 16 + (lane & 7) + ((lane >> 4) << 3);
                int cs = (ks * 2 + ((lane >> 3) & 1)) ^ ((nr >> 1) & 3);
                uint32_t ba = stu + 8192 + nr * 64 + cs * 16;
                LDSM4(bhf[nt][0], bhf[nt][1], bhf[nt][2], bhf[nt][3], ba);
                LDSM4(blf[nt][0], blf[nt][1], blf[nt][2], blf[nt][3], ba + 8192);
            }
            #pragma unroll
            for (int mi = 0; mi < 2; mi++) {
                int r = mw * 32 + mi * 16 + (lane & 15);
                int cs = (ks * 2 + (lane >> 4)) ^ ((r >> 1) & 3);
                uint32_t aa = stu + r * 64 + cs * 16;
                uint32_t ah[4], al[4];
                LDSM4(ah[0], ah[1], ah[2], ah[3], aa);
                LDSM4(al[0], al[1], al[2], al[3], aa + 4096);
                #pragma unroll
                for (int nj = 0; nj < 4; nj++) {
                    int nt = nj >> 1, hf = (nj & 1) * 2;
                    MMA16816(acc[mi][nj], ah, &bhf[nt][hf]);
                    MMA16816(acc[mi][nj], ah, &blf[nt][hf]);
                    MMA16816(acc[mi][nj], al, &bhf[nt][hf]);
                }
            }
        }

        if (tt + 2 < T) fill(tt + 2, (tt + 2) % 3);
        CPC();
    }

    float* Out = (m == 0) ? g_keys : (m == 1) ? g_vals : g_q;
    #pragma unroll
    for (int mi = 0; mi < 2; mi++) {
        #pragma unroll
        for (int nj = 0; nj < 4; nj++) {
            int col = nw * 32 + nj * 8 + (lane & 3) * 2;
            float b0 = 0.f, b1 = 0.f;
            if (m == 1) { b0 = bv[col]; b1 = bv[col + 1]; }
            #pragma unroll
            for (int h = 0; h < 2; h++) {
                int row = row0 + mw * 32 + mi * 16 + (lane >> 2) + h * 8;
                float v0 = acc[mi][nj][h * 2 + 0] + b0;
                float v1 = acc[mi][nj][h * 2 + 1] + b1;
                if (m == 1) {
                    v0 = (v0 >= 0.f) ? v0 : 0.01f * v0;
                    v1 = (v1 >= 0.f) ? v1 : 0.01f * v1;
                }
                *(float2*)(Out + (size_t)row * 128 + col) = make_float2(v0, v1);
            }
        }
    }
}

// ---------------- combined weight prep / init kernel ----------------
__global__ void wsplit_all(
    const float* __restrict__ fw,
    const float* __restrict__ qa, const float* __restrict__ qb,
    const float* __restrict__ qc, const float* __restrict__ qd,
    const float* __restrict__ cw2,
    const float* __restrict__ Wk, const float* __restrict__ Wv,
    const float* __restrict__ Wq,
    const float* __restrict__ b3a, const float* __restrict__ b3b,
    float* __restrict__ out)
{
    const int bx = blockIdx.x, t = threadIdx.x;
    if (bx < 8192) {
        // fc_w1 split WITH conv epilogue K-permutation; pos>=250 -> 0
        int i = bx * 256 + t;
        int r  = i >> 13;
        int kp = i & (KPAD - 1);
        int wq  = kp >> 10;
        int rem = kp & 1023;
        int mi = rem >> 9;
        int c  = (rem >> 8) & 1;
        int l  = (rem >> 3) & 31;
        int e  = rem & 7;
        int idx = e & 3;
        int nj  = c * 2 + (e >> 2);
        int oc  = mi * 16 + (l >> 2) + (idx >> 1) * 8;
        int pos = wq * 32 + nj * 8 + (l & 3) * 2 + (e & 1);
        float v = (pos < 250) ? fw[r * 8000 + oc * 250 + pos] : 0.f;
        __nv_bfloat16 hh, ll;
        bsplit(v, hh, ll);
        g_fwh[i] = hh;
        g_fwl[i] = ll;
    } else if (bx < 9216) {
        int i = (bx - 8192) * 256 + t;
        int which = i >> 16, j = i & 65535;
        const float* src = (which == 0) ? qa : (which == 1) ? qb : (which == 2) ? qc : qd;
        __nv_bfloat16 hh, ll;
        bsplit(src[j], hh, ll);
        g_qwh[i] = hh;
        g_qwl[i] = ll;
    } else if (bx < 9792) {
        int j = (bx - 9216) * 256 + t;      // < 147456
        int g = j / 49152, rem = j % 49152;
        int rowj = rem >> 7, k = rem & 127;
        float v = (rowj < 128) ? Wk[rowj * 128 + k]
                : (rowj < 256) ? Wv[(rowj - 128) * 128 + k]
                : Wq[g * 16384 + (rowj - 256) * 128 + k];
        __nv_bfloat16 hh, ll;
        bsplit(v, hh, ll);
        g_kvh[j] = hh;
        g_kvl[j] = ll;
    } else if (bx < 9804) {
        int idx = (bx - 9792) * 256 + t;
        if (idx < 3072) {
            int oc = idx / 96, rem = idx % 96;
            int ic = rem / 3, tap = rem % 3;
            __nv_bfloat16 hh, ll;
            bsplit(cw2[idx], hh, ll);
            int o = oc * 104 + tap * 32 + ic;
            g_cw2h[o] = hh;
            g_cw2l[o] = ll;
        }
    } else if (bx < 9900) {
        int r = (bx - 9804) * 256 + t;      // < 24576
        out[r] = (r < NROW) ? b3a[0] : b3b[0];
    } else {
        if (t < 128) g_stats[t] = 0.f;
    }
}

// ====== persistent fused conv1(SIMT) + conv2(bf16x3 MMA), permuted-K out ======
#define CV_SMEM 57984
#define CV_SCAN 0          // 2 x 1024B double buffer
#define CV_W1   2048
#define CV_B1   2688
#define CV_B2   2816
#define CV_H1H  3072
#define CV_H1L  23872
#define CV_W2H  44672
#define CV_W2L  51328

__global__ void __launch_bounds__(256, 3) conv_kernel(
    const float* __restrict__ scan,
    const float* __restrict__ w1, const float* __restrict__ b1,
    const float* __restrict__ b2)
{
    extern __shared__ char smem[];
    const uint32_t sb = smem_u32(smem);
    float* s_w1   = (float*)(smem + CV_W1);
    float* s_b1   = (float*)(smem + CV_B1);
    float* s_b2   = (float*)(smem + CV_B2);
    __nv_bfloat16* s_h1h = (__nv_bfloat16*)(smem + CV_H1H);
    __nv_bfloat16* s_h1l = (__nv_bfloat16*)(smem + CV_H1L);

    const int t = threadIdx.x, lane = t & 31, wid = t >> 5;
    const int b = blockIdx.x;
    const int nrows = (b < 300) ? 28 : 27;
    const int start = b * 27 + min(b, 300);

    for (int i = t; i < 416; i += 256) {
        CPA16(sb + CV_W2H + i * 16, (const char*)g_cw2h + i * 16);
        CPA16(sb + CV_W2L + i * 16, (const char*)g_cw2l + i * 16);
    }
    if (t < 64)
        CPA16(sb + CV_SCAN + t * 16, (const char*)(scan + (size_t)start * 256) + t * 16);
    CPC();
    if (t < 160) s_w1[t] = w1[t];
    if (t < 32) { s_b1[t] = b1[t]; s_b2[t] = b2[t]; }
    asm volatile("cp.async.wait_group 0;" ::: "memory");
    __syncthreads();

    const int ic = lane;
    const int pbase = wid * 32;
    float wv[5];
    #pragma unroll
    for (int k = 0; k < 5; k++) wv[k] = s_w1[ic * 5 + k];
    const float c1b = s_b1[ic];

    const int n0 = wid * 32;
    const int lr = lane & 15;
    const int kh = lane >> 4;
    const int browl = (lane & 7) + ((lane >> 4) << 3);
    const int bko = (lane >> 3) & 1;
    const float eb_lo0 = s_b2[(lane >> 2)];
    const float eb_hi0 = s_b2[(lane >> 2) + 8];
    const float eb_lo1 = s_b2[16 + (lane >> 2)];
    const float eb_hi1 = s_b2[16 + (lane >> 2) + 8];

    for (int i = 0; i < nrows; i++) {
        const int row = start + i;
        const float* sc = (const float*)(smem + CV_SCAN + (i & 1) * 1024);

        if (i + 1 < nrows && t < 64)
            CPA16(sb + CV_SCAN + ((i + 1) & 1) * 1024 + t * 16,
                  (const char*)(scan + (size_t)(row + 1) * 256) + t * 16);
        CPC();

        {
            float win[5];
            #pragma unroll
            for (int k = 0; k < 4; k++) win[k] = sc[pbase + k];
            #pragma unroll
            for (int q = 0; q < 32; q++) {
                int p = pbase + q;
                win[4] = sc[(p + 4) & 255];
                float a = c1b + wv[0] * win[0] + wv[1] * win[1] + wv[2] * win[2]
                              + wv[3] * win[3] + wv[4] * win[4];
                a = fmaxf(a, 0.f);
                if (p >= 252) a = 0.f;
                __nv_bfloat16 hh, ll;
                bsplit(a, hh, ll);
                s_h1h[p * 40 + ic] = hh;
                s_h1l[p * 40 + ic] = ll;
                win[0] = win[1]; win[1] = win[2]; win[2] = win[3]; win[3] = win[4];
            }
        }
        if (t < 128) {
            int p = 256 + (t >> 5), icc = t & 31;
            s_h1h[p * 40 + icc] = __float2bfloat16(0.f);
            s_h1l[p * 40 + icc] = __float2bfloat16(0.f);
        }
        __syncthreads();

        float acc[2][4][4];
        #pragma unroll
        for (int a = 0; a < 2; a++)
            #pragma unroll
            for (int bq = 0; bq < 4; bq++)
                #pragma unroll
                for (int c = 0; c < 4; c++) acc[a][bq][c] = 0.f;

        #pragma unroll
        for (int ks = 0; ks < 6; ks++) {
            int tap = ks >> 1;
            int ic16 = (ks & 1) * 32;

            uint32_t awh[2][4], awl[2][4];
            #pragma unroll
            for (int mi = 0; mi < 2; mi++) {
                uint32_t a = sb + CV_W2H + (mi * 16 + lr) * 208 + ks * 32 + kh * 16;
                LDSM4(awh[mi][0], awh[mi][1], awh[mi][2], awh[mi][3], a);
                LDSM4(awl[mi][0], awl[mi][1], awl[mi][2], awl[mi][3], a + 6656);
            }
            uint32_t bh[2][4], bl[2][4];
            #pragma unroll
            for (int nt = 0; nt < 2; nt++) {
                int nrow = n0 + nt * 16 + browl + tap;
                uint32_t bb = sb + CV_H1H + nrow * 80 + ic16 + bko * 16;
                LDSM4(bh[nt][0], bh[nt][1], bh[nt][2], bh[nt][3], bb);
                LDSM4(bl[nt][0], bl[nt][1], bl[nt][2], bl[nt][3], bb + 20800);
            }
            #pragma unroll
            for (int mi = 0; mi < 2; mi++) {
                #pragma unroll
                for (int nj = 0; nj < 4; nj++) {
                    int nt = nj >> 1, hf = (nj & 1) * 2;
                    MMA16816(acc[mi][nj], awh[mi], &bh[nt][hf]);
                    MMA16816(acc[mi][nj], awh[mi], &bl[nt][hf]);
                    MMA16816(acc[mi][nj], awl[mi], &bh[nt][hf]);
                }
            }
        }

        __nv_bfloat16* oh = g_ah + (size_t)row * KPAD;
        __nv_bfloat16* ol = g_al + (size_t)row * KPAD;
        #pragma unroll
        for (int mi = 0; mi < 2; mi++) {
            float b_lo = mi ? eb_lo1 : eb_lo0;
            float b_hi = mi ? eb_hi1 : eb_hi0;
            #pragma unroll
            for (int c = 0; c < 2; c++) {
                uint32_t ph[4], pl[4];
                #pragma unroll
                for (int u = 0; u < 4; u++) {
                    int nj = c * 2 + (u >> 1);
                    int idx0 = (u & 1) * 2;
                    float bb = (u & 1) ? b_hi : b_lo;
                    float v0 = fmaxf(acc[mi][nj][idx0 + 0] + bb, 0.f);
                    float v1 = fmaxf(acc[mi][nj][idx0 + 1] + bb, 0.f);
                    __nv_bfloat16 h0, l0, h1, l1;
                    bsplit(v0, h0, l0);
                    bsplit(v1, h1, l1);
                    __nv_bfloat162 hh = __halves2bfloat162(h0, h1);
                    __nv_bfloat162 ll = __halves2bfloat162(l0, l1);
                    ph[u] = *(uint32_t*)&hh;
                    pl[u] = *(uint32_t*)&ll;
                }
                size_t off = (size_t)wid * 1024 + mi * 512 + c * 256 + lane * 8;
                *(uint4*)(oh + off) = make_uint4(ph[0], ph[1], ph[2], ph[3]);
                *(uint4*)(ol + off) = make_uint4(pl[0], pl[1], pl[2], pl[3]);
            }
        }

        asm volatile("cp.async.wait_group 0;" ::: "memory");
        __syncthreads();
    }
}

// -------- fc1 combine + fc2 (256->10) + concat -> g_inps + stats accumulate --------
__global__ void __launch_bounds__(256) fc2_concat(
    const float* __restrict__ w2, const float* __restrict__ b2,
    const float* __restrict__ b1,
    const float* __restrict__ obs, const float* __restrict__ acts)
{
    __shared__ float fs[8][10];
    __shared__ float sh_s[64], sh_q[64];
    int warp = threadIdx.x >> 5, lane = threadIdx.x & 31;
    int r = blockIdx.x * 8 + warp;

    if (threadIdx.x < 64) { sh_s[threadIdx.x] = 0.f; sh_q[threadIdx.x] = 0.f; }
    __syncthreads();

    const float* p0 = g_part + (size_t)r * 256;
    const float* p1 = p0 + (size_t)NROW * 256;
    const float* p2 = p1 + (size_t)NROW * 256;
    float x[8];
    #pragma unroll
    for (int i = 0; i < 8; i++) {
        int c = lane + 32 * i;
        x[i] = fmaxf(p0[c] + p1[c] + p2[c] + b1[c], 0.f);
    }

    #pragma unroll
    for (int j = 0; j < 10; j++) {
        float s = 0.f;
        #pragma unroll
        for (int i = 0; i < 8; i++) s += x[i] * w2[j * 256 + lane + 32 * i];
        #pragma unroll
        for (int off = 16; off; off >>= 1) s += __shfl_xor_sync(0xffffffffu, s, off);
        if (lane == 0) fs[warp][j] = s + b2[j];
    }
    __syncwarp();

    float* ir = g_inps + (size_t)r * 60;
    for (int c = lane; c < 60; c += 32) {
        float v;
        if (c < 48)      v = obs[(size_t)r * 48 + c];
        else if (c < 50) v = acts[(size_t)r * 2 + (c - 48)];
        else             v = fs[warp][c - 50];
        ir[c] = v;
        atomicAdd(&sh_s[c], v);
        atomicAdd(&sh_q[c], v * v);
    }
    __syncthreads();
    if (threadIdx.x < 60) {
        atomicAdd(&g_stats[threadIdx.x], sh_s[threadIdx.x]);
        atomicAdd(&g_stats[64 + threadIdx.x], sh_q[threadIdx.x]);
    }
}

// -------- normalize (finalizing stats locally) + encoder(leaky) -> emb split ----
__global__ void __launch_bounds__(256) enc_kvq(
    const float* __restrict__ enc_w, const float* __restrict__ enc_b)
{
    __shared__ float xn[32][60];
    __shared__ float wch[32][61];
    __shared__ float mu_s[60], inv_s[60];

    int t = threadIdx.x;
    int row0 = blockIdx.x * 32;

    if (t < 60) {
        float mu = g_stats[t] * (1.f / NROW);
        float var = g_stats[64 + t] * (1.f / NROW) - mu * mu;
        mu_s[t] = mu;
        inv_s[t] = rsqrtf(var + 1e-5f);
    }
    __syncthreads();

    for (int idx = t; idx < 32 * 60; idx += 256) {
        int r = idx / 60, c = idx % 60;
        xn[r][c] = (g_inps[(size_t)(row0 + r) * 60 + c] - mu_s[c]) * inv_s[c];
    }
    __syncthreads();

    int jj = t & 31, rg = t >> 5;

    for (int jc = 0; jc < 4; jc++) {
        for (int idx = t; idx < 32 * 60; idx += 256) {
            int rr = idx / 60, c = idx % 60;
            wch[rr][c] = enc_w[(jc * 32 + rr) * 60 + c];
        }
        __syncthreads();

        float a0 = 0.f, a1 = 0.f, a2 = 0.f, a3 = 0.f;
        #pragma unroll
        for (int c = 0; c < 60; c++) {
            float w = wch[jj][c];
            a0 += xn[rg * 4 + 0][c] * w;
            a1 += xn[rg * 4 + 1][c] * w;
            a2 += xn[rg * 4 + 2][c] * w;
            a3 += xn[rg * 4 + 3][c] * w;
        }
        float bb = enc_b[jc * 32 + jj];
        float v[4] = {a0 + bb, a1 + bb, a2 + bb, a3 + bb};
        int col = jc * 32 + jj;
        #pragma unroll
        for (int q = 0; q < 4; q++) {
            float vv = (v[q] >= 0.f) ? v[q] : 0.01f * v[q];
            __nv_bfloat16 hh, ll;
            bsplit(vv, hh, ll);
            size_t idx = (size_t)(row0 + rg * 4 + q) * 256 + col;
            g_embh[idx] = hh;
            g_embl[idx] = ll;
        }
        __syncthreads();
    }
}

// ---------------- tiny 3-agent cross-attention ----------------
__global__ void __launch_bounds__(128) attn_kernel()
{
    __shared__ float qs[3][128], ks[3][128], vs[3][128];
    int b = blockIdx.x;
    int t = threadIdx.x;

    #pragma unroll
    for (int g = 0; g < 3; g++) {
        size_t roff = (size_t)(g * BSZ + b) * 128 + t;
        qs[g][t] = g_q[roff];
        ks[g][t] = g_keys[roff];
        vs[g][t] = g_vals[roff];
    }
    __syncthreads();

    const float scale = 0.25f;
    #pragma unroll
    for (int g = 0; g < 3; g++) {
        int o1 = (g == 0) ? 1 : 0;
        int o2 = (g == 2) ? 1 : 2;
        float q = qs[g][t];
        float p1 = q * ks[o1][t];
        float p2 = q * ks[o2][t];
        #pragma unroll
        for (int off = 8; off; off >>= 1) {
            p1 += __shfl_xor_sync(0xffffffffu, p1, off);
            p2 += __shfl_xor_sync(0xffffffffu, p2, off);
        }
        float l1 = p1 * scale, l2 = p2 * scale;
        float mx = fmaxf(l1, l2);
        float e1 = expf(l1 - mx), e2 = expf(l2 - mx);
        float inv = 1.f / (e1 + e2);
        float other = (e1 * vs[o1][t] + e2 * vs[o2][t]) * inv;
        __nv_bfloat16 hh, ll;
        bsplit(other, hh, ll);
        size_t idx = (size_t)(g * BSZ + b) * 256 + 128 + t;
        g_embh[idx] = hh;
        g_embl[idx] = ll;
    }
}

// ---------------- launch ----------------
extern "C" void kernel_launch(void* const* d_in, const int* in_sizes, int n_in,
                              void* d_out, int out_size)
{
    const float* obs     = (const float*)d_in[0];
    const float* acts    = (const float*)d_in[1];
    const float* scan    = (const float*)d_in[2];
    const float* conv_w1 = (const float*)d_in[3];
    const float* conv_b1 = (const float*)d_in[4];
    const float* conv_w2 = (const float*)d_in[5];
    const float* conv_b2 = (const float*)d_in[6];
    const float* fc_w1   = (const float*)d_in[7];
    const float* fc_b1   = (const float*)d_in[8];
    const float* fc_w2   = (const float*)d_in[9];
    const float* fc_b2   = (const float*)d_in[10];
    const float* enc_w   = (const float*)d_in[11];
    const float* enc_b   = (const float*)d_in[12];
    const float* Wk      = (const float*)d_in[13];
    const float* Wv      = (const float*)d_in[14];
    const float* bv      = (const float*)d_in[15];
    const float* Wq      = (const float*)d_in[16];
    const float* q1_w1   = (const float*)d_in[17];
    const float* q1_b1   = (const float*)d_in[18];
    const float* q1_w2   = (const float*)d_in[19];
    const float* q1_b2   = (const float*)d_in[20];
    const float* q1_w3   = (const float*)d_in[21];
    const float* q1_b3   = (const float*)d_in[22];
    const float* q2_w1   = (const float*)d_in[23];
    const float* q2_b1   = (const float*)d_in[24];
    const float* q2_w2   = (const float*)d_in[25];
    const float* q2_b2   = (const float*)d_in[26];
    const float* q2_w3   = (const float*)d_in[27];
    const float* q2_b3   = (const float*)d_in[28];
    float* out = (float*)d_out;

    cudaFuncSetAttribute(fc1_gemm, cudaFuncAttributeMaxDynamicSharedMemorySize, FSMEM);
    cudaFuncSetAttribute(mlp_gemm<1>, cudaFuncAttributeMaxDynamicSharedMemorySize, GSMEM1);
    cudaFuncSetAttribute(mlp_gemm<2>, cudaFuncAttributeMaxDynamicSharedMemorySize, GSMEM2);
    cudaFuncSetAttribute(kvq_gemm, cudaFuncAttributeMaxDynamicSharedMemorySize, GSMEM1);
    cudaFuncSetAttribute(conv_kernel, cudaFuncAttributeMaxDynamicSharedMemorySize, CV_SMEM);

    // all weight prep + out init (b3 bias) + stats zero in one launch
    wsplit_all<<<9901, 256>>>(fc_w1, q1_w1, q2_w1, q1_w2, q2_w2, conv_w2,
                              Wk, Wv, Wq, q1_b3, q2_b3, out);

    conv_kernel<<<444, 256, CV_SMEM>>>(scan, conv_w1, conv_b1, conv_b2);
    fc1_gemm<<<dim3(2, 96, 3), 256, FSMEM>>>();
    fc2_concat<<<NROW / 8, 256>>>(fc_w2, fc_b2, fc_b1, obs, acts);
    enc_kvq<<<NROW / 32, 256>>>(enc_w, enc_b);
    kvq_gemm<<<dim3(3, 64, 3), 256, GSMEM1>>>(bv);
    attn_kernel<<<BSZ, 128>>>();

    mlp_gemm<1><<<dim3(4, 192), 256, GSMEM1>>>(q1_b1, q2_b1, nullptr, nullptr, nullptr);
    mlp_gemm<2><<<dim3(2, 192, 2), 256, GSMEM2>>>(q1_b2, q2_b2, q1_w3, q2_w3, out);
}